// round 2
// baseline (speedup 1.0000x reference)
#include <cuda_runtime.h>
#include <math.h>

// ---------------------------------------------------------------------------
// Problem constants
// ---------------------------------------------------------------------------
#define BB  32
#define PP  512
#define NN  512
#define EMB 256
#define HH  16
#define DD  16

// Scratch (device globals -- no allocation allowed)
__device__ float g_K[BB * HH * NN * DD];    // [b][h][n][d]
__device__ float g_V[BB * HH * NN * DD];    // [b][h][n][d]
__device__ float g_Q[BB * HH * PP * DD];    // [b][h][p][d]
__device__ float g_att[BB * PP * HH * DD];  // [b][p][h*16+d]
__device__ float g_mh[BB * PP * EMB];       // [b][p][e]

// ---------------------------------------------------------------------------
// Generic GEMM  out = A @ W^T (+ extra rank-1 term) (+ bias)
// A: [M=16384][256], W: [256][ldw], out 256 cols.
// OUT_SEL: 0 -> g_K (heads), 1 -> g_V (heads), 2 -> g_Q (heads), 3 -> g_mh (flat)
// EXTRA: add exA[m] * W[c*ldw + 256]  (the "load" column of Wq, ldw=257)
// SRC_ATT: read A from g_att instead of the A parameter.
// Tiling: 64x64 block tile, BK=16, 256 threads, 4x4 micro-tile.
// ---------------------------------------------------------------------------
template <int OUT_SEL, bool EXTRA, bool BIAS, bool SRC_ATT>
__global__ __launch_bounds__(256) void gemm_nt_kernel(
    const float* __restrict__ A,
    const float* __restrict__ W, int ldw,
    const float* __restrict__ exA,
    const float* __restrict__ bias)
{
    __shared__ float As[16][68];  // [k][m_local] (transposed), padded
    __shared__ float Ws[16][68];  // [k][n_local]

    const float* Ap = SRC_ATT ? (const float*)g_att : A;
    float* out = (OUT_SEL == 0) ? g_K : (OUT_SEL == 1) ? g_V
               : (OUT_SEL == 2) ? g_Q : g_mh;

    const int m0 = blockIdx.x * 64;
    const int n0 = blockIdx.y * 64;
    const int tid = threadIdx.x;
    const int tx = tid & 15;   // n direction (4 cols each)
    const int ty = tid >> 4;   // m direction (4 rows each)
    const int lrow = tid >> 2; // loader row 0..63
    const int lq = tid & 3;    // loader quad 0..3 (k chunk of 4)

    float acc[4][4];
#pragma unroll
    for (int r = 0; r < 4; r++)
#pragma unroll
        for (int e = 0; e < 4; e++) acc[r][e] = 0.0f;

    for (int k0 = 0; k0 < 256; k0 += 16) {
        // stage loads in registers
        float4 av = *(const float4*)(Ap + (size_t)(m0 + lrow) * 256 + k0 + lq * 4);
        float w0, w1, w2, w3;
        if (EXTRA) {
            // ldw=257 rows are not 16B aligned -> scalar loads
            const float* wr = W + (size_t)(n0 + lrow) * ldw + k0 + lq * 4;
            w0 = wr[0]; w1 = wr[1]; w2 = wr[2]; w3 = wr[3];
        } else {
            float4 wv = *(const float4*)(W + (size_t)(n0 + lrow) * ldw + k0 + lq * 4);
            w0 = wv.x; w1 = wv.y; w2 = wv.z; w3 = wv.w;
        }
        __syncthreads();  // previous tile fully consumed
        As[lq * 4 + 0][lrow] = av.x;
        As[lq * 4 + 1][lrow] = av.y;
        As[lq * 4 + 2][lrow] = av.z;
        As[lq * 4 + 3][lrow] = av.w;
        Ws[lq * 4 + 0][lrow] = w0;
        Ws[lq * 4 + 1][lrow] = w1;
        Ws[lq * 4 + 2][lrow] = w2;
        Ws[lq * 4 + 3][lrow] = w3;
        __syncthreads();

#pragma unroll
        for (int k = 0; k < 16; k++) {
            float4 a4 = *(const float4*)&As[k][ty * 4];
            float4 b4 = *(const float4*)&Ws[k][tx * 4];
            float a[4] = {a4.x, a4.y, a4.z, a4.w};
            float b[4] = {b4.x, b4.y, b4.z, b4.w};
#pragma unroll
            for (int r = 0; r < 4; r++)
#pragma unroll
                for (int e = 0; e < 4; e++) acc[r][e] += a[r] * b[e];
        }
    }

    float exAr[4] = {0, 0, 0, 0}, exWc[4] = {0, 0, 0, 0};
    if (EXTRA) {
#pragma unroll
        for (int r = 0; r < 4; r++) exAr[r] = exA[m0 + ty * 4 + r];
#pragma unroll
        for (int e = 0; e < 4; e++) exWc[e] = W[(size_t)(n0 + tx * 4 + e) * ldw + 256];
    }

#pragma unroll
    for (int r = 0; r < 4; r++) {
        const int m = m0 + ty * 4 + r;
#pragma unroll
        for (int e = 0; e < 4; e++) {
            const int c = n0 + tx * 4 + e;
            float v = acc[r][e];
            if (EXTRA) v += exAr[r] * exWc[e];
            if (BIAS) v += bias[c];
            if (OUT_SEL < 3) {
                // heads layout: [b][h][n or p][d]
                const int b = m >> 9, n = m & 511;
                const int h = c >> 4, d = c & 15;
                out[(((size_t)(b * 16 + h) * 512) + n) * 16 + d] = v;
            } else {
                out[(size_t)m * 256 + c] = v;
            }
        }
    }
}

// ---------------------------------------------------------------------------
// Attention: block per (b,h). K_h, V_h staged transposed in smem.
// 256 threads = 8 warps; each warp processes 64 p-rows sequentially.
// Lane l owns n in {j*128 + l*4 .. +3 | j=0..3}  (16 n per lane, float4 chunks)
// ---------------------------------------------------------------------------
#define KT_LD 516  // padded row stride (floats) for [16][512] transposed tiles

__global__ __launch_bounds__(256) void attention_kernel(
    const float* __restrict__ mask)
{
    extern __shared__ float sm[];
    float* Ks = sm;              // [16][KT_LD]
    float* Vs = sm + 16 * KT_LD; // [16][KT_LD]

    const int bh = blockIdx.x;
    const int b = bh >> 4;
    const int h = bh & 15;

    const float* Kg = g_K + (size_t)bh * (NN * DD);
    const float* Vg = g_V + (size_t)bh * (NN * DD);
    for (int idx = threadIdx.x; idx < NN * DD; idx += blockDim.x) {
        const int n = idx >> 4, d = idx & 15;
        Ks[d * KT_LD + n] = Kg[idx];
        Vs[d * KT_LD + n] = Vg[idx];
    }
    __syncthreads();

    const int warp = threadIdx.x >> 5;
    const int lane = threadIdx.x & 31;

    for (int rr = 0; rr < 64; rr++) {
        const int p = warp * 64 + rr;

        // load q (uniform across warp -> broadcast)
        const float* qp = g_Q + ((size_t)bh * PP + p) * DD;
        float q[16];
#pragma unroll
        for (int u = 0; u < 4; u++) {
            float4 qv = *(const float4*)(qp + u * 4);
            q[u * 4 + 0] = qv.x; q[u * 4 + 1] = qv.y;
            q[u * 4 + 2] = qv.z; q[u * 4 + 3] = qv.w;
        }

        const float* mrow = mask + ((size_t)(b * PP + p)) * NN;

        // pass 1: scores
        float4 s[4];
        float mx = -1e30f;
#pragma unroll
        for (int j = 0; j < 4; j++) {
            const int base = j * 128 + lane * 4;
            float4 a = make_float4(0.f, 0.f, 0.f, 0.f);
#pragma unroll
            for (int d = 0; d < 16; d++) {
                float4 kv = *(const float4*)&Ks[d * KT_LD + base];
                const float qd = q[d];
                a.x += qd * kv.x; a.y += qd * kv.y;
                a.z += qd * kv.z; a.w += qd * kv.w;
            }
            float4 mk = *(const float4*)&mrow[base];
            s[j].x = a.x * 0.25f + mk.x;
            s[j].y = a.y * 0.25f + mk.y;
            s[j].z = a.z * 0.25f + mk.z;
            s[j].w = a.w * 0.25f + mk.w;
            mx = fmaxf(mx, fmaxf(fmaxf(s[j].x, s[j].y), fmaxf(s[j].z, s[j].w)));
        }
#pragma unroll
        for (int o = 16; o; o >>= 1) mx = fmaxf(mx, __shfl_xor_sync(0xffffffffu, mx, o));

        // pass 2: exp + AV
        float acc[16];
#pragma unroll
        for (int d = 0; d < 16; d++) acc[d] = 0.0f;
        float lsum = 0.0f;
#pragma unroll
        for (int j = 0; j < 4; j++) {
            const int base = j * 128 + lane * 4;
            const float ex = __expf(s[j].x - mx);
            const float ey = __expf(s[j].y - mx);
            const float ez = __expf(s[j].z - mx);
            const float ew = __expf(s[j].w - mx);
            lsum += (ex + ey) + (ez + ew);
#pragma unroll
            for (int d = 0; d < 16; d++) {
                float4 vv = *(const float4*)&Vs[d * KT_LD + base];
                acc[d] += ex * vv.x + ey * vv.y + ez * vv.z + ew * vv.w;
            }
        }
#pragma unroll
        for (int o = 16; o; o >>= 1) lsum += __shfl_xor_sync(0xffffffffu, lsum, o);
#pragma unroll
        for (int d = 0; d < 16; d++)
#pragma unroll
            for (int o = 16; o; o >>= 1) acc[d] += __shfl_xor_sync(0xffffffffu, acc[d], o);

        if (lane == 0) {
            const float inv = 1.0f / lsum;
            float* op = g_att + ((size_t)(b * PP + p)) * (HH * DD) + h * DD;
#pragma unroll
            for (int u = 0; u < 4; u++) {
                float4 ov;
                ov.x = acc[u * 4 + 0] * inv; ov.y = acc[u * 4 + 1] * inv;
                ov.z = acc[u * 4 + 2] * inv; ov.w = acc[u * 4 + 3] * inv;
                *(float4*)(op + u * 4) = ov;
            }
        }
    }
}

// ---------------------------------------------------------------------------
// Final fused kernel: block per (b, 32-row p-tile).
// Phase 1: S[32][512] = mh_tile @ enc_b^T   (register-tiled GEMM)
// Phase 2: per-row (warp): 100th-smallest dist via 32-step binary search on
//          orderable uint keys; penalty; 10*tanh; +mask; softmax; write probs.
// ---------------------------------------------------------------------------
__global__ __launch_bounds__(256) void final_kernel(
    const float* __restrict__ enc,
    const float* __restrict__ dist,
    const float* __restrict__ mask,
    float* __restrict__ out)
{
    extern __shared__ float sm[];
    float* mh_s  = sm;                  // [32][256]
    float* S_s   = sm + 32 * 256;       // [32][512]
    float* enc_s = sm + 32 * 256 + 32 * 512;  // [64][17]

    const int b = blockIdx.y;
    const int p0 = blockIdx.x * 32;
    const int tid = threadIdx.x;

    // load mh tile
    for (int idx = tid * 4; idx < 32 * 256; idx += 256 * 4) {
        *(float4*)&mh_s[idx] =
            *(const float4*)&g_mh[((size_t)(b * PP + p0)) * 256 + idx];
    }
    __syncthreads();

    const int tx = tid & 15;  // n direction, 4 each -> 64
    const int ty = tid >> 4;  // p direction, 2 each -> 32
    const float* encb = enc + (size_t)b * NN * EMB;
    const int li = tid >> 2, lq = tid & 3;

    for (int nb = 0; nb < 8; nb++) {
        const int n0 = nb * 64;
        float acc0[4] = {0, 0, 0, 0}, acc1[4] = {0, 0, 0, 0};
        for (int kb = 0; kb < 16; kb++) {
            const int k0 = kb * 16;
            float4 ev = *(const float4*)&encb[(size_t)(n0 + li) * 256 + k0 + lq * 4];
            __syncthreads();
            enc_s[li * 17 + lq * 4 + 0] = ev.x;
            enc_s[li * 17 + lq * 4 + 1] = ev.y;
            enc_s[li * 17 + lq * 4 + 2] = ev.z;
            enc_s[li * 17 + lq * 4 + 3] = ev.w;
            __syncthreads();
#pragma unroll
            for (int k = 0; k < 16; k++) {
                const float a0 = mh_s[(ty * 2 + 0) * 256 + k0 + k];
                const float a1 = mh_s[(ty * 2 + 1) * 256 + k0 + k];
#pragma unroll
                for (int e = 0; e < 4; e++) {
                    const float bv = enc_s[(tx * 4 + e) * 17 + k];
                    acc0[e] += a0 * bv;
                    acc1[e] += a1 * bv;
                }
            }
        }
#pragma unroll
        for (int e = 0; e < 4; e++) {
            S_s[(ty * 2 + 0) * 512 + n0 + tx * 4 + e] = acc0[e];
            S_s[(ty * 2 + 1) * 512 + n0 + tx * 4 + e] = acc1[e];
        }
        __syncthreads();
    }

    // ------- phase 2: warp per row (8 warps x 4 rows = 32 rows) -------
    const int warp = tid >> 5, lane = tid & 31;
    for (int rr = 0; rr < 4; rr++) {
        const int r = warp * 4 + rr;
        const int p = p0 + r;
        const float* drow = dist + ((size_t)(b * PP + p)) * NN;
        const float* mrow = mask + ((size_t)(b * PP + p)) * NN;

        // load distances, convert to orderable keys
        unsigned key[16];
        float dv[16];
#pragma unroll
        for (int j = 0; j < 16; j++) {
            dv[j] = drow[j * 32 + lane];
            unsigned u = __float_as_uint(dv[j]);
            key[j] = (u & 0x80000000u) ? ~u : (u ^ 0x80000000u);
        }

        // binary search for 100th smallest key
        unsigned lo = 0u, hi = 0xffffffffu;
#pragma unroll 1
        for (int it = 0; it < 32; it++) {
            const unsigned mid = lo + ((hi - lo) >> 1);
            int c = 0;
#pragma unroll
            for (int j = 0; j < 16; j++) c += (key[j] <= mid) ? 1 : 0;
            c = __reduce_add_sync(0xffffffffu, c);
            if (c >= 100) hi = mid; else lo = mid + 1;
        }
        const unsigned tau = hi;

        // penalty + clip + mask, track max
        float cv[16];
        float mx = -1e30f;
#pragma unroll
        for (int j = 0; j < 16; j++) {
            const int n = j * 32 + lane;
            float sc = S_s[r * 512 + n] * 0.0625f;  // 1/sqrt(256)
            sc += (key[j] <= tau) ? (-dv[j] * 0.7071067811865475f) : 1.0f;
            const float cc = 10.0f * tanhf(sc) + mrow[n];
            cv[j] = cc;
            mx = fmaxf(mx, cc);
        }
#pragma unroll
        for (int o = 16; o; o >>= 1) mx = fmaxf(mx, __shfl_xor_sync(0xffffffffu, mx, o));

        float lsum = 0.0f;
#pragma unroll
        for (int j = 0; j < 16; j++) {
            cv[j] = __expf(cv[j] - mx);
            lsum += cv[j];
        }
#pragma unroll
        for (int o = 16; o; o >>= 1) lsum += __shfl_xor_sync(0xffffffffu, lsum, o);
        const float inv = 1.0f / lsum;

        float* orow = out + ((size_t)(b * PP + p)) * NN;
#pragma unroll
        for (int j = 0; j < 16; j++) orow[j * 32 + lane] = cv[j] * inv;
    }
}

// ---------------------------------------------------------------------------
// Launch
// ---------------------------------------------------------------------------
extern "C" void kernel_launch(void* const* d_in, const int* in_sizes, int n_in,
                              void* d_out, int out_size)
{
    const float* enc   = (const float*)d_in[0];   // [B,N,EMB]
    const float* last  = (const float*)d_in[1];   // [B,P,EMB]
    const float* load  = (const float*)d_in[2];   // [B,P]
    const float* dist  = (const float*)d_in[3];   // [B,P,N]
    // d_in[4] cur_theta (unused), d_in[5] ins_feature (unused)
    const float* mask  = (const float*)d_in[6];   // [B,P,N]
    const float* Wq    = (const float*)d_in[7];   // [256,257]
    const float* Wk    = (const float*)d_in[8];   // [256,256]
    const float* Wv    = (const float*)d_in[9];   // [256,256]
    const float* Wc    = (const float*)d_in[10];  // [256,256]
    const float* Wcb   = (const float*)d_in[11];  // [256]
    float* out = (float*)d_out;

    const dim3 gg(BB * PP / 64, 4);  // 256 x 4

    // K, V, Q projections (heads layout)
    gemm_nt_kernel<0, false, false, false><<<gg, 256>>>(enc,  Wk, 256, nullptr, nullptr);
    gemm_nt_kernel<1, false, false, false><<<gg, 256>>>(enc,  Wv, 256, nullptr, nullptr);
    gemm_nt_kernel<2, true,  false, false><<<gg, 256>>>(last, Wq, 257, load,    nullptr);

    // attention
    const size_t smA = (size_t)2 * 16 * KT_LD * sizeof(float);  // 66 KB
    cudaFuncSetAttribute(attention_kernel,
                         cudaFuncAttributeMaxDynamicSharedMemorySize, (int)smA);
    attention_kernel<<<BB * HH, 256, smA>>>(mask);

    // output projection
    gemm_nt_kernel<3, false, true, true><<<gg, 256>>>(nullptr, Wc, 256, nullptr, Wcb);

    // fused score2 + penalty + tanh + softmax
    const size_t smF = (size_t)(32 * 256 + 32 * 512 + 64 * 17) * sizeof(float);
    cudaFuncSetAttribute(final_kernel,
                         cudaFuncAttributeMaxDynamicSharedMemorySize, (int)smF);
    dim3 gF(PP / 32, BB);  // 16 x 32
    final_kernel<<<gF, 256, smF>>>(enc, dist, mask, out);
}

// round 3
// speedup vs baseline: 1.3300x; 1.3300x over previous
#include <cuda_runtime.h>
#include <math.h>

// ---------------------------------------------------------------------------
// Problem constants
// ---------------------------------------------------------------------------
#define BB  32
#define PP  512
#define NN  512
#define EMB 256
#define HH  16
#define DD  16

// Scratch (device globals -- no allocation allowed)
__device__ float g_K[BB * HH * NN * DD];    // [b][h][n][d]
__device__ float g_V[BB * HH * NN * DD];    // [b][h][n][d]
__device__ float g_Q[BB * HH * PP * DD];    // [b][h][p][d]
__device__ float g_att[BB * PP * HH * DD];  // [b][p][h*16+d]
__device__ float g_mh[BB * PP * EMB];       // [b][p][e]

// ---------------------------------------------------------------------------
// GEMM  out = A @ W^T (+ rank-1 extra) (+ bias)
// 128x64 block tile, BK=16, 256 threads, 8x4 micro-tile.
// OUT_SEL: 0 g_K, 1 g_V, 2 g_Q (heads layout), 3 g_mh (flat)
// ---------------------------------------------------------------------------
template <int OUT_SEL, bool EXTRA, bool BIAS, bool SRC_ATT>
__global__ __launch_bounds__(256) void gemm2_kernel(
    const float* __restrict__ A,
    const float* __restrict__ W, int ldw,
    const float* __restrict__ exA,
    const float* __restrict__ bias)
{
    __shared__ float As[16][132];  // [k][m], padded (528B rows, 16B aligned)
    __shared__ float Ws[16][68];   // [k][n], padded

    const float* Ap = SRC_ATT ? (const float*)g_att : A;
    float* out = (OUT_SEL == 0) ? g_K : (OUT_SEL == 1) ? g_V
               : (OUT_SEL == 2) ? g_Q : g_mh;

    const int m0 = blockIdx.x * 128;
    const int n0 = blockIdx.y * 64;
    const int tid = threadIdx.x;

    const int arow = tid >> 1;        // 0..127
    const int ak   = (tid & 1) * 8;   // 0 / 8
    const int wrow = tid >> 2;        // 0..63
    const int wk   = (tid & 3) * 4;   // 0,4,8,12
    const int ty = tid >> 4;          // 0..15 -> 8 m-rows each
    const int tx = tid & 15;          // 0..15 -> 4 n-cols each

    float acc[8][4];
#pragma unroll
    for (int r = 0; r < 8; r++)
#pragma unroll
        for (int e = 0; e < 4; e++) acc[r][e] = 0.0f;

    for (int k0 = 0; k0 < 256; k0 += 16) {
        const float* ap = Ap + (size_t)(m0 + arow) * 256 + k0 + ak;
        float4 a0 = *(const float4*)(ap);
        float4 a1 = *(const float4*)(ap + 4);
        float w0, w1, w2, w3;
        if (EXTRA) {
            const float* wr = W + (size_t)(n0 + wrow) * ldw + k0 + wk;
            w0 = wr[0]; w1 = wr[1]; w2 = wr[2]; w3 = wr[3];
        } else {
            float4 wv = *(const float4*)(W + (size_t)(n0 + wrow) * ldw + k0 + wk);
            w0 = wv.x; w1 = wv.y; w2 = wv.z; w3 = wv.w;
        }
        __syncthreads();
        As[ak + 0][arow] = a0.x; As[ak + 1][arow] = a0.y;
        As[ak + 2][arow] = a0.z; As[ak + 3][arow] = a0.w;
        As[ak + 4][arow] = a1.x; As[ak + 5][arow] = a1.y;
        As[ak + 6][arow] = a1.z; As[ak + 7][arow] = a1.w;
        Ws[wk + 0][wrow] = w0; Ws[wk + 1][wrow] = w1;
        Ws[wk + 2][wrow] = w2; Ws[wk + 3][wrow] = w3;
        __syncthreads();

#pragma unroll
        for (int k = 0; k < 16; k++) {
            float4 av0 = *(const float4*)&As[k][ty * 8];
            float4 av1 = *(const float4*)&As[k][ty * 8 + 4];
            float4 bv  = *(const float4*)&Ws[k][tx * 4];
            float a[8] = {av0.x, av0.y, av0.z, av0.w, av1.x, av1.y, av1.z, av1.w};
            float b[4] = {bv.x, bv.y, bv.z, bv.w};
#pragma unroll
            for (int r = 0; r < 8; r++)
#pragma unroll
                for (int e = 0; e < 4; e++) acc[r][e] += a[r] * b[e];
        }
    }

    float exAr[8], exWc[4];
    if (EXTRA) {
#pragma unroll
        for (int r = 0; r < 8; r++) exAr[r] = exA[m0 + ty * 8 + r];
#pragma unroll
        for (int e = 0; e < 4; e++) exWc[e] = W[(size_t)(n0 + tx * 4 + e) * ldw + 256];
    }

#pragma unroll
    for (int r = 0; r < 8; r++) {
        const int m = m0 + ty * 8 + r;
#pragma unroll
        for (int e = 0; e < 4; e++) {
            const int c = n0 + tx * 4 + e;
            float v = acc[r][e];
            if (EXTRA) v += exAr[r] * exWc[e];
            if (BIAS) v += bias[c];
            if (OUT_SEL < 3) {
                const int b = m >> 9, n = m & 511;
                const int h = c >> 4, d = c & 15;
                out[(((size_t)(b * 16 + h) * 512) + n) * 16 + d] = v;
            } else {
                out[(size_t)m * 256 + c] = v;
            }
        }
    }
}

// ---------------------------------------------------------------------------
// Flash-style attention: block per (b,h, 64-row p-tile). 256 threads.
// Thread grid: ty=tid>>3 (0..31, 2 p-rows each), tx=tid&7 (n-lanes).
// Per 128-n chunk, thread owns n = c*128 + seg*32 + tx*4 + i (seg 0..3, i 0..3)
// -> conflict-free float4 smem reads, coalesced mask reads.
// Online softmax; O in registers; single 3-step x8 reduction per tile.
// ---------------------------------------------------------------------------
#define KT_LD 520  // 520*4 = 2080 B row stride (16B aligned)

__global__ __launch_bounds__(256) void attention2_kernel(
    const float* __restrict__ mask)
{
    extern __shared__ float sm[];
    float* Kt = sm;                   // [16][KT_LD]
    float* Vt = sm + 16 * KT_LD;      // [16][KT_LD]
    float* Qs = sm + 32 * KT_LD;      // [64*16]

    const int bh = blockIdx.x;
    const int b  = bh >> 4;
    const int h  = bh & 15;
    const int p0 = blockIdx.y * 64;
    const int tid = threadIdx.x;

    const float* Kg = g_K + (size_t)bh * (NN * DD);
    const float* Vg = g_V + (size_t)bh * (NN * DD);
    for (int idx = tid; idx < NN * DD; idx += 256) {
        const int n = idx >> 4, d = idx & 15;
        Kt[d * KT_LD + n] = Kg[idx];
        Vt[d * KT_LD + n] = Vg[idx];
    }
    {
        const float4* Qg = (const float4*)(g_Q + ((size_t)bh * PP + p0) * DD);
        ((float4*)Qs)[tid] = Qg[tid];  // 64x16 floats = 256 float4
    }
    __syncthreads();

    const int ty = tid >> 3;  // 0..31
    const int tx = tid & 7;   // 0..7

    // q registers: 2 rows x 16
    float q[2][16];
#pragma unroll
    for (int r = 0; r < 2; r++) {
        const float* qp = &Qs[(ty * 2 + r) * 16];
#pragma unroll
        for (int u = 0; u < 4; u++) {
            float4 qv = *(const float4*)(qp + u * 4);
            q[r][u * 4 + 0] = qv.x; q[r][u * 4 + 1] = qv.y;
            q[r][u * 4 + 2] = qv.z; q[r][u * 4 + 3] = qv.w;
        }
    }

    float m[2] = {-1e30f, -1e30f};
    float l[2] = {0.0f, 0.0f};
    float O[2][16];
#pragma unroll
    for (int r = 0; r < 2; r++)
#pragma unroll
        for (int d = 0; d < 16; d++) O[r][d] = 0.0f;

    const size_t mbase0 = ((size_t)(b * PP + p0 + ty * 2 + 0)) * NN;
    const size_t mbase1 = ((size_t)(b * PP + p0 + ty * 2 + 1)) * NN;

#pragma unroll 1
    for (int c = 0; c < 4; c++) {
        const int nb = c * 128 + tx * 4;

        // ---- S = Q K^T (chunk) ----
        float s[2][16];
#pragma unroll
        for (int r = 0; r < 2; r++)
#pragma unroll
            for (int i = 0; i < 16; i++) s[r][i] = 0.0f;

#pragma unroll
        for (int d = 0; d < 16; d++) {
            const float q0 = q[0][d], q1 = q[1][d];
            const float* kr = &Kt[d * KT_LD + nb];
#pragma unroll
            for (int seg = 0; seg < 4; seg++) {
                float4 kv = *(const float4*)(kr + seg * 32);
                s[0][seg * 4 + 0] += q0 * kv.x; s[0][seg * 4 + 1] += q0 * kv.y;
                s[0][seg * 4 + 2] += q0 * kv.z; s[0][seg * 4 + 3] += q0 * kv.w;
                s[1][seg * 4 + 0] += q1 * kv.x; s[1][seg * 4 + 1] += q1 * kv.y;
                s[1][seg * 4 + 2] += q1 * kv.z; s[1][seg * 4 + 3] += q1 * kv.w;
            }
        }

        // ---- scale + mask ----
#pragma unroll
        for (int seg = 0; seg < 4; seg++) {
            float4 m0v = *(const float4*)&mask[mbase0 + nb + seg * 32];
            float4 m1v = *(const float4*)&mask[mbase1 + nb + seg * 32];
            s[0][seg * 4 + 0] = s[0][seg * 4 + 0] * 0.25f + m0v.x;
            s[0][seg * 4 + 1] = s[0][seg * 4 + 1] * 0.25f + m0v.y;
            s[0][seg * 4 + 2] = s[0][seg * 4 + 2] * 0.25f + m0v.z;
            s[0][seg * 4 + 3] = s[0][seg * 4 + 3] * 0.25f + m0v.w;
            s[1][seg * 4 + 0] = s[1][seg * 4 + 0] * 0.25f + m1v.x;
            s[1][seg * 4 + 1] = s[1][seg * 4 + 1] * 0.25f + m1v.y;
            s[1][seg * 4 + 2] = s[1][seg * 4 + 2] * 0.25f + m1v.z;
            s[1][seg * 4 + 3] = s[1][seg * 4 + 3] * 0.25f + m1v.w;
        }

        // ---- online softmax update ----
#pragma unroll
        for (int r = 0; r < 2; r++) {
            float cm = s[r][0];
#pragma unroll
            for (int i = 1; i < 16; i++) cm = fmaxf(cm, s[r][i]);
#pragma unroll
            for (int o = 1; o < 8; o <<= 1)
                cm = fmaxf(cm, __shfl_xor_sync(0xffffffffu, cm, o));
            const float mnew = fmaxf(m[r], cm);
            const float f = __expf(m[r] - mnew);
            m[r] = mnew;
            l[r] *= f;
#pragma unroll
            for (int d = 0; d < 16; d++) O[r][d] *= f;
            float ls = 0.0f;
#pragma unroll
            for (int i = 0; i < 16; i++) {
                s[r][i] = __expf(s[r][i] - mnew);
                ls += s[r][i];
            }
            l[r] += ls;
        }

        // ---- O += P V (chunk) ----
#pragma unroll
        for (int d = 0; d < 16; d++) {
            const float* vr = &Vt[d * KT_LD + nb];
            float a0 = 0.0f, a1 = 0.0f;
#pragma unroll
            for (int seg = 0; seg < 4; seg++) {
                float4 vv = *(const float4*)(vr + seg * 32);
                a0 += s[0][seg * 4 + 0] * vv.x + s[0][seg * 4 + 1] * vv.y
                    + s[0][seg * 4 + 2] * vv.z + s[0][seg * 4 + 3] * vv.w;
                a1 += s[1][seg * 4 + 0] * vv.x + s[1][seg * 4 + 1] * vv.y
                    + s[1][seg * 4 + 2] * vv.z + s[1][seg * 4 + 3] * vv.w;
            }
            O[0][d] += a0;
            O[1][d] += a1;
        }
    }

    // ---- reduce across the 8-lane tx group ----
#pragma unroll
    for (int r = 0; r < 2; r++) {
#pragma unroll
        for (int o = 1; o < 8; o <<= 1)
            l[r] += __shfl_xor_sync(0xffffffffu, l[r], o);
#pragma unroll
        for (int d = 0; d < 16; d++)
#pragma unroll
            for (int o = 1; o < 8; o <<= 1)
                O[r][d] += __shfl_xor_sync(0xffffffffu, O[r][d], o);
    }

    if (tx < 2) {
        const int r = tx;
        const float inv = 1.0f / l[r];
        const int p = p0 + ty * 2 + r;
        float* op = g_att + ((size_t)(b * PP + p)) * (HH * DD) + h * DD;
#pragma unroll
        for (int u = 0; u < 4; u++) {
            float4 ov;
            ov.x = O[r][u * 4 + 0] * inv; ov.y = O[r][u * 4 + 1] * inv;
            ov.z = O[r][u * 4 + 2] * inv; ov.w = O[r][u * 4 + 3] * inv;
            *(float4*)(op + u * 4) = ov;
        }
    }
}

// ---------------------------------------------------------------------------
// Final fused kernel (unchanged from R2): block per (b, 32-row p-tile).
// ---------------------------------------------------------------------------
__global__ __launch_bounds__(256) void final_kernel(
    const float* __restrict__ enc,
    const float* __restrict__ dist,
    const float* __restrict__ mask,
    float* __restrict__ out)
{
    extern __shared__ float sm[];
    float* mh_s  = sm;                        // [32][256]
    float* S_s   = sm + 32 * 256;             // [32][512]
    float* enc_s = sm + 32 * 256 + 32 * 512;  // [64][17]

    const int b = blockIdx.y;
    const int p0 = blockIdx.x * 32;
    const int tid = threadIdx.x;

    for (int idx = tid * 4; idx < 32 * 256; idx += 256 * 4) {
        *(float4*)&mh_s[idx] =
            *(const float4*)&g_mh[((size_t)(b * PP + p0)) * 256 + idx];
    }
    __syncthreads();

    const int tx = tid & 15;
    const int ty = tid >> 4;
    const float* encb = enc + (size_t)b * NN * EMB;
    const int li = tid >> 2, lq = tid & 3;

    for (int nb = 0; nb < 8; nb++) {
        const int n0 = nb * 64;
        float acc0[4] = {0, 0, 0, 0}, acc1[4] = {0, 0, 0, 0};
        for (int kb = 0; kb < 16; kb++) {
            const int k0 = kb * 16;
            float4 ev = *(const float4*)&encb[(size_t)(n0 + li) * 256 + k0 + lq * 4];
            __syncthreads();
            enc_s[li * 17 + lq * 4 + 0] = ev.x;
            enc_s[li * 17 + lq * 4 + 1] = ev.y;
            enc_s[li * 17 + lq * 4 + 2] = ev.z;
            enc_s[li * 17 + lq * 4 + 3] = ev.w;
            __syncthreads();
#pragma unroll
            for (int k = 0; k < 16; k++) {
                const float a0 = mh_s[(ty * 2 + 0) * 256 + k0 + k];
                const float a1 = mh_s[(ty * 2 + 1) * 256 + k0 + k];
#pragma unroll
                for (int e = 0; e < 4; e++) {
                    const float bv = enc_s[(tx * 4 + e) * 17 + k];
                    acc0[e] += a0 * bv;
                    acc1[e] += a1 * bv;
                }
            }
        }
#pragma unroll
        for (int e = 0; e < 4; e++) {
            S_s[(ty * 2 + 0) * 512 + n0 + tx * 4 + e] = acc0[e];
            S_s[(ty * 2 + 1) * 512 + n0 + tx * 4 + e] = acc1[e];
        }
        __syncthreads();
    }

    const int warp = tid >> 5, lane = tid & 31;
    for (int rr = 0; rr < 4; rr++) {
        const int r = warp * 4 + rr;
        const int p = p0 + r;
        const float* drow = dist + ((size_t)(b * PP + p)) * NN;
        const float* mrow = mask + ((size_t)(b * PP + p)) * NN;

        unsigned key[16];
        float dv[16];
#pragma unroll
        for (int j = 0; j < 16; j++) {
            dv[j] = drow[j * 32 + lane];
            unsigned u = __float_as_uint(dv[j]);
            key[j] = (u & 0x80000000u) ? ~u : (u ^ 0x80000000u);
        }

        unsigned lo = 0u, hi = 0xffffffffu;
#pragma unroll 1
        for (int it = 0; it < 32; it++) {
            const unsigned mid = lo + ((hi - lo) >> 1);
            int c = 0;
#pragma unroll
            for (int j = 0; j < 16; j++) c += (key[j] <= mid) ? 1 : 0;
            c = __reduce_add_sync(0xffffffffu, c);
            if (c >= 100) hi = mid; else lo = mid + 1;
        }
        const unsigned tau = hi;

        float cv[16];
        float mx = -1e30f;
#pragma unroll
        for (int j = 0; j < 16; j++) {
            const int n = j * 32 + lane;
            float sc = S_s[r * 512 + n] * 0.0625f;
            sc += (key[j] <= tau) ? (-dv[j] * 0.7071067811865475f) : 1.0f;
            const float cc = 10.0f * tanhf(sc) + mrow[n];
            cv[j] = cc;
            mx = fmaxf(mx, cc);
        }
#pragma unroll
        for (int o = 16; o; o >>= 1) mx = fmaxf(mx, __shfl_xor_sync(0xffffffffu, mx, o));

        float lsum = 0.0f;
#pragma unroll
        for (int j = 0; j < 16; j++) {
            cv[j] = __expf(cv[j] - mx);
            lsum += cv[j];
        }
#pragma unroll
        for (int o = 16; o; o >>= 1) lsum += __shfl_xor_sync(0xffffffffu, lsum, o);
        const float inv = 1.0f / lsum;

        float* orow = out + ((size_t)(b * PP + p)) * NN;
#pragma unroll
        for (int j = 0; j < 16; j++) orow[j * 32 + lane] = cv[j] * inv;
    }
}

// ---------------------------------------------------------------------------
// Launch
// ---------------------------------------------------------------------------
extern "C" void kernel_launch(void* const* d_in, const int* in_sizes, int n_in,
                              void* d_out, int out_size)
{
    const float* enc   = (const float*)d_in[0];
    const float* last  = (const float*)d_in[1];
    const float* load  = (const float*)d_in[2];
    const float* dist  = (const float*)d_in[3];
    const float* mask  = (const float*)d_in[6];
    const float* Wq    = (const float*)d_in[7];
    const float* Wk    = (const float*)d_in[8];
    const float* Wv    = (const float*)d_in[9];
    const float* Wc    = (const float*)d_in[10];
    const float* Wcb   = (const float*)d_in[11];
    float* out = (float*)d_out;

    const dim3 gg(BB * PP / 128, 4);  // 128 x 4

    gemm2_kernel<0, false, false, false><<<gg, 256>>>(enc,  Wk, 256, nullptr, nullptr);
    gemm2_kernel<1, false, false, false><<<gg, 256>>>(enc,  Wv, 256, nullptr, nullptr);
    gemm2_kernel<2, true,  false, false><<<gg, 256>>>(last, Wq, 257, load,    nullptr);

    const size_t smA = (size_t)(2 * 16 * KT_LD + 64 * 16) * sizeof(float);  // ~70.7 KB
    cudaFuncSetAttribute(attention2_kernel,
                         cudaFuncAttributeMaxDynamicSharedMemorySize, (int)smA);
    dim3 gA(BB * HH, PP / 64);  // 512 x 8
    attention2_kernel<<<gA, 256, smA>>>(mask);

    gemm2_kernel<3, false, true, true><<<gg, 256>>>(nullptr, Wc, 256, nullptr, Wcb);

    const size_t smF = (size_t)(32 * 256 + 32 * 512 + 64 * 17) * sizeof(float);
    cudaFuncSetAttribute(final_kernel,
                         cudaFuncAttributeMaxDynamicSharedMemorySize, (int)smF);
    dim3 gF(PP / 32, BB);
    final_kernel<<<gF, 256, smF>>>(enc, dist, mask, out);
}

// round 4
// speedup vs baseline: 1.7204x; 1.2935x over previous
#include <cuda_runtime.h>
#include <math.h>

// ---------------------------------------------------------------------------
// Problem constants
// ---------------------------------------------------------------------------
#define BB  32
#define PP  512
#define NN  512
#define EMB 256
#define HH  16
#define DD  16

// Scratch (device globals -- no allocation allowed)
__device__ float g_K[BB * HH * NN * DD];    // [b][h][n][d]
__device__ float g_V[BB * HH * NN * DD];    // [b][h][n][d]
__device__ float g_Q[BB * HH * PP * DD];    // [b][h][p][d]
__device__ float g_att[BB * PP * HH * DD];  // [b][p][h*16+d]
__device__ float g_mh[BB * PP * EMB];       // [b][p][e]
__device__ float g_encT[BB * EMB * NN];     // [b][k][n] transposed encoder

// ---------------------------------------------------------------------------
// Packed fp32x2 helpers (sm_103a FFMA2 path; ptxas never auto-fuses)
// ---------------------------------------------------------------------------
union F2U { float2 f; unsigned long long u; };

__device__ __forceinline__ float2 fma2(float2 a, float2 b, float2 c) {
    F2U A, B, C, D; A.f = a; B.f = b; C.f = c;
    asm("fma.rn.f32x2 %0, %1, %2, %3;" : "=l"(D.u) : "l"(A.u), "l"(B.u), "l"(C.u));
    return D.f;
}
__device__ __forceinline__ float2 mul2(float2 a, float2 b) {
    F2U A, B, D; A.f = a; B.f = b;
    asm("mul.rn.f32x2 %0, %1, %2;" : "=l"(D.u) : "l"(A.u), "l"(B.u));
    return D.f;
}
__device__ __forceinline__ float2 add2(float2 a, float2 b) {
    F2U A, B, D; A.f = a; B.f = b;
    asm("add.rn.f32x2 %0, %1, %2;" : "=l"(D.u) : "l"(A.u), "l"(B.u));
    return D.f;
}

#define SELC(v, i) ((i) == 0 ? (v).x : (i) == 1 ? (v).y : (i) == 2 ? (v).z : (v).w)

// ---------------------------------------------------------------------------
// GEMM  out = A @ W^T (+ rank-1 extra) (+ bias)
// 128x64 block tile, BK=16, 256 threads, 8x4 micro-tile, FFMA2 along m.
// ---------------------------------------------------------------------------
template <int OUT_SEL, bool EXTRA, bool BIAS, bool SRC_ATT>
__global__ __launch_bounds__(256) void gemm2_kernel(
    const float* __restrict__ A,
    const float* __restrict__ W, int ldw,
    const float* __restrict__ exA,
    const float* __restrict__ bias)
{
    __shared__ float As[16][132];
    __shared__ float Ws[16][68];

    const float* Ap = SRC_ATT ? (const float*)g_att : A;
    float* out = (OUT_SEL == 0) ? g_K : (OUT_SEL == 1) ? g_V
               : (OUT_SEL == 2) ? g_Q : g_mh;

    const int m0 = blockIdx.x * 128;
    const int n0 = blockIdx.y * 64;
    const int tid = threadIdx.x;

    const int arow = tid >> 1;
    const int ak   = (tid & 1) * 8;
    const int wrow = tid >> 2;
    const int wk   = (tid & 3) * 4;
    const int ty = tid >> 4;
    const int tx = tid & 15;

    float2 acc2[4][4];
#pragma unroll
    for (int mp = 0; mp < 4; mp++)
#pragma unroll
        for (int e = 0; e < 4; e++) acc2[mp][e] = make_float2(0.f, 0.f);

    for (int k0 = 0; k0 < 256; k0 += 16) {
        const float* ap = Ap + (size_t)(m0 + arow) * 256 + k0 + ak;
        float4 a0 = *(const float4*)(ap);
        float4 a1 = *(const float4*)(ap + 4);
        float w0, w1, w2, w3;
        if (EXTRA) {
            const float* wr = W + (size_t)(n0 + wrow) * ldw + k0 + wk;
            w0 = wr[0]; w1 = wr[1]; w2 = wr[2]; w3 = wr[3];
        } else {
            float4 wv = *(const float4*)(W + (size_t)(n0 + wrow) * ldw + k0 + wk);
            w0 = wv.x; w1 = wv.y; w2 = wv.z; w3 = wv.w;
        }
        __syncthreads();
        As[ak + 0][arow] = a0.x; As[ak + 1][arow] = a0.y;
        As[ak + 2][arow] = a0.z; As[ak + 3][arow] = a0.w;
        As[ak + 4][arow] = a1.x; As[ak + 5][arow] = a1.y;
        As[ak + 6][arow] = a1.z; As[ak + 7][arow] = a1.w;
        Ws[wk + 0][wrow] = w0; Ws[wk + 1][wrow] = w1;
        Ws[wk + 2][wrow] = w2; Ws[wk + 3][wrow] = w3;
        __syncthreads();

#pragma unroll
        for (int k = 0; k < 16; k++) {
            float4 av0 = *(const float4*)&As[k][ty * 8];
            float4 av1 = *(const float4*)&As[k][ty * 8 + 4];
            float4 bv  = *(const float4*)&Ws[k][tx * 4];
            float2 am[4] = {{av0.x, av0.y}, {av0.z, av0.w},
                            {av1.x, av1.y}, {av1.z, av1.w}};
            float2 bb[4] = {{bv.x, bv.x}, {bv.y, bv.y},
                            {bv.z, bv.z}, {bv.w, bv.w}};
#pragma unroll
            for (int mp = 0; mp < 4; mp++)
#pragma unroll
                for (int e = 0; e < 4; e++)
                    acc2[mp][e] = fma2(am[mp], bb[e], acc2[mp][e]);
        }
    }

    float exAr[8], exWc[4];
    if (EXTRA) {
#pragma unroll
        for (int r = 0; r < 8; r++) exAr[r] = exA[m0 + ty * 8 + r];
#pragma unroll
        for (int e = 0; e < 4; e++) exWc[e] = W[(size_t)(n0 + tx * 4 + e) * ldw + 256];
    }

#pragma unroll
    for (int mp = 0; mp < 4; mp++) {
#pragma unroll
        for (int hf = 0; hf < 2; hf++) {
            const int r = mp * 2 + hf;
            const int m = m0 + ty * 8 + r;
#pragma unroll
            for (int e = 0; e < 4; e++) {
                const int c = n0 + tx * 4 + e;
                float v = hf ? acc2[mp][e].y : acc2[mp][e].x;
                if (EXTRA) v += exAr[r] * exWc[e];
                if (BIAS) v += bias[c];
                if (OUT_SEL < 3) {
                    const int b = m >> 9, n = m & 511;
                    const int h = c >> 4, d = c & 15;
                    out[(((size_t)(b * 16 + h) * 512) + n) * 16 + d] = v;
                } else {
                    out[(size_t)m * 256 + c] = v;
                }
            }
        }
    }
}

// ---------------------------------------------------------------------------
// Flash attention v3: block per (b,h, 128-row p-tile). 256 threads.
// tx = tid&7 (8 n-lanes), ty = tid>>3 (32 groups x 4 rows = 128 rows).
// q read from smem (broadcast); s/O packed float2; FFMA2 throughout.
// ---------------------------------------------------------------------------
#define KT_LD 520

__global__ __launch_bounds__(256) void attention3_kernel(
    const float* __restrict__ mask)
{
    extern __shared__ float sm[];
    float* Kt = sm;                   // [16][KT_LD]
    float* Vt = sm + 16 * KT_LD;      // [16][KT_LD]
    float* Qs = sm + 32 * KT_LD;      // [128*16]

    const int bh = blockIdx.x;
    const int b  = bh >> 4;
    const int h  = bh & 15;
    const int p0 = blockIdx.y * 128;
    const int tid = threadIdx.x;

    const float* Kg = g_K + (size_t)bh * (NN * DD);
    const float* Vg = g_V + (size_t)bh * (NN * DD);
    for (int idx = tid; idx < NN * DD; idx += 256) {
        const int n = idx >> 4, d = idx & 15;
        Kt[d * KT_LD + n] = Kg[idx];
        Vt[d * KT_LD + n] = Vg[idx];
    }
    {
        const float4* Qg = (const float4*)(g_Q + ((size_t)bh * PP + p0) * DD);
        ((float4*)Qs)[tid] = Qg[tid];
        ((float4*)Qs)[tid + 256] = Qg[tid + 256];
    }
    __syncthreads();

    const int tx = tid & 7;
    const int ty = tid >> 3;
    const int qb = ty * 4 * 16;

    float2 O2[4][8];
    float mxs[4], ls[4];
#pragma unroll
    for (int r = 0; r < 4; r++) {
        mxs[r] = -1e30f; ls[r] = 0.0f;
#pragma unroll
        for (int j = 0; j < 8; j++) O2[r][j] = make_float2(0.f, 0.f);
    }

#pragma unroll 1
    for (int c = 0; c < 4; c++) {
        const int nb = c * 128 + tx * 4;

        float2 s2[4][8];
#pragma unroll
        for (int r = 0; r < 4; r++)
#pragma unroll
            for (int j = 0; j < 8; j++) s2[r][j] = make_float2(0.f, 0.f);

        // ---- S = Q K^T ----
#pragma unroll
        for (int dq = 0; dq < 4; dq++) {
            float4 qv[4];
#pragma unroll
            for (int r = 0; r < 4; r++)
                qv[r] = *(const float4*)&Qs[qb + r * 16 + dq * 4];
#pragma unroll
            for (int dd = 0; dd < 4; dd++) {
                const int d = dq * 4 + dd;
                const float* kr = &Kt[d * KT_LD + nb];
                float4 ka = *(const float4*)(kr);
                float4 kb4 = *(const float4*)(kr + 32);
                float4 kc = *(const float4*)(kr + 64);
                float4 kd = *(const float4*)(kr + 96);
                float2 kp[8] = {{ka.x, ka.y}, {ka.z, ka.w},
                                {kb4.x, kb4.y}, {kb4.z, kb4.w},
                                {kc.x, kc.y}, {kc.z, kc.w},
                                {kd.x, kd.y}, {kd.z, kd.w}};
#pragma unroll
                for (int r = 0; r < 4; r++) {
                    const float qd = SELC(qv[r], dd);
                    const float2 qq = make_float2(qd, qd);
#pragma unroll
                    for (int j = 0; j < 8; j++)
                        s2[r][j] = fma2(qq, kp[j], s2[r][j]);
                }
            }
        }

        // ---- scale + mask ----
        const float2 qtr = make_float2(0.25f, 0.25f);
#pragma unroll
        for (int r = 0; r < 4; r++) {
            const float* mp_ = mask + ((size_t)(b * PP + p0 + ty * 4 + r)) * NN + nb;
#pragma unroll
            for (int seg = 0; seg < 4; seg++) {
                float4 mv = *(const float4*)(mp_ + seg * 32);
                s2[r][seg * 2 + 0] = fma2(s2[r][seg * 2 + 0], qtr, make_float2(mv.x, mv.y));
                s2[r][seg * 2 + 1] = fma2(s2[r][seg * 2 + 1], qtr, make_float2(mv.z, mv.w));
            }
        }

        // ---- online softmax ----
#pragma unroll
        for (int r = 0; r < 4; r++) {
            float cm = fmaxf(s2[r][0].x, s2[r][0].y);
#pragma unroll
            for (int j = 1; j < 8; j++)
                cm = fmaxf(cm, fmaxf(s2[r][j].x, s2[r][j].y));
#pragma unroll
            for (int o = 1; o < 8; o <<= 1)
                cm = fmaxf(cm, __shfl_xor_sync(0xffffffffu, cm, o));
            const float mnew = fmaxf(mxs[r], cm);
            const float fs = __expf(mxs[r] - mnew);
            mxs[r] = mnew;
            ls[r] *= fs;
            const float2 fs2 = make_float2(fs, fs);
#pragma unroll
            for (int j = 0; j < 8; j++) O2[r][j] = mul2(O2[r][j], fs2);
            float2 sacc = make_float2(0.f, 0.f);
#pragma unroll
            for (int j = 0; j < 8; j++) {
                s2[r][j].x = __expf(s2[r][j].x - mnew);
                s2[r][j].y = __expf(s2[r][j].y - mnew);
                sacc = add2(sacc, s2[r][j]);
            }
            ls[r] += sacc.x + sacc.y;
        }

        // ---- O += P V ----
#pragma unroll
        for (int d = 0; d < 16; d++) {
            const float* vr = &Vt[d * KT_LD + nb];
            float4 va = *(const float4*)(vr);
            float4 vb = *(const float4*)(vr + 32);
            float4 vc = *(const float4*)(vr + 64);
            float4 vd = *(const float4*)(vr + 96);
            float2 vp[8] = {{va.x, va.y}, {va.z, va.w},
                            {vb.x, vb.y}, {vb.z, vb.w},
                            {vc.x, vc.y}, {vc.z, vc.w},
                            {vd.x, vd.y}, {vd.z, vd.w}};
#pragma unroll
            for (int r = 0; r < 4; r++) {
                float2 t2 = mul2(s2[r][0], vp[0]);
#pragma unroll
                for (int j = 1; j < 8; j++) t2 = fma2(s2[r][j], vp[j], t2);
                const float t = t2.x + t2.y;
                if (d & 1) O2[r][d >> 1].y += t;
                else       O2[r][d >> 1].x += t;
            }
        }
    }

    // ---- reduce across the 8-lane tx group ----
#pragma unroll
    for (int r = 0; r < 4; r++) {
#pragma unroll
        for (int o = 1; o < 8; o <<= 1)
            ls[r] += __shfl_xor_sync(0xffffffffu, ls[r], o);
#pragma unroll
        for (int j = 0; j < 8; j++) {
#pragma unroll
            for (int o = 1; o < 8; o <<= 1) {
                O2[r][j].x += __shfl_xor_sync(0xffffffffu, O2[r][j].x, o);
                O2[r][j].y += __shfl_xor_sync(0xffffffffu, O2[r][j].y, o);
            }
        }
    }

#pragma unroll
    for (int r = 0; r < 4; r++) {
        if (tx == r) {
            const float inv = 1.0f / ls[r];
            const int p = p0 + ty * 4 + r;
            float* op = g_att + ((size_t)(b * PP + p)) * (HH * DD) + h * DD;
#pragma unroll
            for (int u = 0; u < 4; u++) {
                float4 ov;
                ov.x = O2[r][u * 2 + 0].x * inv;
                ov.y = O2[r][u * 2 + 0].y * inv;
                ov.z = O2[r][u * 2 + 1].x * inv;
                ov.w = O2[r][u * 2 + 1].y * inv;
                *(float4*)(op + u * 4) = ov;
            }
        }
    }
}

// ---------------------------------------------------------------------------
// Encoder transpose: g_encT[b][k][n] = enc[b][n][k]
// ---------------------------------------------------------------------------
__global__ void transpose_enc_kernel(const float* __restrict__ enc)
{
    __shared__ float t[32][33];
    const int b = blockIdx.z;
    const int n0 = blockIdx.x * 32;
    const int k0 = blockIdx.y * 32;
    const int tx = threadIdx.x, ty = threadIdx.y;
#pragma unroll
    for (int i = 0; i < 4; i++)
        t[ty + i * 8][tx] = enc[((size_t)b * NN + n0 + ty + i * 8) * EMB + k0 + tx];
    __syncthreads();
#pragma unroll
    for (int i = 0; i < 4; i++)
        g_encT[((size_t)b * EMB + k0 + ty + i * 8) * NN + n0 + tx] = t[tx][ty + i * 8];
}

// ---------------------------------------------------------------------------
// Final fused kernel: block per (b, 64-row p-tile). 256 threads.
// Phase 1: S = mh @ enc^T, kb-outer / nb-inner, acc in regs (4 rows/thread).
// Phase 2: per-row topk-threshold + tanh-clip + softmax (warp per row).
// ---------------------------------------------------------------------------
#define ET_LD 520

__global__ __launch_bounds__(256) void final2_kernel(
    const float* __restrict__ dist,
    const float* __restrict__ mask,
    float* __restrict__ out)
{
    extern __shared__ float sm[];
    float* mh_s  = sm;                 // [64][16] (per-kb slab)
    float* enc_s = sm + 64 * 16;       // [16][ET_LD]
    float* S_s   = sm + 64 * 16 + 16 * ET_LD;  // [64][512]

    const int b = blockIdx.y;
    const int p0 = blockIdx.x * 64;
    const int tid = threadIdx.x;
    const int ty = tid >> 4;   // 0..15, 4 rows each
    const int tx = tid & 15;   // 0..15, 4 n per nb

    float2 acc2[4][8][2];
#pragma unroll
    for (int r = 0; r < 4; r++)
#pragma unroll
        for (int nb = 0; nb < 8; nb++) {
            acc2[r][nb][0] = make_float2(0.f, 0.f);
            acc2[r][nb][1] = make_float2(0.f, 0.f);
        }

    const int lrow = tid >> 2, lq = tid & 3;  // mh loader

#pragma unroll 1
    for (int kb = 0; kb < 16; kb++) {
        const int k0 = kb * 16;
        // stage (registers first, then sync)
        float4 mv = *(const float4*)&g_mh[((size_t)(b * PP + p0 + lrow)) * 256 + k0 + lq * 4];
        float4 ev[8];
#pragma unroll
        for (int rep = 0; rep < 8; rep++) {
            const int idx = rep * 256 + tid;      // 0..2047
            const int k = idx >> 7;               // 0..15
            const int nq = (idx & 127) * 4;       // 0..508
            ev[rep] = *(const float4*)&g_encT[((size_t)b * EMB + k0 + k) * NN + nq];
        }
        __syncthreads();
        *(float4*)&mh_s[lrow * 16 + lq * 4] = mv;
#pragma unroll
        for (int rep = 0; rep < 8; rep++) {
            const int idx = rep * 256 + tid;
            const int k = idx >> 7;
            const int nq = (idx & 127) * 4;
            *(float4*)&enc_s[k * ET_LD + nq] = ev[rep];
        }
        __syncthreads();

#pragma unroll
        for (int kq = 0; kq < 4; kq++) {
            float4 aq[4];
#pragma unroll
            for (int r = 0; r < 4; r++)
                aq[r] = *(const float4*)&mh_s[(ty * 4 + r) * 16 + kq * 4];
#pragma unroll
            for (int kk = 0; kk < 4; kk++) {
                const int k = kq * 4 + kk;
                float2 aa[4];
#pragma unroll
                for (int r = 0; r < 4; r++) {
                    const float a = SELC(aq[r], kk);
                    aa[r] = make_float2(a, a);
                }
#pragma unroll
                for (int nb = 0; nb < 8; nb++) {
                    float4 bv = *(const float4*)&enc_s[k * ET_LD + nb * 64 + tx * 4];
                    const float2 b0 = make_float2(bv.x, bv.y);
                    const float2 b1 = make_float2(bv.z, bv.w);
#pragma unroll
                    for (int r = 0; r < 4; r++) {
                        acc2[r][nb][0] = fma2(aa[r], b0, acc2[r][nb][0]);
                        acc2[r][nb][1] = fma2(aa[r], b1, acc2[r][nb][1]);
                    }
                }
            }
        }
    }

    // write S tile
#pragma unroll
    for (int r = 0; r < 4; r++)
#pragma unroll
        for (int nb = 0; nb < 8; nb++) {
            float4 sv;
            sv.x = acc2[r][nb][0].x; sv.y = acc2[r][nb][0].y;
            sv.z = acc2[r][nb][1].x; sv.w = acc2[r][nb][1].y;
            *(float4*)&S_s[(ty * 4 + r) * 512 + nb * 64 + tx * 4] = sv;
        }
    __syncthreads();

    // ------- phase 2: warp per row (8 warps x 8 rows = 64 rows) -------
    const int warp = tid >> 5, lane = tid & 31;
#pragma unroll 1
    for (int rr = 0; rr < 8; rr++) {
        const int r = warp * 8 + rr;
        const int p = p0 + r;
        const float* drow = dist + ((size_t)(b * PP + p)) * NN;
        const float* mrow = mask + ((size_t)(b * PP + p)) * NN;

        unsigned key[16];
        float dv[16];
#pragma unroll
        for (int j = 0; j < 16; j++) {
            dv[j] = drow[j * 32 + lane];
            unsigned u = __float_as_uint(dv[j]);
            key[j] = (u & 0x80000000u) ? ~u : (u ^ 0x80000000u);
        }

        unsigned lo = 0u, hi = 0xffffffffu;
#pragma unroll 1
        for (int it = 0; it < 32; it++) {
            const unsigned mid = lo + ((hi - lo) >> 1);
            int c = 0;
#pragma unroll
            for (int j = 0; j < 16; j++) c += (key[j] <= mid) ? 1 : 0;
            c = __reduce_add_sync(0xffffffffu, c);
            if (c >= 100) hi = mid; else lo = mid + 1;
        }
        const unsigned tau = hi;

        float cv[16];
        float mx = -1e30f;
#pragma unroll
        for (int j = 0; j < 16; j++) {
            const int n = j * 32 + lane;
            float sc = S_s[r * 512 + n] * 0.0625f;
            sc += (key[j] <= tau) ? (-dv[j] * 0.7071067811865475f) : 1.0f;
            const float cc = 10.0f * tanhf(sc) + mrow[n];
            cv[j] = cc;
            mx = fmaxf(mx, cc);
        }
#pragma unroll
        for (int o = 16; o; o >>= 1) mx = fmaxf(mx, __shfl_xor_sync(0xffffffffu, mx, o));

        float lsum = 0.0f;
#pragma unroll
        for (int j = 0; j < 16; j++) {
            cv[j] = __expf(cv[j] - mx);
            lsum += cv[j];
        }
#pragma unroll
        for (int o = 16; o; o >>= 1) lsum += __shfl_xor_sync(0xffffffffu, lsum, o);
        const float inv = 1.0f / lsum;

        float* orow = out + ((size_t)(b * PP + p)) * NN;
#pragma unroll
        for (int j = 0; j < 16; j++) orow[j * 32 + lane] = cv[j] * inv;
    }
}

// ---------------------------------------------------------------------------
// Launch
// ---------------------------------------------------------------------------
extern "C" void kernel_launch(void* const* d_in, const int* in_sizes, int n_in,
                              void* d_out, int out_size)
{
    const float* enc   = (const float*)d_in[0];
    const float* last  = (const float*)d_in[1];
    const float* load  = (const float*)d_in[2];
    const float* dist  = (const float*)d_in[3];
    const float* mask  = (const float*)d_in[6];
    const float* Wq    = (const float*)d_in[7];
    const float* Wk    = (const float*)d_in[8];
    const float* Wv    = (const float*)d_in[9];
    const float* Wc    = (const float*)d_in[10];
    const float* Wcb   = (const float*)d_in[11];
    float* out = (float*)d_out;

    // encoder transpose (independent; used by final kernel)
    transpose_enc_kernel<<<dim3(NN / 32, EMB / 32, BB), dim3(32, 8)>>>(enc);

    const dim3 gg(BB * PP / 128, 4);

    gemm2_kernel<0, false, false, false><<<gg, 256>>>(enc,  Wk, 256, nullptr, nullptr);
    gemm2_kernel<1, false, false, false><<<gg, 256>>>(enc,  Wv, 256, nullptr, nullptr);
    gemm2_kernel<2, true,  false, false><<<gg, 256>>>(last, Wq, 257, load,    nullptr);

    const size_t smA = (size_t)(2 * 16 * KT_LD + 128 * 16) * sizeof(float);  // 74752 B
    cudaFuncSetAttribute(attention3_kernel,
                         cudaFuncAttributeMaxDynamicSharedMemorySize, (int)smA);
    dim3 gA(BB * HH, PP / 128);  // 512 x 4
    attention3_kernel<<<gA, 256, smA>>>(mask);

    gemm2_kernel<3, false, true, true><<<gg, 256>>>(nullptr, Wc, 256, nullptr, Wcb);

    const size_t smF = (size_t)(64 * 16 + 16 * ET_LD + 64 * 512) * sizeof(float);  // 168448 B
    cudaFuncSetAttribute(final2_kernel,
                         cudaFuncAttributeMaxDynamicSharedMemorySize, (int)smF);
    dim3 gF(PP / 64, BB);  // 8 x 32
    final2_kernel<<<gF, 256, smF>>>(dist, mask, out);
}

// round 5
// speedup vs baseline: 2.1474x; 1.2482x over previous
#include <cuda_runtime.h>
#include <cuda_bf16.h>
#include <math.h>

// ---------------------------------------------------------------------------
// Problem constants
// ---------------------------------------------------------------------------
#define BB  32
#define PP  512
#define NN  512
#define EMB 256
#define HH  16
#define DD  16

// Scratch (device globals -- no allocation allowed)
__device__ float g_K[BB * HH * NN * DD];    // [b][h][n][d]
__device__ float g_V[BB * HH * NN * DD];    // [b][h][n][d]
__device__ float g_Q[BB * HH * PP * DD];    // [b][h][p][d]
__device__ float g_att[BB * PP * HH * DD];  // [b][p][h*16+d]
__device__ float g_mh[BB * PP * EMB];       // [b][p][e]

// ---------------------------------------------------------------------------
// Packed fp32x2 helpers (for attention)
// ---------------------------------------------------------------------------
union F2U { float2 f; unsigned long long u; };

__device__ __forceinline__ float2 fma2(float2 a, float2 b, float2 c) {
    F2U A, B, C, D; A.f = a; B.f = b; C.f = c;
    asm("fma.rn.f32x2 %0, %1, %2, %3;" : "=l"(D.u) : "l"(A.u), "l"(B.u), "l"(C.u));
    return D.f;
}
__device__ __forceinline__ float2 mul2(float2 a, float2 b) {
    F2U A, B, D; A.f = a; B.f = b;
    asm("mul.rn.f32x2 %0, %1, %2;" : "=l"(D.u) : "l"(A.u), "l"(B.u));
    return D.f;
}
__device__ __forceinline__ float2 add2(float2 a, float2 b) {
    F2U A, B, D; A.f = a; B.f = b;
    asm("add.rn.f32x2 %0, %1, %2;" : "=l"(D.u) : "l"(A.u), "l"(B.u));
    return D.f;
}

#define SELC(v, i) ((i) == 0 ? (v).x : (i) == 1 ? (v).y : (i) == 2 ? (v).z : (v).w)

// ---------------------------------------------------------------------------
// mma.sync m16n8k16 bf16 helper
// ---------------------------------------------------------------------------
__device__ __forceinline__ void mma16816(float* c, const unsigned* a, const unsigned* b) {
    asm volatile(
        "mma.sync.aligned.m16n8k16.row.col.f32.bf16.bf16.f32 "
        "{%0,%1,%2,%3}, {%4,%5,%6,%7}, {%8,%9}, {%0,%1,%2,%3};"
        : "+f"(c[0]), "+f"(c[1]), "+f"(c[2]), "+f"(c[3])
        : "r"(a[0]), "r"(a[1]), "r"(a[2]), "r"(a[3]), "r"(b[0]), "r"(b[1]));
}

// fp32 -> bf16 hi/lo split
__device__ __forceinline__ void cvt_hl(float x, __nv_bfloat16& h, __nv_bfloat16& l) {
    h = __float2bfloat16(x);
    l = __float2bfloat16(x - __bfloat162float(h));
}

// store float4 as 4 bf16-hi + 4 bf16-lo at p_h/p_l (4-elem aligned)
__device__ __forceinline__ void store_hl4(__nv_bfloat16* p_h, __nv_bfloat16* p_l, float4 v) {
    __nv_bfloat16 h0, l0, h1, l1, h2, l2, h3, l3;
    cvt_hl(v.x, h0, l0); cvt_hl(v.y, h1, l1);
    cvt_hl(v.z, h2, l2); cvt_hl(v.w, h3, l3);
    *(__nv_bfloat162*)(p_h)     = __nv_bfloat162(h0, h1);
    *(__nv_bfloat162*)(p_h + 2) = __nv_bfloat162(h2, h3);
    *(__nv_bfloat162*)(p_l)     = __nv_bfloat162(l0, l1);
    *(__nv_bfloat162*)(p_l + 2) = __nv_bfloat162(l2, l3);
}

#define LDAB 40  // padded bf16 row stride for 32-wide k tiles (80B: conflict-free frags)

// ---------------------------------------------------------------------------
// Tensor-core GEMM  out = A @ W^T (+ rank-1 extra) (+ bias), bf16 hi/lo split.
// A: [M=16384][256] fp32, W: [256][ldw] fp32.
// Block 128x64, BK=32, 256 threads (8 warps as 4m x 2n), warp tile 32x32.
// ---------------------------------------------------------------------------
template <int OUT_SEL, bool EXTRA, bool BIAS, bool SRC_ATT>
__global__ __launch_bounds__(256) void gemm3_kernel(
    const float* __restrict__ A,
    const float* __restrict__ W, int ldw,
    const float* __restrict__ exA,
    const float* __restrict__ bias)
{
    __shared__ __nv_bfloat16 Ah[128 * LDAB], Al[128 * LDAB];
    __shared__ __nv_bfloat16 Bh[64 * LDAB],  Bl[64 * LDAB];

    const float* Ap = SRC_ATT ? (const float*)g_att : A;
    float* out = (OUT_SEL == 0) ? g_K : (OUT_SEL == 1) ? g_V
               : (OUT_SEL == 2) ? g_Q : g_mh;

    const int m0 = blockIdx.x * 128;
    const int n0 = blockIdx.y * 64;
    const int tid = threadIdx.x;
    const int warp = tid >> 5, lane = tid & 31;
    const int wm = warp >> 1, wn = warp & 1;
    const int gr = lane >> 2, qc = lane & 3;

    float acc[2][4][4];
#pragma unroll
    for (int mt = 0; mt < 2; mt++)
#pragma unroll
        for (int nt = 0; nt < 4; nt++)
#pragma unroll
            for (int e = 0; e < 4; e++) acc[mt][nt][e] = 0.0f;

    for (int k0 = 0; k0 < 256; k0 += 32) {
        // ---- stage loads (regs first) ----
        float4 av[4];
#pragma unroll
        for (int i = 0; i < 4; i++) {
            const int lin = tid + i * 256;
            const int row = lin >> 3, c4 = lin & 7;
            av[i] = *(const float4*)(Ap + (size_t)(m0 + row) * 256 + k0 + c4 * 4);
        }
        float wv[2][4];
#pragma unroll
        for (int i = 0; i < 2; i++) {
            const int lin = tid + i * 256;
            const int row = lin >> 3, c4 = lin & 7;
            const float* wp = W + (size_t)(n0 + row) * ldw + k0 + c4 * 4;
            if (EXTRA) {  // ldw=257, unaligned
                wv[i][0] = wp[0]; wv[i][1] = wp[1]; wv[i][2] = wp[2]; wv[i][3] = wp[3];
            } else {
                float4 t = *(const float4*)wp;
                wv[i][0] = t.x; wv[i][1] = t.y; wv[i][2] = t.z; wv[i][3] = t.w;
            }
        }
        __syncthreads();
#pragma unroll
        for (int i = 0; i < 4; i++) {
            const int lin = tid + i * 256;
            const int row = lin >> 3, c4 = lin & 7;
            store_hl4(&Ah[row * LDAB + c4 * 4], &Al[row * LDAB + c4 * 4], av[i]);
        }
#pragma unroll
        for (int i = 0; i < 2; i++) {
            const int lin = tid + i * 256;
            const int row = lin >> 3, c4 = lin & 7;
            float4 t = make_float4(wv[i][0], wv[i][1], wv[i][2], wv[i][3]);
            store_hl4(&Bh[row * LDAB + c4 * 4], &Bl[row * LDAB + c4 * 4], t);
        }
        __syncthreads();

        // ---- compute: 2 k16 steps ----
#pragma unroll
        for (int ks = 0; ks < 32; ks += 16) {
            unsigned ah[2][4], al[2][4], bh[4][2], bl[4][2];
#pragma unroll
            for (int mt = 0; mt < 2; mt++) {
                const int base = (wm * 32 + mt * 16 + gr) * LDAB + ks + 2 * qc;
                ah[mt][0] = *(const unsigned*)&Ah[base];
                ah[mt][1] = *(const unsigned*)&Ah[base + 8 * LDAB];
                ah[mt][2] = *(const unsigned*)&Ah[base + 8];
                ah[mt][3] = *(const unsigned*)&Ah[base + 8 * LDAB + 8];
                al[mt][0] = *(const unsigned*)&Al[base];
                al[mt][1] = *(const unsigned*)&Al[base + 8 * LDAB];
                al[mt][2] = *(const unsigned*)&Al[base + 8];
                al[mt][3] = *(const unsigned*)&Al[base + 8 * LDAB + 8];
            }
#pragma unroll
            for (int nt = 0; nt < 4; nt++) {
                const int base = (wn * 32 + nt * 8 + gr) * LDAB + ks + 2 * qc;
                bh[nt][0] = *(const unsigned*)&Bh[base];
                bh[nt][1] = *(const unsigned*)&Bh[base + 8];
                bl[nt][0] = *(const unsigned*)&Bl[base];
                bl[nt][1] = *(const unsigned*)&Bl[base + 8];
            }
#pragma unroll
            for (int mt = 0; mt < 2; mt++)
#pragma unroll
                for (int nt = 0; nt < 4; nt++) {
                    mma16816(acc[mt][nt], ah[mt], bh[nt]);
                    mma16816(acc[mt][nt], ah[mt], bl[nt]);
                    mma16816(acc[mt][nt], al[mt], bh[nt]);
                }
        }
    }

    // ---- epilogue ----
#pragma unroll
    for (int mt = 0; mt < 2; mt++) {
#pragma unroll
        for (int part = 0; part < 2; part++) {
            const int m = m0 + wm * 32 + mt * 16 + gr + part * 8;
            float ex = 0.0f;
            if (EXTRA) ex = exA[m];
#pragma unroll
            for (int nt = 0; nt < 4; nt++) {
                const int col = n0 + wn * 32 + nt * 8 + 2 * qc;
                float2 v = make_float2(acc[mt][nt][part * 2], acc[mt][nt][part * 2 + 1]);
                if (EXTRA) {
                    v.x += ex * W[(size_t)col * ldw + 256];
                    v.y += ex * W[(size_t)(col + 1) * ldw + 256];
                }
                if (BIAS) { v.x += bias[col]; v.y += bias[col + 1]; }
                if (OUT_SEL < 3) {
                    const int b = m >> 9, n = m & 511;
                    const int h = col >> 4, d = col & 15;
                    *(float2*)&out[(((size_t)(b * 16 + h) * 512) + n) * 16 + d] = v;
                } else {
                    *(float2*)&out[(size_t)m * 256 + col] = v;
                }
            }
        }
    }
}

// ---------------------------------------------------------------------------
// Flash attention v3 (unchanged from R4): block per (b,h, 128-row p-tile).
// ---------------------------------------------------------------------------
#define KT_LD 520

__global__ __launch_bounds__(256) void attention3_kernel(
    const float* __restrict__ mask)
{
    extern __shared__ float sm[];
    float* Kt = sm;
    float* Vt = sm + 16 * KT_LD;
    float* Qs = sm + 32 * KT_LD;

    const int bh = blockIdx.x;
    const int b  = bh >> 4;
    const int h  = bh & 15;
    const int p0 = blockIdx.y * 128;
    const int tid = threadIdx.x;

    const float* Kg = g_K + (size_t)bh * (NN * DD);
    const float* Vg = g_V + (size_t)bh * (NN * DD);
    for (int idx = tid; idx < NN * DD; idx += 256) {
        const int n = idx >> 4, d = idx & 15;
        Kt[d * KT_LD + n] = Kg[idx];
        Vt[d * KT_LD + n] = Vg[idx];
    }
    {
        const float4* Qg = (const float4*)(g_Q + ((size_t)bh * PP + p0) * DD);
        ((float4*)Qs)[tid] = Qg[tid];
        ((float4*)Qs)[tid + 256] = Qg[tid + 256];
    }
    __syncthreads();

    const int tx = tid & 7;
    const int ty = tid >> 3;
    const int qb = ty * 4 * 16;

    float2 O2[4][8];
    float mxs[4], ls[4];
#pragma unroll
    for (int r = 0; r < 4; r++) {
        mxs[r] = -1e30f; ls[r] = 0.0f;
#pragma unroll
        for (int j = 0; j < 8; j++) O2[r][j] = make_float2(0.f, 0.f);
    }

#pragma unroll 1
    for (int c = 0; c < 4; c++) {
        const int nb = c * 128 + tx * 4;

        float2 s2[4][8];
#pragma unroll
        for (int r = 0; r < 4; r++)
#pragma unroll
            for (int j = 0; j < 8; j++) s2[r][j] = make_float2(0.f, 0.f);

#pragma unroll
        for (int dq = 0; dq < 4; dq++) {
            float4 qv[4];
#pragma unroll
            for (int r = 0; r < 4; r++)
                qv[r] = *(const float4*)&Qs[qb + r * 16 + dq * 4];
#pragma unroll
            for (int dd = 0; dd < 4; dd++) {
                const int d = dq * 4 + dd;
                const float* kr = &Kt[d * KT_LD + nb];
                float4 ka = *(const float4*)(kr);
                float4 kb4 = *(const float4*)(kr + 32);
                float4 kc = *(const float4*)(kr + 64);
                float4 kd = *(const float4*)(kr + 96);
                float2 kp[8] = {{ka.x, ka.y}, {ka.z, ka.w},
                                {kb4.x, kb4.y}, {kb4.z, kb4.w},
                                {kc.x, kc.y}, {kc.z, kc.w},
                                {kd.x, kd.y}, {kd.z, kd.w}};
#pragma unroll
                for (int r = 0; r < 4; r++) {
                    const float qd = SELC(qv[r], dd);
                    const float2 qq = make_float2(qd, qd);
#pragma unroll
                    for (int j = 0; j < 8; j++)
                        s2[r][j] = fma2(qq, kp[j], s2[r][j]);
                }
            }
        }

        const float2 qtr = make_float2(0.25f, 0.25f);
#pragma unroll
        for (int r = 0; r < 4; r++) {
            const float* mp_ = mask + ((size_t)(b * PP + p0 + ty * 4 + r)) * NN + nb;
#pragma unroll
            for (int seg = 0; seg < 4; seg++) {
                float4 mv = *(const float4*)(mp_ + seg * 32);
                s2[r][seg * 2 + 0] = fma2(s2[r][seg * 2 + 0], qtr, make_float2(mv.x, mv.y));
                s2[r][seg * 2 + 1] = fma2(s2[r][seg * 2 + 1], qtr, make_float2(mv.z, mv.w));
            }
        }

#pragma unroll
        for (int r = 0; r < 4; r++) {
            float cm = fmaxf(s2[r][0].x, s2[r][0].y);
#pragma unroll
            for (int j = 1; j < 8; j++)
                cm = fmaxf(cm, fmaxf(s2[r][j].x, s2[r][j].y));
#pragma unroll
            for (int o = 1; o < 8; o <<= 1)
                cm = fmaxf(cm, __shfl_xor_sync(0xffffffffu, cm, o));
            const float mnew = fmaxf(mxs[r], cm);
            const float fs = __expf(mxs[r] - mnew);
            mxs[r] = mnew;
            ls[r] *= fs;
            const float2 fs2 = make_float2(fs, fs);
#pragma unroll
            for (int j = 0; j < 8; j++) O2[r][j] = mul2(O2[r][j], fs2);
            float2 sacc = make_float2(0.f, 0.f);
#pragma unroll
            for (int j = 0; j < 8; j++) {
                s2[r][j].x = __expf(s2[r][j].x - mnew);
                s2[r][j].y = __expf(s2[r][j].y - mnew);
                sacc = add2(sacc, s2[r][j]);
            }
            ls[r] += sacc.x + sacc.y;
        }

#pragma unroll
        for (int d = 0; d < 16; d++) {
            const float* vr = &Vt[d * KT_LD + nb];
            float4 va = *(const float4*)(vr);
            float4 vb = *(const float4*)(vr + 32);
            float4 vc = *(const float4*)(vr + 64);
            float4 vd = *(const float4*)(vr + 96);
            float2 vp[8] = {{va.x, va.y}, {va.z, va.w},
                            {vb.x, vb.y}, {vb.z, vb.w},
                            {vc.x, vc.y}, {vc.z, vc.w},
                            {vd.x, vd.y}, {vd.z, vd.w}};
#pragma unroll
            for (int r = 0; r < 4; r++) {
                float2 t2 = mul2(s2[r][0], vp[0]);
#pragma unroll
                for (int j = 1; j < 8; j++) t2 = fma2(s2[r][j], vp[j], t2);
                const float t = t2.x + t2.y;
                if (d & 1) O2[r][d >> 1].y += t;
                else       O2[r][d >> 1].x += t;
            }
        }
    }

#pragma unroll
    for (int r = 0; r < 4; r++) {
#pragma unroll
        for (int o = 1; o < 8; o <<= 1)
            ls[r] += __shfl_xor_sync(0xffffffffu, ls[r], o);
#pragma unroll
        for (int j = 0; j < 8; j++) {
#pragma unroll
            for (int o = 1; o < 8; o <<= 1) {
                O2[r][j].x += __shfl_xor_sync(0xffffffffu, O2[r][j].x, o);
                O2[r][j].y += __shfl_xor_sync(0xffffffffu, O2[r][j].y, o);
            }
        }
    }

#pragma unroll
    for (int r = 0; r < 4; r++) {
        if (tx == r) {
            const float inv = 1.0f / ls[r];
            const int p = p0 + ty * 4 + r;
            float* op = g_att + ((size_t)(b * PP + p)) * (HH * DD) + h * DD;
#pragma unroll
            for (int u = 0; u < 4; u++) {
                float4 ov;
                ov.x = O2[r][u * 2 + 0].x * inv;
                ov.y = O2[r][u * 2 + 0].y * inv;
                ov.z = O2[r][u * 2 + 1].x * inv;
                ov.w = O2[r][u * 2 + 1].y * inv;
                *(float4*)(op + u * 4) = ov;
            }
        }
    }
}

// ---------------------------------------------------------------------------
// Final fused kernel v3: block per (b, 64-row p-tile). 256 threads.
// Phase 1: S = mh @ enc^T via bf16-split mma (enc [n][k] is col-major B).
//          8 warps = 2m x 4n; per 128-n chunk, warp tile 32x32; BK=32.
// Phase 2: per-row topk-threshold + tanh-clip + softmax (warp per row).
// ---------------------------------------------------------------------------
__global__ __launch_bounds__(256) void final3_kernel(
    const float* __restrict__ enc,
    const float* __restrict__ dist,
    const float* __restrict__ mask,
    float* __restrict__ out)
{
    extern __shared__ char smraw[];
    __nv_bfloat16* Ah = (__nv_bfloat16*)smraw;       // [64][LDAB]
    __nv_bfloat16* Al = Ah + 64 * LDAB;
    __nv_bfloat16* Bh = Al + 64 * LDAB;              // [128][LDAB]
    __nv_bfloat16* Bl = Bh + 128 * LDAB;
    float* S_s = (float*)(Bl + 128 * LDAB);          // [64][512]

    const int b = blockIdx.y;
    const int p0 = blockIdx.x * 64;
    const int tid = threadIdx.x;
    const int warp = tid >> 5, lane = tid & 31;
    const int wm = warp >> 2, wn = warp & 3;
    const int gr = lane >> 2, qc = lane & 3;

    const float* encb = enc + (size_t)b * NN * EMB;

#pragma unroll 1
    for (int nc = 0; nc < 4; nc++) {
        float acc[2][4][4];
#pragma unroll
        for (int mt = 0; mt < 2; mt++)
#pragma unroll
            for (int nt = 0; nt < 4; nt++)
#pragma unroll
                for (int e = 0; e < 4; e++) acc[mt][nt][e] = 0.0f;

#pragma unroll 1
        for (int k0 = 0; k0 < 256; k0 += 32) {
            float4 av[2];
#pragma unroll
            for (int i = 0; i < 2; i++) {
                const int lin = tid + i * 256;
                const int row = lin >> 3, c4 = lin & 7;
                av[i] = *(const float4*)&g_mh[((size_t)(b * PP + p0 + row)) * 256 + k0 + c4 * 4];
            }
            float4 bv[4];
#pragma unroll
            for (int i = 0; i < 4; i++) {
                const int lin = tid + i * 256;
                const int row = lin >> 3, c4 = lin & 7;
                bv[i] = *(const float4*)&encb[(size_t)(nc * 128 + row) * 256 + k0 + c4 * 4];
            }
            __syncthreads();
#pragma unroll
            for (int i = 0; i < 2; i++) {
                const int lin = tid + i * 256;
                const int row = lin >> 3, c4 = lin & 7;
                store_hl4(&Ah[row * LDAB + c4 * 4], &Al[row * LDAB + c4 * 4], av[i]);
            }
#pragma unroll
            for (int i = 0; i < 4; i++) {
                const int lin = tid + i * 256;
                const int row = lin >> 3, c4 = lin & 7;
                store_hl4(&Bh[row * LDAB + c4 * 4], &Bl[row * LDAB + c4 * 4], bv[i]);
            }
            __syncthreads();

#pragma unroll
            for (int ks = 0; ks < 32; ks += 16) {
                unsigned ah[2][4], al[2][4], bh[4][2], bl[4][2];
#pragma unroll
                for (int mt = 0; mt < 2; mt++) {
                    const int base = (wm * 32 + mt * 16 + gr) * LDAB + ks + 2 * qc;
                    ah[mt][0] = *(const unsigned*)&Ah[base];
                    ah[mt][1] = *(const unsigned*)&Ah[base + 8 * LDAB];
                    ah[mt][2] = *(const unsigned*)&Ah[base + 8];
                    ah[mt][3] = *(const unsigned*)&Ah[base + 8 * LDAB + 8];
                    al[mt][0] = *(const unsigned*)&Al[base];
                    al[mt][1] = *(const unsigned*)&Al[base + 8 * LDAB];
                    al[mt][2] = *(const unsigned*)&Al[base + 8];
                    al[mt][3] = *(const unsigned*)&Al[base + 8 * LDAB + 8];
                }
#pragma unroll
                for (int nt = 0; nt < 4; nt++) {
                    const int base = (wn * 32 + nt * 8 + gr) * LDAB + ks + 2 * qc;
                    bh[nt][0] = *(const unsigned*)&Bh[base];
                    bh[nt][1] = *(const unsigned*)&Bh[base + 8];
                    bl[nt][0] = *(const unsigned*)&Bl[base];
                    bl[nt][1] = *(const unsigned*)&Bl[base + 8];
                }
#pragma unroll
                for (int mt = 0; mt < 2; mt++)
#pragma unroll
                    for (int nt = 0; nt < 4; nt++) {
                        mma16816(acc[mt][nt], ah[mt], bh[nt]);
                        mma16816(acc[mt][nt], ah[mt], bl[nt]);
                        mma16816(acc[mt][nt], al[mt], bh[nt]);
                    }
            }
        }

        // dump this n-chunk into S_s
#pragma unroll
        for (int mt = 0; mt < 2; mt++)
#pragma unroll
            for (int part = 0; part < 2; part++) {
                const int r = wm * 32 + mt * 16 + gr + part * 8;
#pragma unroll
                for (int nt = 0; nt < 4; nt++) {
                    const int col = nc * 128 + wn * 32 + nt * 8 + 2 * qc;
                    float2 v = make_float2(acc[mt][nt][part * 2], acc[mt][nt][part * 2 + 1]);
                    *(float2*)&S_s[r * 512 + col] = v;
                }
            }
    }
    __syncthreads();

    // ------- phase 2: warp per row (8 warps x 8 rows = 64 rows) -------
#pragma unroll 1
    for (int rr = 0; rr < 8; rr++) {
        const int r = warp * 8 + rr;
        const int p = p0 + r;
        const float* drow = dist + ((size_t)(b * PP + p)) * NN;
        const float* mrow = mask + ((size_t)(b * PP + p)) * NN;

        unsigned key[16];
        float dv[16];
#pragma unroll
        for (int j = 0; j < 16; j++) {
            dv[j] = drow[j * 32 + lane];
            unsigned u = __float_as_uint(dv[j]);
            key[j] = (u & 0x80000000u) ? ~u : (u ^ 0x80000000u);
        }

        unsigned lo = 0u, hi = 0xffffffffu;
#pragma unroll 1
        for (int it = 0; it < 32; it++) {
            const unsigned mid = lo + ((hi - lo) >> 1);
            int c = 0;
#pragma unroll
            for (int j = 0; j < 16; j++) c += (key[j] <= mid) ? 1 : 0;
            c = __reduce_add_sync(0xffffffffu, c);
            if (c >= 100) hi = mid; else lo = mid + 1;
        }
        const unsigned tau = hi;

        float cv[16];
        float mx = -1e30f;
#pragma unroll
        for (int j = 0; j < 16; j++) {
            const int n = j * 32 + lane;
            float sc = S_s[r * 512 + n] * 0.0625f;
            sc += (key[j] <= tau) ? (-dv[j] * 0.7071067811865475f) : 1.0f;
            const float cc = 10.0f * tanhf(sc) + mrow[n];
            cv[j] = cc;
            mx = fmaxf(mx, cc);
        }
#pragma unroll
        for (int o = 16; o; o >>= 1) mx = fmaxf(mx, __shfl_xor_sync(0xffffffffu, mx, o));

        float lsum = 0.0f;
#pragma unroll
        for (int j = 0; j < 16; j++) {
            cv[j] = __expf(cv[j] - mx);
            lsum += cv[j];
        }
#pragma unroll
        for (int o = 16; o; o >>= 1) lsum += __shfl_xor_sync(0xffffffffu, lsum, o);
        const float inv = 1.0f / lsum;

        float* orow = out + ((size_t)(b * PP + p)) * NN;
#pragma unroll
        for (int j = 0; j < 16; j++) orow[j * 32 + lane] = cv[j] * inv;
    }
}

// ---------------------------------------------------------------------------
// Launch
// ---------------------------------------------------------------------------
extern "C" void kernel_launch(void* const* d_in, const int* in_sizes, int n_in,
                              void* d_out, int out_size)
{
    const float* enc   = (const float*)d_in[0];
    const float* last  = (const float*)d_in[1];
    const float* load  = (const float*)d_in[2];
    const float* dist  = (const float*)d_in[3];
    const float* mask  = (const float*)d_in[6];
    const float* Wq    = (const float*)d_in[7];
    const float* Wk    = (const float*)d_in[8];
    const float* Wv    = (const float*)d_in[9];
    const float* Wc    = (const float*)d_in[10];
    const float* Wcb   = (const float*)d_in[11];
    float* out = (float*)d_out;

    const dim3 gg(BB * PP / 128, 4);  // 128 x 4

    gemm3_kernel<0, false, false, false><<<gg, 256>>>(enc,  Wk, 256, nullptr, nullptr);
    gemm3_kernel<1, false, false, false><<<gg, 256>>>(enc,  Wv, 256, nullptr, nullptr);
    gemm3_kernel<2, true,  false, false><<<gg, 256>>>(last, Wq, 257, load,    nullptr);

    const size_t smA = (size_t)(2 * 16 * KT_LD + 128 * 16) * sizeof(float);  // 74752 B
    cudaFuncSetAttribute(attention3_kernel,
                         cudaFuncAttributeMaxDynamicSharedMemorySize, (int)smA);
    dim3 gA(BB * HH, PP / 128);  // 512 x 4
    attention3_kernel<<<gA, 256, smA>>>(mask);

    gemm3_kernel<3, false, true, true><<<gg, 256>>>(nullptr, Wc, 256, nullptr, Wcb);

    // final: bf16 staging (30720 B) + S_s fp32 (131072 B)
    const size_t smF = (size_t)(64 + 64 + 128 + 128) * LDAB * sizeof(__nv_bfloat16)
                     + (size_t)64 * 512 * sizeof(float);  // 161792 B
    cudaFuncSetAttribute(final3_kernel,
                         cudaFuncAttributeMaxDynamicSharedMemorySize, (int)smF);
    dim3 gF(PP / 64, BB);  // 8 x 32
    final3_kernel<<<gF, 256, smF>>>(enc, dist, mask, out);
}

// round 6
// speedup vs baseline: 2.3774x; 1.1071x over previous
#include <cuda_runtime.h>
#include <cuda_bf16.h>
#include <math.h>

// ---------------------------------------------------------------------------
// Problem constants
// ---------------------------------------------------------------------------
#define BB  32
#define PP  512
#define NN  512
#define EMB 256
#define HH  16
#define DD  16

// Scratch (device globals -- no allocation allowed)
__device__ float g_K[BB * HH * NN * DD];    // [b][h][n][d]
__device__ float g_V[BB * HH * NN * DD];    // [b][h][n][d]
__device__ float g_Q[BB * HH * PP * DD];    // [b][h][p][d]
__device__ float g_att[BB * PP * HH * DD];  // [b][p][h*16+d]
__device__ float g_mh[BB * PP * EMB];       // [b][p][e]

// ---------------------------------------------------------------------------
// mma.sync m16n8k16 bf16 helper
// ---------------------------------------------------------------------------
__device__ __forceinline__ void mma16816(float* c, const unsigned* a, const unsigned* b) {
    asm volatile(
        "mma.sync.aligned.m16n8k16.row.col.f32.bf16.bf16.f32 "
        "{%0,%1,%2,%3}, {%4,%5,%6,%7}, {%8,%9}, {%0,%1,%2,%3};"
        : "+f"(c[0]), "+f"(c[1]), "+f"(c[2]), "+f"(c[3])
        : "r"(a[0]), "r"(a[1]), "r"(a[2]), "r"(a[3]), "r"(b[0]), "r"(b[1]));
}

// pack two fp32 -> bf16x2 (lo in low half, hi in high half)
__device__ __forceinline__ unsigned pack_bf16x2(float lo, float hi) {
    unsigned r;
    asm("cvt.rn.satfinite.bf16x2.f32 %0, %1, %2;" : "=r"(r) : "f"(hi), "f"(lo));
    return r;
}

// pack hi/lo split pair: ph = bf16(x0,x1); pl = bf16 residuals
__device__ __forceinline__ void pack_hl(float x0, float x1, unsigned& ph, unsigned& pl) {
    ph = pack_bf16x2(x0, x1);
    const float h0 = __uint_as_float(ph << 16);
    const float h1 = __uint_as_float(ph & 0xFFFF0000u);
    pl = pack_bf16x2(x0 - h0, x1 - h1);
}

// fp32 -> bf16 hi/lo split
__device__ __forceinline__ void cvt_hl(float x, __nv_bfloat16& h, __nv_bfloat16& l) {
    h = __float2bfloat16(x);
    l = __float2bfloat16(x - __bfloat162float(h));
}

// store float4 as 4 bf16-hi + 4 bf16-lo at p_h/p_l (4-elem aligned)
__device__ __forceinline__ void store_hl4(__nv_bfloat16* p_h, __nv_bfloat16* p_l, float4 v) {
    unsigned h01, l01, h23, l23;
    pack_hl(v.x, v.y, h01, l01);
    pack_hl(v.z, v.w, h23, l23);
    *(unsigned*)(p_h)     = h01;
    *(unsigned*)(p_h + 2) = h23;
    *(unsigned*)(p_l)     = l01;
    *(unsigned*)(p_l + 2) = l23;
}

#define LDAB 40  // padded bf16 row stride for 32-wide k tiles

// ---------------------------------------------------------------------------
// Tensor-core GEMM  out = A @ W^T (+ rank-1 extra) (+ bias), bf16 hi/lo split.
// Block 128x64, BK=32, 256 threads (8 warps as 4m x 2n), warp tile 32x32.
// ---------------------------------------------------------------------------
template <int OUT_SEL, bool EXTRA, bool BIAS, bool SRC_ATT>
__global__ __launch_bounds__(256) void gemm3_kernel(
    const float* __restrict__ A,
    const float* __restrict__ W, int ldw,
    const float* __restrict__ exA,
    const float* __restrict__ bias)
{
    __shared__ __nv_bfloat16 Ah[128 * LDAB], Al[128 * LDAB];
    __shared__ __nv_bfloat16 Bh[64 * LDAB],  Bl[64 * LDAB];

    const float* Ap = SRC_ATT ? (const float*)g_att : A;
    float* out = (OUT_SEL == 0) ? g_K : (OUT_SEL == 1) ? g_V
               : (OUT_SEL == 2) ? g_Q : g_mh;

    const int m0 = blockIdx.x * 128;
    const int n0 = blockIdx.y * 64;
    const int tid = threadIdx.x;
    const int warp = tid >> 5, lane = tid & 31;
    const int wm = warp >> 1, wn = warp & 1;
    const int gr = lane >> 2, qc = lane & 3;

    float acc[2][4][4];
#pragma unroll
    for (int mt = 0; mt < 2; mt++)
#pragma unroll
        for (int nt = 0; nt < 4; nt++)
#pragma unroll
            for (int e = 0; e < 4; e++) acc[mt][nt][e] = 0.0f;

    for (int k0 = 0; k0 < 256; k0 += 32) {
        float4 av[4];
#pragma unroll
        for (int i = 0; i < 4; i++) {
            const int lin = tid + i * 256;
            const int row = lin >> 3, c4 = lin & 7;
            av[i] = *(const float4*)(Ap + (size_t)(m0 + row) * 256 + k0 + c4 * 4);
        }
        float wv[2][4];
#pragma unroll
        for (int i = 0; i < 2; i++) {
            const int lin = tid + i * 256;
            const int row = lin >> 3, c4 = lin & 7;
            const float* wp = W + (size_t)(n0 + row) * ldw + k0 + c4 * 4;
            if (EXTRA) {
                wv[i][0] = wp[0]; wv[i][1] = wp[1]; wv[i][2] = wp[2]; wv[i][3] = wp[3];
            } else {
                float4 t = *(const float4*)wp;
                wv[i][0] = t.x; wv[i][1] = t.y; wv[i][2] = t.z; wv[i][3] = t.w;
            }
        }
        __syncthreads();
#pragma unroll
        for (int i = 0; i < 4; i++) {
            const int lin = tid + i * 256;
            const int row = lin >> 3, c4 = lin & 7;
            store_hl4(&Ah[row * LDAB + c4 * 4], &Al[row * LDAB + c4 * 4], av[i]);
        }
#pragma unroll
        for (int i = 0; i < 2; i++) {
            const int lin = tid + i * 256;
            const int row = lin >> 3, c4 = lin & 7;
            float4 t = make_float4(wv[i][0], wv[i][1], wv[i][2], wv[i][3]);
            store_hl4(&Bh[row * LDAB + c4 * 4], &Bl[row * LDAB + c4 * 4], t);
        }
        __syncthreads();

#pragma unroll
        for (int ks = 0; ks < 32; ks += 16) {
            unsigned ah[2][4], al[2][4], bh[4][2], bl[4][2];
#pragma unroll
            for (int mt = 0; mt < 2; mt++) {
                const int base = (wm * 32 + mt * 16 + gr) * LDAB + ks + 2 * qc;
                ah[mt][0] = *(const unsigned*)&Ah[base];
                ah[mt][1] = *(const unsigned*)&Ah[base + 8 * LDAB];
                ah[mt][2] = *(const unsigned*)&Ah[base + 8];
                ah[mt][3] = *(const unsigned*)&Ah[base + 8 * LDAB + 8];
                al[mt][0] = *(const unsigned*)&Al[base];
                al[mt][1] = *(const unsigned*)&Al[base + 8 * LDAB];
                al[mt][2] = *(const unsigned*)&Al[base + 8];
                al[mt][3] = *(const unsigned*)&Al[base + 8 * LDAB + 8];
            }
#pragma unroll
            for (int nt = 0; nt < 4; nt++) {
                const int base = (wn * 32 + nt * 8 + gr) * LDAB + ks + 2 * qc;
                bh[nt][0] = *(const unsigned*)&Bh[base];
                bh[nt][1] = *(const unsigned*)&Bh[base + 8];
                bl[nt][0] = *(const unsigned*)&Bl[base];
                bl[nt][1] = *(const unsigned*)&Bl[base + 8];
            }
#pragma unroll
            for (int mt = 0; mt < 2; mt++)
#pragma unroll
                for (int nt = 0; nt < 4; nt++) {
                    mma16816(acc[mt][nt], ah[mt], bh[nt]);
                    mma16816(acc[mt][nt], ah[mt], bl[nt]);
                    mma16816(acc[mt][nt], al[mt], bh[nt]);
                }
        }
    }

#pragma unroll
    for (int mt = 0; mt < 2; mt++) {
#pragma unroll
        for (int part = 0; part < 2; part++) {
            const int m = m0 + wm * 32 + mt * 16 + gr + part * 8;
            float ex = 0.0f;
            if (EXTRA) ex = exA[m];
#pragma unroll
            for (int nt = 0; nt < 4; nt++) {
                const int col = n0 + wn * 32 + nt * 8 + 2 * qc;
                float2 v = make_float2(acc[mt][nt][part * 2], acc[mt][nt][part * 2 + 1]);
                if (EXTRA) {
                    v.x += ex * W[(size_t)col * ldw + 256];
                    v.y += ex * W[(size_t)(col + 1) * ldw + 256];
                }
                if (BIAS) { v.x += bias[col]; v.y += bias[col + 1]; }
                if (OUT_SEL < 3) {
                    const int b = m >> 9, n = m & 511;
                    const int h = col >> 4, d = col & 15;
                    *(float2*)&out[(((size_t)(b * 16 + h) * 512) + n) * 16 + d] = v;
                } else {
                    *(float2*)&out[(size_t)m * 256 + col] = v;
                }
            }
        }
    }
}

// ---------------------------------------------------------------------------
// Flash attention v4 (tensor cores): block per (b,h,128-p tile), 8 warps.
// Warp owns a full 16-row m-tile across all n (softmax stays in-warp).
// S = QK^T via m16n8k16 (k=d=16, one step), bf16 hi/lo split (3 mmas).
// P converted in-register to A-fragments; O += P V (k=128/chunk, split).
// Q pre-scaled by 0.25 during split. V staged transposed [d][n], pad 520.
// ---------------------------------------------------------------------------
#define VT_LD 520

__global__ __launch_bounds__(256) void attention4_kernel(
    const float* __restrict__ mask)
{
    extern __shared__ __nv_bfloat16 smb[];
    __nv_bfloat16* Kh  = smb;                 // [512][16]
    __nv_bfloat16* Kl  = Kh + 512 * 16;
    __nv_bfloat16* Vth = Kl + 512 * 16;       // [16][VT_LD]
    __nv_bfloat16* Vtl = Vth + 16 * VT_LD;
    __nv_bfloat16* Qh  = Vtl + 16 * VT_LD;    // [128][16]
    __nv_bfloat16* Ql  = Qh + 128 * 16;

    const int bh = blockIdx.x;
    const int b  = bh >> 4;
    const int h  = bh & 15;
    const int p0 = blockIdx.y * 128;
    const int tid = threadIdx.x;

    // ---- stage K (hi/lo) ----
    const float4* Kg4 = (const float4*)(g_K + (size_t)bh * (NN * DD));
    for (int i = tid; i < 2048; i += 256) {
        float4 v = Kg4[i];
        const int row = i >> 2, dg = (i & 3) * 4;
        store_hl4(&Kh[row * 16 + dg], &Kl[row * 16 + dg], v);
    }
    // ---- stage V transposed (hi/lo) ----
    const float4* Vg4 = (const float4*)(g_V + (size_t)bh * (NN * DD));
    for (int i = tid; i < 2048; i += 256) {
        float4 v = Vg4[i];
        const int n = i >> 2, dg = (i & 3) * 4;
        float x[4] = {v.x, v.y, v.z, v.w};
#pragma unroll
        for (int j = 0; j < 4; j++) {
            __nv_bfloat16 hh, ll;
            cvt_hl(x[j], hh, ll);
            Vth[(dg + j) * VT_LD + n] = hh;
            Vtl[(dg + j) * VT_LD + n] = ll;
        }
    }
    // ---- stage Q (scaled by 0.25, hi/lo) ----
    const float4* Qg4 = (const float4*)(g_Q + ((size_t)bh * PP + p0) * DD);
    for (int i = tid; i < 512; i += 256) {
        float4 v = Qg4[i];
        v.x *= 0.25f; v.y *= 0.25f; v.z *= 0.25f; v.w *= 0.25f;
        const int row = i >> 2, dg = (i & 3) * 4;
        store_hl4(&Qh[row * 16 + dg], &Ql[row * 16 + dg], v);
    }
    __syncthreads();

    const int warp = tid >> 5, lane = tid & 31;
    const int gr = lane >> 2, qc = lane & 3;
    const int prow = warp * 16;

    // Q A-fragments (persist)
    unsigned qh[4], ql[4];
    {
        const int base = (prow + gr) * 16 + 2 * qc;
        qh[0] = *(const unsigned*)&Qh[base];
        qh[1] = *(const unsigned*)&Qh[base + 8 * 16];
        qh[2] = *(const unsigned*)&Qh[base + 8];
        qh[3] = *(const unsigned*)&Qh[base + 8 * 16 + 8];
        ql[0] = *(const unsigned*)&Ql[base];
        ql[1] = *(const unsigned*)&Ql[base + 8 * 16];
        ql[2] = *(const unsigned*)&Ql[base + 8];
        ql[3] = *(const unsigned*)&Ql[base + 8 * 16 + 8];
    }

    float m0 = -1e30f, m1 = -1e30f, l0 = 0.0f, l1 = 0.0f;
    float O[2][4];
#pragma unroll
    for (int nd = 0; nd < 2; nd++)
#pragma unroll
        for (int e = 0; e < 4; e++) O[nd][e] = 0.0f;

    const size_t mrow0 = ((size_t)(b * PP + p0 + prow + gr)) * NN;
    const size_t mrow1 = ((size_t)(b * PP + p0 + prow + gr + 8)) * NN;

#pragma unroll 1
    for (int c = 0; c < 4; c++) {
        const int n0c = c * 128;

        // ---- S = Q K^T (16 n-frags x 3 split mmas) ----
        float s[16][4];
#pragma unroll
        for (int nf = 0; nf < 16; nf++) {
            s[nf][0] = s[nf][1] = s[nf][2] = s[nf][3] = 0.0f;
            const int nrow = n0c + nf * 8 + gr;
            unsigned kbh[2], kbl[2];
            kbh[0] = *(const unsigned*)&Kh[nrow * 16 + 2 * qc];
            kbh[1] = *(const unsigned*)&Kh[nrow * 16 + 2 * qc + 8];
            kbl[0] = *(const unsigned*)&Kl[nrow * 16 + 2 * qc];
            kbl[1] = *(const unsigned*)&Kl[nrow * 16 + 2 * qc + 8];
            mma16816(s[nf], qh, kbh);
            mma16816(s[nf], qh, kbl);
            mma16816(s[nf], ql, kbh);
        }

        // ---- + mask, row max ----
        float mx0 = -1e30f, mx1 = -1e30f;
#pragma unroll
        for (int nf = 0; nf < 16; nf++) {
            const int ncol = n0c + nf * 8 + 2 * qc;
            float2 mk0 = *(const float2*)&mask[mrow0 + ncol];
            float2 mk1 = *(const float2*)&mask[mrow1 + ncol];
            s[nf][0] += mk0.x; s[nf][1] += mk0.y;
            s[nf][2] += mk1.x; s[nf][3] += mk1.y;
            mx0 = fmaxf(mx0, fmaxf(s[nf][0], s[nf][1]));
            mx1 = fmaxf(mx1, fmaxf(s[nf][2], s[nf][3]));
        }
        mx0 = fmaxf(mx0, __shfl_xor_sync(0xffffffffu, mx0, 1));
        mx0 = fmaxf(mx0, __shfl_xor_sync(0xffffffffu, mx0, 2));
        mx1 = fmaxf(mx1, __shfl_xor_sync(0xffffffffu, mx1, 1));
        mx1 = fmaxf(mx1, __shfl_xor_sync(0xffffffffu, mx1, 2));

        const float mn0 = fmaxf(m0, mx0);
        const float mn1 = fmaxf(m1, mx1);
        const float f0 = __expf(m0 - mn0);
        const float f1 = __expf(m1 - mn1);
        m0 = mn0; m1 = mn1;
#pragma unroll
        for (int nd = 0; nd < 2; nd++) {
            O[nd][0] *= f0; O[nd][1] *= f0;
            O[nd][2] *= f1; O[nd][3] *= f1;
        }

        float rs0 = 0.0f, rs1 = 0.0f;
#pragma unroll
        for (int nf = 0; nf < 16; nf++) {
            s[nf][0] = __expf(s[nf][0] - mn0);
            s[nf][1] = __expf(s[nf][1] - mn0);
            s[nf][2] = __expf(s[nf][2] - mn1);
            s[nf][3] = __expf(s[nf][3] - mn1);
            rs0 += s[nf][0] + s[nf][1];
            rs1 += s[nf][2] + s[nf][3];
        }
        rs0 += __shfl_xor_sync(0xffffffffu, rs0, 1);
        rs0 += __shfl_xor_sync(0xffffffffu, rs0, 2);
        rs1 += __shfl_xor_sync(0xffffffffu, rs1, 1);
        rs1 += __shfl_xor_sync(0xffffffffu, rs1, 2);
        l0 = l0 * f0 + rs0;
        l1 = l1 * f1 + rs1;

        // ---- O += P V (8 k-steps x 2 d-frags x 3 split mmas) ----
#pragma unroll
        for (int t = 0; t < 8; t++) {
            unsigned ah[4], al[4];
            pack_hl(s[2 * t][0],     s[2 * t][1],     ah[0], al[0]);
            pack_hl(s[2 * t][2],     s[2 * t][3],     ah[1], al[1]);
            pack_hl(s[2 * t + 1][0], s[2 * t + 1][1], ah[2], al[2]);
            pack_hl(s[2 * t + 1][2], s[2 * t + 1][3], ah[3], al[3]);
            const int kcol = n0c + 16 * t + 2 * qc;
#pragma unroll
            for (int nd = 0; nd < 2; nd++) {
                const int d0 = nd * 8 + gr;
                unsigned vbh[2], vbl[2];
                vbh[0] = *(const unsigned*)&Vth[d0 * VT_LD + kcol];
                vbh[1] = *(const unsigned*)&Vth[d0 * VT_LD + kcol + 8];
                vbl[0] = *(const unsigned*)&Vtl[d0 * VT_LD + kcol];
                vbl[1] = *(const unsigned*)&Vtl[d0 * VT_LD + kcol + 8];
                mma16816(O[nd], ah, vbh);
                mma16816(O[nd], ah, vbl);
                mma16816(O[nd], al, vbh);
            }
        }
    }

    // ---- epilogue ----
    const float inv0 = 1.0f / l0;
    const float inv1 = 1.0f / l1;
    float* op0 = g_att + ((size_t)(b * PP + p0 + prow + gr)) * (HH * DD) + h * DD;
    float* op1 = g_att + ((size_t)(b * PP + p0 + prow + gr + 8)) * (HH * DD) + h * DD;
#pragma unroll
    for (int nd = 0; nd < 2; nd++) {
        *(float2*)&op0[nd * 8 + 2 * qc] = make_float2(O[nd][0] * inv0, O[nd][1] * inv0);
        *(float2*)&op1[nd * 8 + 2 * qc] = make_float2(O[nd][2] * inv1, O[nd][3] * inv1);
    }
}

// ---------------------------------------------------------------------------
// Final fused kernel v3 (unchanged): block per (b, 64-row p-tile).
// ---------------------------------------------------------------------------
__global__ __launch_bounds__(256) void final3_kernel(
    const float* __restrict__ enc,
    const float* __restrict__ dist,
    const float* __restrict__ mask,
    float* __restrict__ out)
{
    extern __shared__ char smraw[];
    __nv_bfloat16* Ah = (__nv_bfloat16*)smraw;
    __nv_bfloat16* Al = Ah + 64 * LDAB;
    __nv_bfloat16* Bh = Al + 64 * LDAB;
    __nv_bfloat16* Bl = Bh + 128 * LDAB;
    float* S_s = (float*)(Bl + 128 * LDAB);

    const int b = blockIdx.y;
    const int p0 = blockIdx.x * 64;
    const int tid = threadIdx.x;
    const int warp = tid >> 5, lane = tid & 31;
    const int wm = warp >> 2, wn = warp & 3;
    const int gr = lane >> 2, qc = lane & 3;

    const float* encb = enc + (size_t)b * NN * EMB;

#pragma unroll 1
    for (int nc = 0; nc < 4; nc++) {
        float acc[2][4][4];
#pragma unroll
        for (int mt = 0; mt < 2; mt++)
#pragma unroll
            for (int nt = 0; nt < 4; nt++)
#pragma unroll
                for (int e = 0; e < 4; e++) acc[mt][nt][e] = 0.0f;

#pragma unroll 1
        for (int k0 = 0; k0 < 256; k0 += 32) {
            float4 av[2];
#pragma unroll
            for (int i = 0; i < 2; i++) {
                const int lin = tid + i * 256;
                const int row = lin >> 3, c4 = lin & 7;
                av[i] = *(const float4*)&g_mh[((size_t)(b * PP + p0 + row)) * 256 + k0 + c4 * 4];
            }
            float4 bv[4];
#pragma unroll
            for (int i = 0; i < 4; i++) {
                const int lin = tid + i * 256;
                const int row = lin >> 3, c4 = lin & 7;
                bv[i] = *(const float4*)&encb[(size_t)(nc * 128 + row) * 256 + k0 + c4 * 4];
            }
            __syncthreads();
#pragma unroll
            for (int i = 0; i < 2; i++) {
                const int lin = tid + i * 256;
                const int row = lin >> 3, c4 = lin & 7;
                store_hl4(&Ah[row * LDAB + c4 * 4], &Al[row * LDAB + c4 * 4], av[i]);
            }
#pragma unroll
            for (int i = 0; i < 4; i++) {
                const int lin = tid + i * 256;
                const int row = lin >> 3, c4 = lin & 7;
                store_hl4(&Bh[row * LDAB + c4 * 4], &Bl[row * LDAB + c4 * 4], bv[i]);
            }
            __syncthreads();

#pragma unroll
            for (int ks = 0; ks < 32; ks += 16) {
                unsigned ah[2][4], al[2][4], bh[4][2], bl[4][2];
#pragma unroll
                for (int mt = 0; mt < 2; mt++) {
                    const int base = (wm * 32 + mt * 16 + gr) * LDAB + ks + 2 * qc;
                    ah[mt][0] = *(const unsigned*)&Ah[base];
                    ah[mt][1] = *(const unsigned*)&Ah[base + 8 * LDAB];
                    ah[mt][2] = *(const unsigned*)&Ah[base + 8];
                    ah[mt][3] = *(const unsigned*)&Ah[base + 8 * LDAB + 8];
                    al[mt][0] = *(const unsigned*)&Al[base];
                    al[mt][1] = *(const unsigned*)&Al[base + 8 * LDAB];
                    al[mt][2] = *(const unsigned*)&Al[base + 8];
                    al[mt][3] = *(const unsigned*)&Al[base + 8 * LDAB + 8];
                }
#pragma unroll
                for (int nt = 0; nt < 4; nt++) {
                    const int base = (wn * 32 + nt * 8 + gr) * LDAB + ks + 2 * qc;
                    bh[nt][0] = *(const unsigned*)&Bh[base];
                    bh[nt][1] = *(const unsigned*)&Bh[base + 8];
                    bl[nt][0] = *(const unsigned*)&Bl[base];
                    bl[nt][1] = *(const unsigned*)&Bl[base + 8];
                }
#pragma unroll
                for (int mt = 0; mt < 2; mt++)
#pragma unroll
                    for (int nt = 0; nt < 4; nt++) {
                        mma16816(acc[mt][nt], ah[mt], bh[nt]);
                        mma16816(acc[mt][nt], ah[mt], bl[nt]);
                        mma16816(acc[mt][nt], al[mt], bh[nt]);
                    }
            }
        }

#pragma unroll
        for (int mt = 0; mt < 2; mt++)
#pragma unroll
            for (int part = 0; part < 2; part++) {
                const int r = wm * 32 + mt * 16 + gr + part * 8;
#pragma unroll
                for (int nt = 0; nt < 4; nt++) {
                    const int col = nc * 128 + wn * 32 + nt * 8 + 2 * qc;
                    float2 v = make_float2(acc[mt][nt][part * 2], acc[mt][nt][part * 2 + 1]);
                    *(float2*)&S_s[r * 512 + col] = v;
                }
            }
    }
    __syncthreads();

#pragma unroll 1
    for (int rr = 0; rr < 8; rr++) {
        const int r = warp * 8 + rr;
        const int p = p0 + r;
        const float* drow = dist + ((size_t)(b * PP + p)) * NN;
        const float* mrow = mask + ((size_t)(b * PP + p)) * NN;

        unsigned key[16];
        float dv[16];
#pragma unroll
        for (int j = 0; j < 16; j++) {
            dv[j] = drow[j * 32 + lane];
            unsigned u = __float_as_uint(dv[j]);
            key[j] = (u & 0x80000000u) ? ~u : (u ^ 0x80000000u);
        }

        unsigned lo = 0u, hi = 0xffffffffu;
#pragma unroll 1
        for (int it = 0; it < 32; it++) {
            const unsigned mid = lo + ((hi - lo) >> 1);
            int c = 0;
#pragma unroll
            for (int j = 0; j < 16; j++) c += (key[j] <= mid) ? 1 : 0;
            c = __reduce_add_sync(0xffffffffu, c);
            if (c >= 100) hi = mid; else lo = mid + 1;
        }
        const unsigned tau = hi;

        float cv[16];
        float mx = -1e30f;
#pragma unroll
        for (int j = 0; j < 16; j++) {
            const int n = j * 32 + lane;
            float sc = S_s[r * 512 + n] * 0.0625f;
            sc += (key[j] <= tau) ? (-dv[j] * 0.7071067811865475f) : 1.0f;
            const float cc = 10.0f * tanhf(sc) + mrow[n];
            cv[j] = cc;
            mx = fmaxf(mx, cc);
        }
#pragma unroll
        for (int o = 16; o; o >>= 1) mx = fmaxf(mx, __shfl_xor_sync(0xffffffffu, mx, o));

        float lsum = 0.0f;
#pragma unroll
        for (int j = 0; j < 16; j++) {
            cv[j] = __expf(cv[j] - mx);
            lsum += cv[j];
        }
#pragma unroll
        for (int o = 16; o; o >>= 1) lsum += __shfl_xor_sync(0xffffffffu, lsum, o);
        const float inv = 1.0f / lsum;

        float* orow = out + ((size_t)(b * PP + p)) * NN;
#pragma unroll
        for (int j = 0; j < 16; j++) orow[j * 32 + lane] = cv[j] * inv;
    }
}

// ---------------------------------------------------------------------------
// Launch
// ---------------------------------------------------------------------------
extern "C" void kernel_launch(void* const* d_in, const int* in_sizes, int n_in,
                              void* d_out, int out_size)
{
    const float* enc   = (const float*)d_in[0];
    const float* last  = (const float*)d_in[1];
    const float* load  = (const float*)d_in[2];
    const float* dist  = (const float*)d_in[3];
    const float* mask  = (const float*)d_in[6];
    const float* Wq    = (const float*)d_in[7];
    const float* Wk    = (const float*)d_in[8];
    const float* Wv    = (const float*)d_in[9];
    const float* Wc    = (const float*)d_in[10];
    const float* Wcb   = (const float*)d_in[11];
    float* out = (float*)d_out;

    const dim3 gg(BB * PP / 128, 4);

    gemm3_kernel<0, false, false, false><<<gg, 256>>>(enc,  Wk, 256, nullptr, nullptr);
    gemm3_kernel<1, false, false, false><<<gg, 256>>>(enc,  Wv, 256, nullptr, nullptr);
    gemm3_kernel<2, true,  false, false><<<gg, 256>>>(last, Wq, 257, load,    nullptr);

    // attention v4: smem = (2*512*16 + 2*16*520 + 2*128*16) bf16 = 74240 B
    const size_t smA = (size_t)(2 * 512 * 16 + 2 * 16 * VT_LD + 2 * 128 * 16)
                       * sizeof(__nv_bfloat16);
    cudaFuncSetAttribute(attention4_kernel,
                         cudaFuncAttributeMaxDynamicSharedMemorySize, (int)smA);
    dim3 gA(BB * HH, PP / 128);  // 512 x 4
    attention4_kernel<<<gA, 256, smA>>>(mask);

    gemm3_kernel<3, false, true, true><<<gg, 256>>>(nullptr, Wc, 256, nullptr, Wcb);

    const size_t smF = (size_t)(64 + 64 + 128 + 128) * LDAB * sizeof(__nv_bfloat16)
                     + (size_t)64 * 512 * sizeof(float);
    cudaFuncSetAttribute(final3_kernel,
                         cudaFuncAttributeMaxDynamicSharedMemorySize, (int)smF);
    dim3 gF(PP / 64, BB);
    final3_kernel<<<gF, 256, smF>>>(enc, dist, mask, out);
}

// round 7
// speedup vs baseline: 2.9342x; 1.2342x over previous
#include <cuda_runtime.h>
#include <cuda_bf16.h>
#include <math.h>

// ---------------------------------------------------------------------------
// Problem constants
// ---------------------------------------------------------------------------
#define BB  32
#define PP  512
#define NN  512
#define EMB 256
#define HH  16
#define DD  16

// Scratch (device globals -- no allocation allowed)
__device__ float g_K[BB * HH * NN * DD];    // [b][h][n][d]
__device__ float g_V[BB * HH * NN * DD];    // [b][h][n][d]
__device__ float g_Q[BB * HH * PP * DD];    // [b][h][p][d]
__device__ float g_att[BB * PP * HH * DD];  // [b][p][h*16+d]
__device__ float g_mh[BB * PP * EMB];       // [b][p][e]

// ---------------------------------------------------------------------------
// mma.sync m16n8k16 bf16 helper
// ---------------------------------------------------------------------------
__device__ __forceinline__ void mma16816(float* c, const unsigned* a, const unsigned* b) {
    asm volatile(
        "mma.sync.aligned.m16n8k16.row.col.f32.bf16.bf16.f32 "
        "{%0,%1,%2,%3}, {%4,%5,%6,%7}, {%8,%9}, {%0,%1,%2,%3};"
        : "+f"(c[0]), "+f"(c[1]), "+f"(c[2]), "+f"(c[3])
        : "r"(a[0]), "r"(a[1]), "r"(a[2]), "r"(a[3]), "r"(b[0]), "r"(b[1]));
}

// pack two fp32 -> bf16x2
__device__ __forceinline__ unsigned pack_bf16x2(float lo, float hi) {
    unsigned r;
    asm("cvt.rn.satfinite.bf16x2.f32 %0, %1, %2;" : "=r"(r) : "f"(hi), "f"(lo));
    return r;
}

// pack hi/lo split pair
__device__ __forceinline__ void pack_hl(float x0, float x1, unsigned& ph, unsigned& pl) {
    ph = pack_bf16x2(x0, x1);
    const float h0 = __uint_as_float(ph << 16);
    const float h1 = __uint_as_float(ph & 0xFFFF0000u);
    pl = pack_bf16x2(x0 - h0, x1 - h1);
}

__device__ __forceinline__ void cvt_hl(float x, __nv_bfloat16& h, __nv_bfloat16& l) {
    h = __float2bfloat16(x);
    l = __float2bfloat16(x - __bfloat162float(h));
}

__device__ __forceinline__ void store_hl4(__nv_bfloat16* p_h, __nv_bfloat16* p_l, float4 v) {
    unsigned h01, l01, h23, l23;
    pack_hl(v.x, v.y, h01, l01);
    pack_hl(v.z, v.w, h23, l23);
    *(unsigned*)(p_h)     = h01;
    *(unsigned*)(p_h + 2) = h23;
    *(unsigned*)(p_l)     = l01;
    *(unsigned*)(p_l + 2) = l23;
}

#define LDAB 40  // padded bf16 row stride for 32-wide k tiles

// ---------------------------------------------------------------------------
// Tensor-core GEMM  out = A @ W^T (+ rank-1 extra) (+ bias), bf16 hi/lo split.
// Block 128x64, BK=32, 256 threads (8 warps as 4m x 2n), warp tile 32x32.
// ---------------------------------------------------------------------------
template <int OUT_SEL, bool EXTRA, bool BIAS, bool SRC_ATT>
__global__ __launch_bounds__(256) void gemm3_kernel(
    const float* __restrict__ A,
    const float* __restrict__ W, int ldw,
    const float* __restrict__ exA,
    const float* __restrict__ bias)
{
    __shared__ __nv_bfloat16 Ah[128 * LDAB], Al[128 * LDAB];
    __shared__ __nv_bfloat16 Bh[64 * LDAB],  Bl[64 * LDAB];

    const float* Ap = SRC_ATT ? (const float*)g_att : A;
    float* out = (OUT_SEL == 0) ? g_K : (OUT_SEL == 1) ? g_V
               : (OUT_SEL == 2) ? g_Q : g_mh;

    const int m0 = blockIdx.x * 128;
    const int n0 = blockIdx.y * 64;
    const int tid = threadIdx.x;
    const int warp = tid >> 5, lane = tid & 31;
    const int wm = warp >> 1, wn = warp & 1;
    const int gr = lane >> 2, qc = lane & 3;

    float acc[2][4][4];
#pragma unroll
    for (int mt = 0; mt < 2; mt++)
#pragma unroll
        for (int nt = 0; nt < 4; nt++)
#pragma unroll
            for (int e = 0; e < 4; e++) acc[mt][nt][e] = 0.0f;

    for (int k0 = 0; k0 < 256; k0 += 32) {
        float4 av[4];
#pragma unroll
        for (int i = 0; i < 4; i++) {
            const int lin = tid + i * 256;
            const int row = lin >> 3, c4 = lin & 7;
            av[i] = *(const float4*)(Ap + (size_t)(m0 + row) * 256 + k0 + c4 * 4);
        }
        float wv[2][4];
#pragma unroll
        for (int i = 0; i < 2; i++) {
            const int lin = tid + i * 256;
            const int row = lin >> 3, c4 = lin & 7;
            const float* wp = W + (size_t)(n0 + row) * ldw + k0 + c4 * 4;
            if (EXTRA) {
                wv[i][0] = wp[0]; wv[i][1] = wp[1]; wv[i][2] = wp[2]; wv[i][3] = wp[3];
            } else {
                float4 t = *(const float4*)wp;
                wv[i][0] = t.x; wv[i][1] = t.y; wv[i][2] = t.z; wv[i][3] = t.w;
            }
        }
        __syncthreads();
#pragma unroll
        for (int i = 0; i < 4; i++) {
            const int lin = tid + i * 256;
            const int row = lin >> 3, c4 = lin & 7;
            store_hl4(&Ah[row * LDAB + c4 * 4], &Al[row * LDAB + c4 * 4], av[i]);
        }
#pragma unroll
        for (int i = 0; i < 2; i++) {
            const int lin = tid + i * 256;
            const int row = lin >> 3, c4 = lin & 7;
            float4 t = make_float4(wv[i][0], wv[i][1], wv[i][2], wv[i][3]);
            store_hl4(&Bh[row * LDAB + c4 * 4], &Bl[row * LDAB + c4 * 4], t);
        }
        __syncthreads();

#pragma unroll
        for (int ks = 0; ks < 32; ks += 16) {
            unsigned ah[2][4], al[2][4], bh[4][2], bl[4][2];
#pragma unroll
            for (int mt = 0; mt < 2; mt++) {
                const int base = (wm * 32 + mt * 16 + gr) * LDAB + ks + 2 * qc;
                ah[mt][0] = *(const unsigned*)&Ah[base];
                ah[mt][1] = *(const unsigned*)&Ah[base + 8 * LDAB];
                ah[mt][2] = *(const unsigned*)&Ah[base + 8];
                ah[mt][3] = *(const unsigned*)&Ah[base + 8 * LDAB + 8];
                al[mt][0] = *(const unsigned*)&Al[base];
                al[mt][1] = *(const unsigned*)&Al[base + 8 * LDAB];
                al[mt][2] = *(const unsigned*)&Al[base + 8];
                al[mt][3] = *(const unsigned*)&Al[base + 8 * LDAB + 8];
            }
#pragma unroll
            for (int nt = 0; nt < 4; nt++) {
                const int base = (wn * 32 + nt * 8 + gr) * LDAB + ks + 2 * qc;
                bh[nt][0] = *(const unsigned*)&Bh[base];
                bh[nt][1] = *(const unsigned*)&Bh[base + 8];
                bl[nt][0] = *(const unsigned*)&Bl[base];
                bl[nt][1] = *(const unsigned*)&Bl[base + 8];
            }
#pragma unroll
            for (int mt = 0; mt < 2; mt++)
#pragma unroll
                for (int nt = 0; nt < 4; nt++) {
                    mma16816(acc[mt][nt], ah[mt], bh[nt]);
                    mma16816(acc[mt][nt], ah[mt], bl[nt]);
                    mma16816(acc[mt][nt], al[mt], bh[nt]);
                }
        }
    }

#pragma unroll
    for (int mt = 0; mt < 2; mt++) {
#pragma unroll
        for (int part = 0; part < 2; part++) {
            const int m = m0 + wm * 32 + mt * 16 + gr + part * 8;
            float ex = 0.0f;
            if (EXTRA) ex = exA[m];
#pragma unroll
            for (int nt = 0; nt < 4; nt++) {
                const int col = n0 + wn * 32 + nt * 8 + 2 * qc;
                float2 v = make_float2(acc[mt][nt][part * 2], acc[mt][nt][part * 2 + 1]);
                if (EXTRA) {
                    v.x += ex * W[(size_t)col * ldw + 256];
                    v.y += ex * W[(size_t)(col + 1) * ldw + 256];
                }
                if (BIAS) { v.x += bias[col]; v.y += bias[col + 1]; }
                if (OUT_SEL < 3) {
                    const int b = m >> 9, n = m & 511;
                    const int h = col >> 4, d = col & 15;
                    *(float2*)&out[(((size_t)(b * 16 + h) * 512) + n) * 16 + d] = v;
                } else {
                    *(float2*)&out[(size_t)m * 256 + col] = v;
                }
            }
        }
    }
}

// ---------------------------------------------------------------------------
// Flash attention v5 (tensor cores, occupancy 2): 64-col n-chunks.
// Block per (b,h,128-p tile), 8 warps; warp owns 16 p-rows across all n.
// ---------------------------------------------------------------------------
#define VT_LD 520

__global__ __launch_bounds__(256, 2) void attention5_kernel(
    const float* __restrict__ mask)
{
    extern __shared__ __nv_bfloat16 smb[];
    __nv_bfloat16* Kh  = smb;                 // [512][16]
    __nv_bfloat16* Kl  = Kh + 512 * 16;
    __nv_bfloat16* Vth = Kl + 512 * 16;       // [16][VT_LD]
    __nv_bfloat16* Vtl = Vth + 16 * VT_LD;
    __nv_bfloat16* Qh  = Vtl + 16 * VT_LD;    // [128][16]
    __nv_bfloat16* Ql  = Qh + 128 * 16;

    const int bh = blockIdx.x;
    const int b  = bh >> 4;
    const int h  = bh & 15;
    const int p0 = blockIdx.y * 128;
    const int tid = threadIdx.x;

    // ---- stage K (hi/lo) ----
    const float4* Kg4 = (const float4*)(g_K + (size_t)bh * (NN * DD));
    for (int i = tid; i < 2048; i += 256) {
        float4 v = Kg4[i];
        const int row = i >> 2, dg = (i & 3) * 4;
        store_hl4(&Kh[row * 16 + dg], &Kl[row * 16 + dg], v);
    }
    // ---- stage V transposed (hi/lo) ----
    const float4* Vg4 = (const float4*)(g_V + (size_t)bh * (NN * DD));
    for (int i = tid; i < 2048; i += 256) {
        float4 v = Vg4[i];
        const int n = i >> 2, dg = (i & 3) * 4;
        float x[4] = {v.x, v.y, v.z, v.w};
#pragma unroll
        for (int j = 0; j < 4; j++) {
            __nv_bfloat16 hh, ll;
            cvt_hl(x[j], hh, ll);
            Vth[(dg + j) * VT_LD + n] = hh;
            Vtl[(dg + j) * VT_LD + n] = ll;
        }
    }
    // ---- stage Q (scaled by 0.25, hi/lo) ----
    const float4* Qg4 = (const float4*)(g_Q + ((size_t)bh * PP + p0) * DD);
    for (int i = tid; i < 512; i += 256) {
        float4 v = Qg4[i];
        v.x *= 0.25f; v.y *= 0.25f; v.z *= 0.25f; v.w *= 0.25f;
        const int row = i >> 2, dg = (i & 3) * 4;
        store_hl4(&Qh[row * 16 + dg], &Ql[row * 16 + dg], v);
    }
    __syncthreads();

    const int warp = tid >> 5, lane = tid & 31;
    const int gr = lane >> 2, qc = lane & 3;
    const int prow = warp * 16;

    unsigned qh[4], ql[4];
    {
        const int base = (prow + gr) * 16 + 2 * qc;
        qh[0] = *(const unsigned*)&Qh[base];
        qh[1] = *(const unsigned*)&Qh[base + 8 * 16];
        qh[2] = *(const unsigned*)&Qh[base + 8];
        qh[3] = *(const unsigned*)&Qh[base + 8 * 16 + 8];
        ql[0] = *(const unsigned*)&Ql[base];
        ql[1] = *(const unsigned*)&Ql[base + 8 * 16];
        ql[2] = *(const unsigned*)&Ql[base + 8];
        ql[3] = *(const unsigned*)&Ql[base + 8 * 16 + 8];
    }

    float m0 = -1e30f, m1 = -1e30f, l0 = 0.0f, l1 = 0.0f;
    float O[2][4];
#pragma unroll
    for (int nd = 0; nd < 2; nd++)
#pragma unroll
        for (int e = 0; e < 4; e++) O[nd][e] = 0.0f;

    const size_t mrow0 = ((size_t)(b * PP + p0 + prow + gr)) * NN;
    const size_t mrow1 = ((size_t)(b * PP + p0 + prow + gr + 8)) * NN;

#pragma unroll 1
    for (int c = 0; c < 8; c++) {
        const int n0c = c * 64;

        // ---- S = Q K^T (8 n-frags x 3 split mmas) ----
        float s[8][4];
#pragma unroll
        for (int nf = 0; nf < 8; nf++) {
            s[nf][0] = s[nf][1] = s[nf][2] = s[nf][3] = 0.0f;
            const int nrow = n0c + nf * 8 + gr;
            unsigned kbh[2], kbl[2];
            kbh[0] = *(const unsigned*)&Kh[nrow * 16 + 2 * qc];
            kbh[1] = *(const unsigned*)&Kh[nrow * 16 + 2 * qc + 8];
            kbl[0] = *(const unsigned*)&Kl[nrow * 16 + 2 * qc];
            kbl[1] = *(const unsigned*)&Kl[nrow * 16 + 2 * qc + 8];
            mma16816(s[nf], qh, kbh);
            mma16816(s[nf], qh, kbl);
            mma16816(s[nf], ql, kbh);
        }

        // ---- + mask, row max ----
        float mx0 = -1e30f, mx1 = -1e30f;
#pragma unroll
        for (int nf = 0; nf < 8; nf++) {
            const int ncol = n0c + nf * 8 + 2 * qc;
            float2 mk0 = *(const float2*)&mask[mrow0 + ncol];
            float2 mk1 = *(const float2*)&mask[mrow1 + ncol];
            s[nf][0] += mk0.x; s[nf][1] += mk0.y;
            s[nf][2] += mk1.x; s[nf][3] += mk1.y;
            mx0 = fmaxf(mx0, fmaxf(s[nf][0], s[nf][1]));
            mx1 = fmaxf(mx1, fmaxf(s[nf][2], s[nf][3]));
        }
        mx0 = fmaxf(mx0, __shfl_xor_sync(0xffffffffu, mx0, 1));
        mx0 = fmaxf(mx0, __shfl_xor_sync(0xffffffffu, mx0, 2));
        mx1 = fmaxf(mx1, __shfl_xor_sync(0xffffffffu, mx1, 1));
        mx1 = fmaxf(mx1, __shfl_xor_sync(0xffffffffu, mx1, 2));

        const float mn0 = fmaxf(m0, mx0);
        const float mn1 = fmaxf(m1, mx1);
        const float f0 = __expf(m0 - mn0);
        const float f1 = __expf(m1 - mn1);
        m0 = mn0; m1 = mn1;
#pragma unroll
        for (int nd = 0; nd < 2; nd++) {
            O[nd][0] *= f0; O[nd][1] *= f0;
            O[nd][2] *= f1; O[nd][3] *= f1;
        }

        float rs0 = 0.0f, rs1 = 0.0f;
#pragma unroll
        for (int nf = 0; nf < 8; nf++) {
            s[nf][0] = __expf(s[nf][0] - mn0);
            s[nf][1] = __expf(s[nf][1] - mn0);
            s[nf][2] = __expf(s[nf][2] - mn1);
            s[nf][3] = __expf(s[nf][3] - mn1);
            rs0 += s[nf][0] + s[nf][1];
            rs1 += s[nf][2] + s[nf][3];
        }
        rs0 += __shfl_xor_sync(0xffffffffu, rs0, 1);
        rs0 += __shfl_xor_sync(0xffffffffu, rs0, 2);
        rs1 += __shfl_xor_sync(0xffffffffu, rs1, 1);
        rs1 += __shfl_xor_sync(0xffffffffu, rs1, 2);
        l0 = l0 * f0 + rs0;
        l1 = l1 * f1 + rs1;

        // ---- O += P V (4 k-steps x 2 d-frags x 3 split mmas) ----
#pragma unroll
        for (int t = 0; t < 4; t++) {
            unsigned ah[4], al[4];
            pack_hl(s[2 * t][0],     s[2 * t][1],     ah[0], al[0]);
            pack_hl(s[2 * t][2],     s[2 * t][3],     ah[1], al[1]);
            pack_hl(s[2 * t + 1][0], s[2 * t + 1][1], ah[2], al[2]);
            pack_hl(s[2 * t + 1][2], s[2 * t + 1][3], ah[3], al[3]);
            const int kcol = n0c + 16 * t + 2 * qc;
#pragma unroll
            for (int nd = 0; nd < 2; nd++) {
                const int d0 = nd * 8 + gr;
                unsigned vbh[2], vbl[2];
                vbh[0] = *(const unsigned*)&Vth[d0 * VT_LD + kcol];
                vbh[1] = *(const unsigned*)&Vth[d0 * VT_LD + kcol + 8];
                vbl[0] = *(const unsigned*)&Vtl[d0 * VT_LD + kcol];
                vbl[1] = *(const unsigned*)&Vtl[d0 * VT_LD + kcol + 8];
                mma16816(O[nd], ah, vbh);
                mma16816(O[nd], ah, vbl);
                mma16816(O[nd], al, vbh);
            }
        }
    }

    // ---- epilogue ----
    const float inv0 = 1.0f / l0;
    const float inv1 = 1.0f / l1;
    float* op0 = g_att + ((size_t)(b * PP + p0 + prow + gr)) * (HH * DD) + h * DD;
    float* op1 = g_att + ((size_t)(b * PP + p0 + prow + gr + 8)) * (HH * DD) + h * DD;
#pragma unroll
    for (int nd = 0; nd < 2; nd++) {
        *(float2*)&op0[nd * 8 + 2 * qc] = make_float2(O[nd][0] * inv0, O[nd][1] * inv0);
        *(float2*)&op1[nd * 8 + 2 * qc] = make_float2(O[nd][2] * inv1, O[nd][3] * inv1);
    }
}

// ---------------------------------------------------------------------------
// Final fused kernel v4: block per (b, 32-row p-tile). 256 threads, 2 CTA/SM.
// Phase 1: S = mh @ enc^T via bf16-split mma; 8 warps = 2m x 4n.
// Phase 2: per-row topk-threshold + tanh-clip + softmax (warp per row).
// ---------------------------------------------------------------------------
__global__ __launch_bounds__(256, 2) void final4_kernel(
    const float* __restrict__ enc,
    const float* __restrict__ dist,
    const float* __restrict__ mask,
    float* __restrict__ out)
{
    extern __shared__ char smraw[];
    __nv_bfloat16* Ah = (__nv_bfloat16*)smraw;       // [32][LDAB]
    __nv_bfloat16* Al = Ah + 32 * LDAB;
    __nv_bfloat16* Bh = Al + 32 * LDAB;              // [128][LDAB]
    __nv_bfloat16* Bl = Bh + 128 * LDAB;
    float* S_s = (float*)(Bl + 128 * LDAB);          // [32][512]

    const int b = blockIdx.y;
    const int p0 = blockIdx.x * 32;
    const int tid = threadIdx.x;
    const int warp = tid >> 5, lane = tid & 31;
    const int wm = warp >> 2, wn = warp & 3;
    const int gr = lane >> 2, qc = lane & 3;

    const float* encb = enc + (size_t)b * NN * EMB;

#pragma unroll 1
    for (int nc = 0; nc < 4; nc++) {
        float acc[4][4];
#pragma unroll
        for (int nt = 0; nt < 4; nt++)
#pragma unroll
            for (int e = 0; e < 4; e++) acc[nt][e] = 0.0f;

#pragma unroll 1
        for (int k0 = 0; k0 < 256; k0 += 32) {
            // A: 32 rows x 8 float4-cols = 256 threads, one each
            const int arow = tid >> 3, ac4 = tid & 7;
            float4 av = *(const float4*)&g_mh[((size_t)(b * PP + p0 + arow)) * 256 + k0 + ac4 * 4];
            float4 bv[4];
#pragma unroll
            for (int i = 0; i < 4; i++) {
                const int lin = tid + i * 256;
                const int row = lin >> 3, c4 = lin & 7;
                bv[i] = *(const float4*)&encb[(size_t)(nc * 128 + row) * 256 + k0 + c4 * 4];
            }
            __syncthreads();
            store_hl4(&Ah[arow * LDAB + ac4 * 4], &Al[arow * LDAB + ac4 * 4], av);
#pragma unroll
            for (int i = 0; i < 4; i++) {
                const int lin = tid + i * 256;
                const int row = lin >> 3, c4 = lin & 7;
                store_hl4(&Bh[row * LDAB + c4 * 4], &Bl[row * LDAB + c4 * 4], bv[i]);
            }
            __syncthreads();

#pragma unroll
            for (int ks = 0; ks < 32; ks += 16) {
                unsigned ah[4], al[4], bh[4][2], bl[4][2];
                {
                    const int base = (wm * 16 + gr) * LDAB + ks + 2 * qc;
                    ah[0] = *(const unsigned*)&Ah[base];
                    ah[1] = *(const unsigned*)&Ah[base + 8 * LDAB];
                    ah[2] = *(const unsigned*)&Ah[base + 8];
                    ah[3] = *(const unsigned*)&Ah[base + 8 * LDAB + 8];
                    al[0] = *(const unsigned*)&Al[base];
                    al[1] = *(const unsigned*)&Al[base + 8 * LDAB];
                    al[2] = *(const unsigned*)&Al[base + 8];
                    al[3] = *(const unsigned*)&Al[base + 8 * LDAB + 8];
                }
#pragma unroll
                for (int nt = 0; nt < 4; nt++) {
                    const int base = (wn * 32 + nt * 8 + gr) * LDAB + ks + 2 * qc;
                    bh[nt][0] = *(const unsigned*)&Bh[base];
                    bh[nt][1] = *(const unsigned*)&Bh[base + 8];
                    bl[nt][0] = *(const unsigned*)&Bl[base];
                    bl[nt][1] = *(const unsigned*)&Bl[base + 8];
                }
#pragma unroll
                for (int nt = 0; nt < 4; nt++) {
                    mma16816(acc[nt], ah, bh[nt]);
                    mma16816(acc[nt], ah, bl[nt]);
                    mma16816(acc[nt], al, bh[nt]);
                }
            }
        }

#pragma unroll
        for (int part = 0; part < 2; part++) {
            const int r = wm * 16 + gr + part * 8;
#pragma unroll
            for (int nt = 0; nt < 4; nt++) {
                const int col = nc * 128 + wn * 32 + nt * 8 + 2 * qc;
                float2 v = make_float2(acc[nt][part * 2], acc[nt][part * 2 + 1]);
                *(float2*)&S_s[r * 512 + col] = v;
            }
        }
    }
    __syncthreads();

    // ------- phase 2: warp per row (8 warps x 4 rows = 32 rows) -------
#pragma unroll 1
    for (int rr = 0; rr < 4; rr++) {
        const int r = warp * 4 + rr;
        const int p = p0 + r;
        const float* drow = dist + ((size_t)(b * PP + p)) * NN;
        const float* mrow = mask + ((size_t)(b * PP + p)) * NN;

        unsigned key[16];
        float dv[16];
#pragma unroll
        for (int j = 0; j < 16; j++) {
            dv[j] = drow[j * 32 + lane];
            unsigned u = __float_as_uint(dv[j]);
            key[j] = (u & 0x80000000u) ? ~u : (u ^ 0x80000000u);
        }

        unsigned lo = 0u, hi = 0xffffffffu;
#pragma unroll 1
        for (int it = 0; it < 32; it++) {
            const unsigned mid = lo + ((hi - lo) >> 1);
            int c = 0;
#pragma unroll
            for (int j = 0; j < 16; j++) c += (key[j] <= mid) ? 1 : 0;
            c = __reduce_add_sync(0xffffffffu, c);
            if (c >= 100) hi = mid; else lo = mid + 1;
        }
        const unsigned tau = hi;

        float cv[16];
        float mx = -1e30f;
#pragma unroll
        for (int j = 0; j < 16; j++) {
            const int n = j * 32 + lane;
            float sc = S_s[r * 512 + n] * 0.0625f;
            sc += (key[j] <= tau) ? (-dv[j] * 0.7071067811865475f) : 1.0f;
            const float cc = 10.0f * tanhf(sc) + mrow[n];
            cv[j] = cc;
            mx = fmaxf(mx, cc);
        }
#pragma unroll
        for (int o = 16; o; o >>= 1) mx = fmaxf(mx, __shfl_xor_sync(0xffffffffu, mx, o));

        float lsum = 0.0f;
#pragma unroll
        for (int j = 0; j < 16; j++) {
            cv[j] = __expf(cv[j] - mx);
            lsum += cv[j];
        }
#pragma unroll
        for (int o = 16; o; o >>= 1) lsum += __shfl_xor_sync(0xffffffffu, lsum, o);
        const float inv = 1.0f / lsum;

        float* orow = out + ((size_t)(b * PP + p)) * NN;
#pragma unroll
        for (int j = 0; j < 16; j++) orow[j * 32 + lane] = cv[j] * inv;
    }
}

// ---------------------------------------------------------------------------
// Launch
// ---------------------------------------------------------------------------
extern "C" void kernel_launch(void* const* d_in, const int* in_sizes, int n_in,
                              void* d_out, int out_size)
{
    const float* enc   = (const float*)d_in[0];
    const float* last  = (const float*)d_in[1];
    const float* load  = (const float*)d_in[2];
    const float* dist  = (const float*)d_in[3];
    const float* mask  = (const float*)d_in[6];
    const float* Wq    = (const float*)d_in[7];
    const float* Wk    = (const float*)d_in[8];
    const float* Wv    = (const float*)d_in[9];
    const float* Wc    = (const float*)d_in[10];
    const float* Wcb   = (const float*)d_in[11];
    float* out = (float*)d_out;

    const dim3 gg(BB * PP / 128, 4);

    gemm3_kernel<0, false, false, false><<<gg, 256>>>(enc,  Wk, 256, nullptr, nullptr);
    gemm3_kernel<1, false, false, false><<<gg, 256>>>(enc,  Wv, 256, nullptr, nullptr);
    gemm3_kernel<2, true,  false, false><<<gg, 256>>>(last, Wq, 257, load,    nullptr);

    // attention v5: smem = (2*512*16 + 2*16*520 + 2*128*16) bf16 = 74240 B
    const size_t smA = (size_t)(2 * 512 * 16 + 2 * 16 * VT_LD + 2 * 128 * 16)
                       * sizeof(__nv_bfloat16);
    cudaFuncSetAttribute(attention5_kernel,
                         cudaFuncAttributeMaxDynamicSharedMemorySize, (int)smA);
    dim3 gA(BB * HH, PP / 128);  // 512 x 4
    attention5_kernel<<<gA, 256, smA>>>(mask);

    gemm3_kernel<3, false, true, true><<<gg, 256>>>(nullptr, Wc, 256, nullptr, Wcb);

    // final v4: bf16 staging (32+32+128+128)*40*2 = 25600 B + S_s 32*512*4 = 65536 B
    const size_t smF = (size_t)(32 + 32 + 128 + 128) * LDAB * sizeof(__nv_bfloat16)
                     + (size_t)32 * 512 * sizeof(float);  // 91136 B
    cudaFuncSetAttribute(final4_kernel,
                         cudaFuncAttributeMaxDynamicSharedMemorySize, (int)smF);
    dim3 gF(PP / 32, BB);  // 16 x 32
    final4_kernel<<<gF, 256, smF>>>(enc, dist, mask, out);
}

// round 8
// speedup vs baseline: 3.2122x; 1.0947x over previous
#include <cuda_runtime.h>
#include <cuda_bf16.h>
#include <math.h>

// ---------------------------------------------------------------------------
// Problem constants
// ---------------------------------------------------------------------------
#define BB  32
#define PP  512
#define NN  512
#define EMB 256
#define HH  16
#define DD  16

// Scratch (device globals -- no allocation allowed)
__device__ float g_K[BB * HH * NN * DD];    // [b][h][n][d]
__device__ float g_V[BB * HH * NN * DD];    // [b][h][n][d]
__device__ float g_Q[BB * HH * PP * DD];    // [b][h][p][d]
__device__ float g_att[BB * PP * HH * DD];  // [b][p][h*16+d]
__device__ float g_mh[BB * PP * EMB];       // [b][p][e]

// ---------------------------------------------------------------------------
// mma.sync m16n8k16 bf16 + ldmatrix helpers
// ---------------------------------------------------------------------------
__device__ __forceinline__ void mma16816(float* c, const unsigned* a, const unsigned* b) {
    asm volatile(
        "mma.sync.aligned.m16n8k16.row.col.f32.bf16.bf16.f32 "
        "{%0,%1,%2,%3}, {%4,%5,%6,%7}, {%8,%9}, {%0,%1,%2,%3};"
        : "+f"(c[0]), "+f"(c[1]), "+f"(c[2]), "+f"(c[3])
        : "r"(a[0]), "r"(a[1]), "r"(a[2]), "r"(a[3]), "r"(b[0]), "r"(b[1]));
}

__device__ __forceinline__ void ldsm_x4(unsigned& d0, unsigned& d1,
                                        unsigned& d2, unsigned& d3, unsigned addr) {
    asm volatile("ldmatrix.sync.aligned.m8n8.x4.shared.b16 {%0,%1,%2,%3}, [%4];"
                 : "=r"(d0), "=r"(d1), "=r"(d2), "=r"(d3) : "r"(addr));
}

__device__ __forceinline__ unsigned pack_bf16x2(float lo, float hi) {
    unsigned r;
    asm("cvt.rn.satfinite.bf16x2.f32 %0, %1, %2;" : "=r"(r) : "f"(hi), "f"(lo));
    return r;
}

__device__ __forceinline__ void pack_hl(float x0, float x1, unsigned& ph, unsigned& pl) {
    ph = pack_bf16x2(x0, x1);
    const float h0 = __uint_as_float(ph << 16);
    const float h1 = __uint_as_float(ph & 0xFFFF0000u);
    pl = pack_bf16x2(x0 - h0, x1 - h1);
}

__device__ __forceinline__ void cvt_hl(float x, __nv_bfloat16& h, __nv_bfloat16& l) {
    h = __float2bfloat16(x);
    l = __float2bfloat16(x - __bfloat162float(h));
}

__device__ __forceinline__ void store_hl4(__nv_bfloat16* p_h, __nv_bfloat16* p_l, float4 v) {
    unsigned h01, l01, h23, l23;
    pack_hl(v.x, v.y, h01, l01);
    pack_hl(v.z, v.w, h23, l23);
    *(unsigned*)(p_h)     = h01;
    *(unsigned*)(p_h + 2) = h23;
    *(unsigned*)(p_l)     = l01;
    *(unsigned*)(p_l + 2) = l23;
}

#define LDAB 40  // padded bf16 row stride (80 B) -> LDSM conflict-free

// ---------------------------------------------------------------------------
// Tensor-core GEMM  out = A @ W^T (+ rank-1 extra) (+ bias), bf16 hi/lo split.
// Block 128x64, BK=32, 256 threads (8 warps as 4m x 2n). LDSM fragment loads.
// ---------------------------------------------------------------------------
template <int OUT_SEL, bool EXTRA, bool BIAS, bool SRC_ATT>
__global__ __launch_bounds__(256) void gemm3_kernel(
    const float* __restrict__ A,
    const float* __restrict__ W, int ldw,
    const float* __restrict__ exA,
    const float* __restrict__ bias)
{
    __shared__ __nv_bfloat16 Ah[128 * LDAB], Al[128 * LDAB];
    __shared__ __nv_bfloat16 Bh[64 * LDAB],  Bl[64 * LDAB];

    const float* Ap = SRC_ATT ? (const float*)g_att : A;
    float* out = (OUT_SEL == 0) ? g_K : (OUT_SEL == 1) ? g_V
               : (OUT_SEL == 2) ? g_Q : g_mh;

    const int m0 = blockIdx.x * 128;
    const int n0 = blockIdx.y * 64;
    const int tid = threadIdx.x;
    const int warp = tid >> 5, lane = tid & 31;
    const int wm = warp >> 1, wn = warp & 1;
    const int gr = lane >> 2, qc = lane & 3;
    const int lt = lane >> 3, lr = lane & 7;  // LDSM lane groups

    // LDSM lane base addresses (bytes)
    const unsigned aH = (unsigned)__cvta_generic_to_shared(Ah)
        + ((wm * 32 + (lt & 1) * 8 + lr) * LDAB + (lt >> 1) * 8) * 2;
    const unsigned aL = (unsigned)__cvta_generic_to_shared(Al)
        + ((wm * 32 + (lt & 1) * 8 + lr) * LDAB + (lt >> 1) * 8) * 2;
    const unsigned bH = (unsigned)__cvta_generic_to_shared(Bh)
        + ((wn * 32 + (lt >> 1) * 8 + lr) * LDAB + (lt & 1) * 8) * 2;
    const unsigned bL = (unsigned)__cvta_generic_to_shared(Bl)
        + ((wn * 32 + (lt >> 1) * 8 + lr) * LDAB + (lt & 1) * 8) * 2;

    float acc[2][4][4];
#pragma unroll
    for (int mt = 0; mt < 2; mt++)
#pragma unroll
        for (int nt = 0; nt < 4; nt++)
#pragma unroll
            for (int e = 0; e < 4; e++) acc[mt][nt][e] = 0.0f;

    for (int k0 = 0; k0 < 256; k0 += 32) {
        float4 av[4];
#pragma unroll
        for (int i = 0; i < 4; i++) {
            const int lin = tid + i * 256;
            const int row = lin >> 3, c4 = lin & 7;
            av[i] = *(const float4*)(Ap + (size_t)(m0 + row) * 256 + k0 + c4 * 4);
        }
        float wv[2][4];
#pragma unroll
        for (int i = 0; i < 2; i++) {
            const int lin = tid + i * 256;
            const int row = lin >> 3, c4 = lin & 7;
            const float* wp = W + (size_t)(n0 + row) * ldw + k0 + c4 * 4;
            if (EXTRA) {
                wv[i][0] = wp[0]; wv[i][1] = wp[1]; wv[i][2] = wp[2]; wv[i][3] = wp[3];
            } else {
                float4 t = *(const float4*)wp;
                wv[i][0] = t.x; wv[i][1] = t.y; wv[i][2] = t.z; wv[i][3] = t.w;
            }
        }
        __syncthreads();
#pragma unroll
        for (int i = 0; i < 4; i++) {
            const int lin = tid + i * 256;
            const int row = lin >> 3, c4 = lin & 7;
            store_hl4(&Ah[row * LDAB + c4 * 4], &Al[row * LDAB + c4 * 4], av[i]);
        }
#pragma unroll
        for (int i = 0; i < 2; i++) {
            const int lin = tid + i * 256;
            const int row = lin >> 3, c4 = lin & 7;
            float4 t = make_float4(wv[i][0], wv[i][1], wv[i][2], wv[i][3]);
            store_hl4(&Bh[row * LDAB + c4 * 4], &Bl[row * LDAB + c4 * 4], t);
        }
        __syncthreads();

#pragma unroll
        for (int ks = 0; ks < 32; ks += 16) {
            unsigned ah[2][4], al[2][4], bh[4][2], bl[4][2];
#pragma unroll
            for (int mt = 0; mt < 2; mt++) {
                ldsm_x4(ah[mt][0], ah[mt][1], ah[mt][2], ah[mt][3],
                        aH + (mt * 16 * LDAB + ks) * 2);
                ldsm_x4(al[mt][0], al[mt][1], al[mt][2], al[mt][3],
                        aL + (mt * 16 * LDAB + ks) * 2);
            }
#pragma unroll
            for (int p = 0; p < 2; p++) {
                ldsm_x4(bh[2 * p][0], bh[2 * p][1], bh[2 * p + 1][0], bh[2 * p + 1][1],
                        bH + (p * 16 * LDAB + ks) * 2);
                ldsm_x4(bl[2 * p][0], bl[2 * p][1], bl[2 * p + 1][0], bl[2 * p + 1][1],
                        bL + (p * 16 * LDAB + ks) * 2);
            }
#pragma unroll
            for (int mt = 0; mt < 2; mt++)
#pragma unroll
                for (int nt = 0; nt < 4; nt++) {
                    mma16816(acc[mt][nt], ah[mt], bh[nt]);
                    mma16816(acc[mt][nt], ah[mt], bl[nt]);
                    mma16816(acc[mt][nt], al[mt], bh[nt]);
                }
        }
    }

#pragma unroll
    for (int mt = 0; mt < 2; mt++) {
#pragma unroll
        for (int part = 0; part < 2; part++) {
            const int m = m0 + wm * 32 + mt * 16 + gr + part * 8;
            float ex = 0.0f;
            if (EXTRA) ex = exA[m];
#pragma unroll
            for (int nt = 0; nt < 4; nt++) {
                const int col = n0 + wn * 32 + nt * 8 + 2 * qc;
                float2 v = make_float2(acc[mt][nt][part * 2], acc[mt][nt][part * 2 + 1]);
                if (EXTRA) {
                    v.x += ex * W[(size_t)col * ldw + 256];
                    v.y += ex * W[(size_t)(col + 1) * ldw + 256];
                }
                if (BIAS) { v.x += bias[col]; v.y += bias[col + 1]; }
                if (OUT_SEL < 3) {
                    const int b = m >> 9, n = m & 511;
                    const int h = col >> 4, d = col & 15;
                    *(float2*)&out[(((size_t)(b * 16 + h) * 512) + n) * 16 + d] = v;
                } else {
                    *(float2*)&out[(size_t)m * 256 + col] = v;
                }
            }
        }
    }
}

// ---------------------------------------------------------------------------
// Flash attention v6 (tensor cores + LDSM): 64-col n-chunks, occupancy 2.
// K slab stride 24 bf16 (48 B) -> LDSM conflict-free. V stride 520.
// ---------------------------------------------------------------------------
#define KH_LD 24
#define VT_LD 520
// element offsets in the extern smem pool
#define A6_KH   0
#define A6_KL   (512 * KH_LD)            // 12288
#define A6_VTH  (2 * 512 * KH_LD)        // 24576
#define A6_VTL  (A6_VTH + 16 * VT_LD)    // 32896
#define A6_QH   (A6_VTL + 16 * VT_LD)    // 41216
#define A6_QL   (A6_QH + 128 * 16)       // 43264
#define A6_TOT  (A6_QL + 128 * 16)       // 45312 elems = 90624 B

__global__ __launch_bounds__(256, 2) void attention6_kernel(
    const float* __restrict__ mask)
{
    extern __shared__ __nv_bfloat16 smb[];
    __nv_bfloat16* Kh  = smb + A6_KH;
    __nv_bfloat16* Kl  = smb + A6_KL;
    __nv_bfloat16* Vth = smb + A6_VTH;
    __nv_bfloat16* Vtl = smb + A6_VTL;
    __nv_bfloat16* Qh  = smb + A6_QH;
    __nv_bfloat16* Ql  = smb + A6_QL;

    const int bh = blockIdx.x;
    const int b  = bh >> 4;
    const int h  = bh & 15;
    const int p0 = blockIdx.y * 128;
    const int tid = threadIdx.x;

    // ---- stage K (hi/lo, stride KH_LD) ----
    const float4* Kg4 = (const float4*)(g_K + (size_t)bh * (NN * DD));
    for (int i = tid; i < 2048; i += 256) {
        float4 v = Kg4[i];
        const int row = i >> 2, dg = (i & 3) * 4;
        store_hl4(&Kh[row * KH_LD + dg], &Kl[row * KH_LD + dg], v);
    }
    // ---- stage V transposed (hi/lo) ----
    const float4* Vg4 = (const float4*)(g_V + (size_t)bh * (NN * DD));
    for (int i = tid; i < 2048; i += 256) {
        float4 v = Vg4[i];
        const int n = i >> 2, dg = (i & 3) * 4;
        float x[4] = {v.x, v.y, v.z, v.w};
#pragma unroll
        for (int j = 0; j < 4; j++) {
            __nv_bfloat16 hh, ll;
            cvt_hl(x[j], hh, ll);
            Vth[(dg + j) * VT_LD + n] = hh;
            Vtl[(dg + j) * VT_LD + n] = ll;
        }
    }
    // ---- stage Q (scaled by 0.25, hi/lo) ----
    const float4* Qg4 = (const float4*)(g_Q + ((size_t)bh * PP + p0) * DD);
    for (int i = tid; i < 512; i += 256) {
        float4 v = Qg4[i];
        v.x *= 0.25f; v.y *= 0.25f; v.z *= 0.25f; v.w *= 0.25f;
        const int row = i >> 2, dg = (i & 3) * 4;
        store_hl4(&Qh[row * 16 + dg], &Ql[row * 16 + dg], v);
    }
    __syncthreads();

    const int warp = tid >> 5, lane = tid & 31;
    const int gr = lane >> 2, qc = lane & 3;
    const int lt = lane >> 3, lr = lane & 7;
    const int prow = warp * 16;

    // LDSM lane bases (bytes): K -> (Kh|Kl tiles k0/k8); V -> (Vth|Vtl)
    const unsigned sb = (unsigned)__cvta_generic_to_shared(smb);
    const unsigned kBase = sb + ((lt < 2 ? A6_KH : A6_KL)
                                 + lr * KH_LD + (lt & 1) * 8) * 2;
    const unsigned vBase = sb + ((lt < 2 ? A6_VTH : A6_VTL)
                                 + lr * VT_LD + (lt & 1) * 8) * 2;

    // Q A-fragments (persist)
    unsigned qh[4], ql[4];
    {
        const int base = (prow + gr) * 16 + 2 * qc;
        qh[0] = *(const unsigned*)&Qh[base];
        qh[1] = *(const unsigned*)&Qh[base + 8 * 16];
        qh[2] = *(const unsigned*)&Qh[base + 8];
        qh[3] = *(const unsigned*)&Qh[base + 8 * 16 + 8];
        ql[0] = *(const unsigned*)&Ql[base];
        ql[1] = *(const unsigned*)&Ql[base + 8 * 16];
        ql[2] = *(const unsigned*)&Ql[base + 8];
        ql[3] = *(const unsigned*)&Ql[base + 8 * 16 + 8];
    }

    float m0 = -1e30f, m1 = -1e30f, l0 = 0.0f, l1 = 0.0f;
    float O[2][4];
#pragma unroll
    for (int nd = 0; nd < 2; nd++)
#pragma unroll
        for (int e = 0; e < 4; e++) O[nd][e] = 0.0f;

    const size_t mrow0 = ((size_t)(b * PP + p0 + prow + gr)) * NN;
    const size_t mrow1 = ((size_t)(b * PP + p0 + prow + gr + 8)) * NN;

#pragma unroll 1
    for (int c = 0; c < 8; c++) {
        const int n0c = c * 64;

        // ---- S = Q K^T (8 n-frags; 1 LDSM.x4 + 3 split mmas each) ----
        float s[8][4];
#pragma unroll
        for (int nf = 0; nf < 8; nf++) {
            s[nf][0] = s[nf][1] = s[nf][2] = s[nf][3] = 0.0f;
            unsigned kbh[2], kbl[2];
            ldsm_x4(kbh[0], kbh[1], kbl[0], kbl[1],
                    kBase + (n0c + nf * 8) * (KH_LD * 2));
            mma16816(s[nf], qh, kbh);
            mma16816(s[nf], qh, kbl);
            mma16816(s[nf], ql, kbh);
        }

        // ---- + mask, row max ----
        float mx0 = -1e30f, mx1 = -1e30f;
#pragma unroll
        for (int nf = 0; nf < 8; nf++) {
            const int ncol = n0c + nf * 8 + 2 * qc;
            float2 mk0 = *(const float2*)&mask[mrow0 + ncol];
            float2 mk1 = *(const float2*)&mask[mrow1 + ncol];
            s[nf][0] += mk0.x; s[nf][1] += mk0.y;
            s[nf][2] += mk1.x; s[nf][3] += mk1.y;
            mx0 = fmaxf(mx0, fmaxf(s[nf][0], s[nf][1]));
            mx1 = fmaxf(mx1, fmaxf(s[nf][2], s[nf][3]));
        }
        mx0 = fmaxf(mx0, __shfl_xor_sync(0xffffffffu, mx0, 1));
        mx0 = fmaxf(mx0, __shfl_xor_sync(0xffffffffu, mx0, 2));
        mx1 = fmaxf(mx1, __shfl_xor_sync(0xffffffffu, mx1, 1));
        mx1 = fmaxf(mx1, __shfl_xor_sync(0xffffffffu, mx1, 2));

        const float mn0 = fmaxf(m0, mx0);
        const float mn1 = fmaxf(m1, mx1);
        const float f0 = __expf(m0 - mn0);
        const float f1 = __expf(m1 - mn1);
        m0 = mn0; m1 = mn1;
#pragma unroll
        for (int nd = 0; nd < 2; nd++) {
            O[nd][0] *= f0; O[nd][1] *= f0;
            O[nd][2] *= f1; O[nd][3] *= f1;
        }

        float rs0 = 0.0f, rs1 = 0.0f;
#pragma unroll
        for (int nf = 0; nf < 8; nf++) {
            s[nf][0] = __expf(s[nf][0] - mn0);
            s[nf][1] = __expf(s[nf][1] - mn0);
            s[nf][2] = __expf(s[nf][2] - mn1);
            s[nf][3] = __expf(s[nf][3] - mn1);
            rs0 += s[nf][0] + s[nf][1];
            rs1 += s[nf][2] + s[nf][3];
        }
        rs0 += __shfl_xor_sync(0xffffffffu, rs0, 1);
        rs0 += __shfl_xor_sync(0xffffffffu, rs0, 2);
        rs1 += __shfl_xor_sync(0xffffffffu, rs1, 1);
        rs1 += __shfl_xor_sync(0xffffffffu, rs1, 2);
        l0 = l0 * f0 + rs0;
        l1 = l1 * f1 + rs1;

        // ---- O += P V (4 k-steps x 2 d-frags; 1 LDSM.x4 + 3 mmas each) ----
#pragma unroll
        for (int t = 0; t < 4; t++) {
            unsigned ah[4], al[4];
            pack_hl(s[2 * t][0],     s[2 * t][1],     ah[0], al[0]);
            pack_hl(s[2 * t][2],     s[2 * t][3],     ah[1], al[1]);
            pack_hl(s[2 * t + 1][0], s[2 * t + 1][1], ah[2], al[2]);
            pack_hl(s[2 * t + 1][2], s[2 * t + 1][3], ah[3], al[3]);
#pragma unroll
            for (int nd = 0; nd < 2; nd++) {
                unsigned vbh[2], vbl[2];
                ldsm_x4(vbh[0], vbh[1], vbl[0], vbl[1],
                        vBase + (nd * 8 * VT_LD + n0c + 16 * t) * 2);
                mma16816(O[nd], ah, vbh);
                mma16816(O[nd], ah, vbl);
                mma16816(O[nd], al, vbh);
            }
        }
    }

    // ---- epilogue ----
    const float inv0 = 1.0f / l0;
    const float inv1 = 1.0f / l1;
    float* op0 = g_att + ((size_t)(b * PP + p0 + prow + gr)) * (HH * DD) + h * DD;
    float* op1 = g_att + ((size_t)(b * PP + p0 + prow + gr + 8)) * (HH * DD) + h * DD;
#pragma unroll
    for (int nd = 0; nd < 2; nd++) {
        *(float2*)&op0[nd * 8 + 2 * qc] = make_float2(O[nd][0] * inv0, O[nd][1] * inv0);
        *(float2*)&op1[nd * 8 + 2 * qc] = make_float2(O[nd][2] * inv1, O[nd][3] * inv1);
    }
}

// ---------------------------------------------------------------------------
// Final fused kernel v5: block per (b, 32-row p-tile), 2 CTA/SM, LDSM frags.
// ---------------------------------------------------------------------------
__global__ __launch_bounds__(256, 2) void final5_kernel(
    const float* __restrict__ enc,
    const float* __restrict__ dist,
    const float* __restrict__ mask,
    float* __restrict__ out)
{
    extern __shared__ char smraw[];
    __nv_bfloat16* Ah = (__nv_bfloat16*)smraw;       // [32][LDAB]
    __nv_bfloat16* Al = Ah + 32 * LDAB;
    __nv_bfloat16* Bh = Al + 32 * LDAB;              // [128][LDAB]
    __nv_bfloat16* Bl = Bh + 128 * LDAB;
    float* S_s = (float*)(Bl + 128 * LDAB);          // [32][512]

    const int b = blockIdx.y;
    const int p0 = blockIdx.x * 32;
    const int tid = threadIdx.x;
    const int warp = tid >> 5, lane = tid & 31;
    const int wm = warp >> 2, wn = warp & 3;
    const int gr = lane >> 2, qc = lane & 3;
    const int lt = lane >> 3, lr = lane & 7;

    const unsigned aH = (unsigned)__cvta_generic_to_shared(Ah)
        + ((wm * 16 + (lt & 1) * 8 + lr) * LDAB + (lt >> 1) * 8) * 2;
    const unsigned aL = (unsigned)__cvta_generic_to_shared(Al)
        + ((wm * 16 + (lt & 1) * 8 + lr) * LDAB + (lt >> 1) * 8) * 2;
    const unsigned bHb = (unsigned)__cvta_generic_to_shared(Bh)
        + ((wn * 32 + (lt >> 1) * 8 + lr) * LDAB + (lt & 1) * 8) * 2;
    const unsigned bLb = (unsigned)__cvta_generic_to_shared(Bl)
        + ((wn * 32 + (lt >> 1) * 8 + lr) * LDAB + (lt & 1) * 8) * 2;

    const float* encb = enc + (size_t)b * NN * EMB;

#pragma unroll 1
    for (int nc = 0; nc < 4; nc++) {
        float acc[4][4];
#pragma unroll
        for (int nt = 0; nt < 4; nt++)
#pragma unroll
            for (int e = 0; e < 4; e++) acc[nt][e] = 0.0f;

#pragma unroll 1
        for (int k0 = 0; k0 < 256; k0 += 32) {
            const int arow = tid >> 3, ac4 = tid & 7;
            float4 av = *(const float4*)&g_mh[((size_t)(b * PP + p0 + arow)) * 256 + k0 + ac4 * 4];
            float4 bv[4];
#pragma unroll
            for (int i = 0; i < 4; i++) {
                const int lin = tid + i * 256;
                const int row = lin >> 3, c4 = lin & 7;
                bv[i] = *(const float4*)&encb[(size_t)(nc * 128 + row) * 256 + k0 + c4 * 4];
            }
            __syncthreads();
            store_hl4(&Ah[arow * LDAB + ac4 * 4], &Al[arow * LDAB + ac4 * 4], av);
#pragma unroll
            for (int i = 0; i < 4; i++) {
                const int lin = tid + i * 256;
                const int row = lin >> 3, c4 = lin & 7;
                store_hl4(&Bh[row * LDAB + c4 * 4], &Bl[row * LDAB + c4 * 4], bv[i]);
            }
            __syncthreads();

#pragma unroll
            for (int ks = 0; ks < 32; ks += 16) {
                unsigned ah[4], al[4], bh[4][2], bl[4][2];
                ldsm_x4(ah[0], ah[1], ah[2], ah[3], aH + ks * 2);
                ldsm_x4(al[0], al[1], al[2], al[3], aL + ks * 2);
#pragma unroll
                for (int p = 0; p < 2; p++) {
                    ldsm_x4(bh[2 * p][0], bh[2 * p][1], bh[2 * p + 1][0], bh[2 * p + 1][1],
                            bHb + (p * 16 * LDAB + ks) * 2);
                    ldsm_x4(bl[2 * p][0], bl[2 * p][1], bl[2 * p + 1][0], bl[2 * p + 1][1],
                            bLb + (p * 16 * LDAB + ks) * 2);
                }
#pragma unroll
                for (int nt = 0; nt < 4; nt++) {
                    mma16816(acc[nt], ah, bh[nt]);
                    mma16816(acc[nt], ah, bl[nt]);
                    mma16816(acc[nt], al, bh[nt]);
                }
            }
        }

#pragma unroll
        for (int part = 0; part < 2; part++) {
            const int r = wm * 16 + gr + part * 8;
#pragma unroll
            for (int nt = 0; nt < 4; nt++) {
                const int col = nc * 128 + wn * 32 + nt * 8 + 2 * qc;
                float2 v = make_float2(acc[nt][part * 2], acc[nt][part * 2 + 1]);
                *(float2*)&S_s[r * 512 + col] = v;
            }
        }
    }
    __syncthreads();

    // ------- phase 2: warp per row (8 warps x 4 rows = 32 rows) -------
#pragma unroll 1
    for (int rr = 0; rr < 4; rr++) {
        const int r = warp * 4 + rr;
        const int p = p0 + r;
        const float* drow = dist + ((size_t)(b * PP + p)) * NN;
        const float* mrow = mask + ((size_t)(b * PP + p)) * NN;

        unsigned key[16];
        float dv[16];
#pragma unroll
        for (int j = 0; j < 16; j++) {
            dv[j] = drow[j * 32 + lane];
            unsigned u = __float_as_uint(dv[j]);
            key[j] = (u & 0x80000000u) ? ~u : (u ^ 0x80000000u);
        }

        unsigned lo = 0u, hi = 0xffffffffu;
#pragma unroll 1
        for (int it = 0; it < 32; it++) {
            const unsigned mid = lo + ((hi - lo) >> 1);
            int c = 0;
#pragma unroll
            for (int j = 0; j < 16; j++) c += (key[j] <= mid) ? 1 : 0;
            c = __reduce_add_sync(0xffffffffu, c);
            if (c >= 100) hi = mid; else lo = mid + 1;
        }
        const unsigned tau = hi;

        float cv[16];
        float mx = -1e30f;
#pragma unroll
        for (int j = 0; j < 16; j++) {
            const int n = j * 32 + lane;
            float sc = S_s[r * 512 + n] * 0.0625f;
            sc += (key[j] <= tau) ? (-dv[j] * 0.7071067811865475f) : 1.0f;
            const float cc = 10.0f * tanhf(sc) + mrow[n];
            cv[j] = cc;
            mx = fmaxf(mx, cc);
        }
#pragma unroll
        for (int o = 16; o; o >>= 1) mx = fmaxf(mx, __shfl_xor_sync(0xffffffffu, mx, o));

        float lsum = 0.0f;
#pragma unroll
        for (int j = 0; j < 16; j++) {
            cv[j] = __expf(cv[j] - mx);
            lsum += cv[j];
        }
#pragma unroll
        for (int o = 16; o; o >>= 1) lsum += __shfl_xor_sync(0xffffffffu, lsum, o);
        const float inv = 1.0f / lsum;

        float* orow = out + ((size_t)(b * PP + p)) * NN;
#pragma unroll
        for (int j = 0; j < 16; j++) orow[j * 32 + lane] = cv[j] * inv;
    }
}

// ---------------------------------------------------------------------------
// Launch
// ---------------------------------------------------------------------------
extern "C" void kernel_launch(void* const* d_in, const int* in_sizes, int n_in,
                              void* d_out, int out_size)
{
    const float* enc   = (const float*)d_in[0];
    const float* last  = (const float*)d_in[1];
    const float* load  = (const float*)d_in[2];
    const float* dist  = (const float*)d_in[3];
    const float* mask  = (const float*)d_in[6];
    const float* Wq    = (const float*)d_in[7];
    const float* Wk    = (const float*)d_in[8];
    const float* Wv    = (const float*)d_in[9];
    const float* Wc    = (const float*)d_in[10];
    const float* Wcb   = (const float*)d_in[11];
    float* out = (float*)d_out;

    const dim3 gg(BB * PP / 128, 4);

    gemm3_kernel<0, false, false, false><<<gg, 256>>>(enc,  Wk, 256, nullptr, nullptr);
    gemm3_kernel<1, false, false, false><<<gg, 256>>>(enc,  Wv, 256, nullptr, nullptr);
    gemm3_kernel<2, true,  false, false><<<gg, 256>>>(last, Wq, 257, load,    nullptr);

    // attention v6: smem = A6_TOT bf16 = 90624 B
    const size_t smA = (size_t)A6_TOT * sizeof(__nv_bfloat16);
    cudaFuncSetAttribute(attention6_kernel,
                         cudaFuncAttributeMaxDynamicSharedMemorySize, (int)smA);
    dim3 gA(BB * HH, PP / 128);  // 512 x 4
    attention6_kernel<<<gA, 256, smA>>>(mask);

    gemm3_kernel<3, false, true, true><<<gg, 256>>>(nullptr, Wc, 256, nullptr, Wcb);

    // final v5: bf16 staging (32+32+128+128)*40*2 = 25600 B + S_s 32*512*4
    const size_t smF = (size_t)(32 + 32 + 128 + 128) * LDAB * sizeof(__nv_bfloat16)
                     + (size_t)32 * 512 * sizeof(float);  // 91136 B
    cudaFuncSetAttribute(final5_kernel,
                         cudaFuncAttributeMaxDynamicSharedMemorySize, (int)smF);
    dim3 gF(PP / 32, BB);  // 16 x 32
    final5_kernel<<<gF, 256, smF>>>(enc, dist, mask, out);
}

// round 9
// speedup vs baseline: 3.4550x; 1.0756x over previous
#include <cuda_runtime.h>
#include <cuda_bf16.h>
#include <math.h>

// ---------------------------------------------------------------------------
// Problem constants
// ---------------------------------------------------------------------------
#define BB  32
#define PP  512
#define NN  512
#define EMB 256
#define HH  16
#define DD  16

// Scratch (device globals -- no allocation allowed)
__device__ float g_K[BB * HH * NN * DD];    // [b][h][n][d]
__device__ float g_V[BB * HH * NN * DD];    // [b][h][n][d]
__device__ float g_Q[BB * HH * PP * DD];    // [b][h][p][d]
__device__ float g_att[BB * PP * HH * DD];  // [b][p][h*16+d]
__device__ float g_mh[BB * PP * EMB];       // [b][p][e]
__device__ int   g_mask_nz;                 // 1 if any ninf_mask bit set

// ---------------------------------------------------------------------------
// mma.sync m16n8k16 bf16 + ldmatrix helpers
// ---------------------------------------------------------------------------
__device__ __forceinline__ void mma16816(float* c, const unsigned* a, const unsigned* b) {
    asm volatile(
        "mma.sync.aligned.m16n8k16.row.col.f32.bf16.bf16.f32 "
        "{%0,%1,%2,%3}, {%4,%5,%6,%7}, {%8,%9}, {%0,%1,%2,%3};"
        : "+f"(c[0]), "+f"(c[1]), "+f"(c[2]), "+f"(c[3])
        : "r"(a[0]), "r"(a[1]), "r"(a[2]), "r"(a[3]), "r"(b[0]), "r"(b[1]));
}

__device__ __forceinline__ void ldsm_x4(unsigned& d0, unsigned& d1,
                                        unsigned& d2, unsigned& d3, unsigned addr) {
    asm volatile("ldmatrix.sync.aligned.m8n8.x4.shared.b16 {%0,%1,%2,%3}, [%4];"
                 : "=r"(d0), "=r"(d1), "=r"(d2), "=r"(d3) : "r"(addr));
}

__device__ __forceinline__ unsigned pack_bf16x2(float lo, float hi) {
    unsigned r;
    asm("cvt.rn.satfinite.bf16x2.f32 %0, %1, %2;" : "=r"(r) : "f"(hi), "f"(lo));
    return r;
}

__device__ __forceinline__ void pack_hl(float x0, float x1, unsigned& ph, unsigned& pl) {
    ph = pack_bf16x2(x0, x1);
    const float h0 = __uint_as_float(ph << 16);
    const float h1 = __uint_as_float(ph & 0xFFFF0000u);
    pl = pack_bf16x2(x0 - h0, x1 - h1);
}

__device__ __forceinline__ void cvt_hl(float x, __nv_bfloat16& h, __nv_bfloat16& l) {
    h = __float2bfloat16(x);
    l = __float2bfloat16(x - __bfloat162float(h));
}

__device__ __forceinline__ void store_hl4(__nv_bfloat16* p_h, __nv_bfloat16* p_l, float4 v) {
    unsigned h01, l01, h23, l23;
    pack_hl(v.x, v.y, h01, l01);
    pack_hl(v.z, v.w, h23, l23);
    *(unsigned*)(p_h)     = h01;
    *(unsigned*)(p_h + 2) = h23;
    *(unsigned*)(p_l)     = l01;
    *(unsigned*)(p_l + 2) = l23;
}

#define LDAB 40  // padded bf16 row stride (80 B) -> LDSM conflict-free

// ---------------------------------------------------------------------------
// Flag init
// ---------------------------------------------------------------------------
__global__ void init_flag_kernel() {
    if (threadIdx.x == 0) g_mask_nz = 0;
}

// ---------------------------------------------------------------------------
// Merged projection kernel: blockIdx.z selects K / V / Q.
// z==0 blocks additionally OR-scan the mask (hidden under GEMM compute).
// Block 128x64, BK=32, 256 threads (8 warps as 4m x 2n). LDSM fragment loads.
// ---------------------------------------------------------------------------
__global__ __launch_bounds__(256) void proj_kernel(
    const float* __restrict__ enc,
    const float* __restrict__ last,
    const float* __restrict__ loadv,
    const float* __restrict__ Wk,
    const float* __restrict__ Wv,
    const float* __restrict__ Wq,
    const float* __restrict__ mask)
{
    __shared__ __nv_bfloat16 Ah[128 * LDAB], Al[128 * LDAB];
    __shared__ __nv_bfloat16 Bh[64 * LDAB],  Bl[64 * LDAB];
    __shared__ unsigned sred[8];

    const int z = blockIdx.z;
    const float* Ap = (z == 2) ? last : enc;
    const float* W  = (z == 0) ? Wk : (z == 1) ? Wv : Wq;
    const int ldw   = (z == 2) ? 257 : 256;
    const bool extra = (z == 2);
    float* out = (z == 0) ? g_K : (z == 1) ? g_V : g_Q;

    const int m0 = blockIdx.x * 128;
    const int n0 = blockIdx.y * 64;
    const int tid = threadIdx.x;
    const int warp = tid >> 5, lane = tid & 31;
    const int wm = warp >> 1, wn = warp & 1;
    const int gr = lane >> 2, qc = lane & 3;
    const int lt = lane >> 3, lr = lane & 7;

    // ---- mask OR-scan (z==0 only): 512 blocks x 16384 elems ----
    if (z == 0) {
        unsigned acc = 0;
        const uint4* m4 = (const uint4*)mask + (size_t)blockIdx.y * 128 * 4096
                        + (size_t)blockIdx.x * 4096;
        // blockIdx.x in [0,128), blockIdx.y in [0,4) -> 512 slices of 4096 uint4
        for (int i = tid; i < 4096; i += 256) {
            uint4 v = m4[i];
            acc |= v.x | v.y | v.z | v.w;
        }
#pragma unroll
        for (int o = 16; o; o >>= 1) acc |= __shfl_xor_sync(0xffffffffu, acc, o);
        if (lane == 0) sred[warp] = acc;
        __syncthreads();
        if (tid == 0) {
            unsigned a = 0;
#pragma unroll
            for (int i = 0; i < 8; i++) a |= sred[i];
            if (a) atomicOr(&g_mask_nz, 1);
        }
    }

    const unsigned aH = (unsigned)__cvta_generic_to_shared(Ah)
        + ((wm * 32 + (lt & 1) * 8 + lr) * LDAB + (lt >> 1) * 8) * 2;
    const unsigned aL = (unsigned)__cvta_generic_to_shared(Al)
        + ((wm * 32 + (lt & 1) * 8 + lr) * LDAB + (lt >> 1) * 8) * 2;
    const unsigned bH = (unsigned)__cvta_generic_to_shared(Bh)
        + ((wn * 32 + (lt >> 1) * 8 + lr) * LDAB + (lt & 1) * 8) * 2;
    const unsigned bL = (unsigned)__cvta_generic_to_shared(Bl)
        + ((wn * 32 + (lt >> 1) * 8 + lr) * LDAB + (lt & 1) * 8) * 2;

    float acc[2][4][4];
#pragma unroll
    for (int mt = 0; mt < 2; mt++)
#pragma unroll
        for (int nt = 0; nt < 4; nt++)
#pragma unroll
            for (int e = 0; e < 4; e++) acc[mt][nt][e] = 0.0f;

    for (int k0 = 0; k0 < 256; k0 += 32) {
        float4 av[4];
#pragma unroll
        for (int i = 0; i < 4; i++) {
            const int lin = tid + i * 256;
            const int row = lin >> 3, c4 = lin & 7;
            av[i] = *(const float4*)(Ap + (size_t)(m0 + row) * 256 + k0 + c4 * 4);
        }
        float wv[2][4];
#pragma unroll
        for (int i = 0; i < 2; i++) {
            const int lin = tid + i * 256;
            const int row = lin >> 3, c4 = lin & 7;
            const float* wp = W + (size_t)(n0 + row) * ldw + k0 + c4 * 4;
            if (extra) {
                wv[i][0] = wp[0]; wv[i][1] = wp[1]; wv[i][2] = wp[2]; wv[i][3] = wp[3];
            } else {
                float4 t = *(const float4*)wp;
                wv[i][0] = t.x; wv[i][1] = t.y; wv[i][2] = t.z; wv[i][3] = t.w;
            }
        }
        __syncthreads();
#pragma unroll
        for (int i = 0; i < 4; i++) {
            const int lin = tid + i * 256;
            const int row = lin >> 3, c4 = lin & 7;
            store_hl4(&Ah[row * LDAB + c4 * 4], &Al[row * LDAB + c4 * 4], av[i]);
        }
#pragma unroll
        for (int i = 0; i < 2; i++) {
            const int lin = tid + i * 256;
            const int row = lin >> 3, c4 = lin & 7;
            float4 t = make_float4(wv[i][0], wv[i][1], wv[i][2], wv[i][3]);
            store_hl4(&Bh[row * LDAB + c4 * 4], &Bl[row * LDAB + c4 * 4], t);
        }
        __syncthreads();

#pragma unroll
        for (int ks = 0; ks < 32; ks += 16) {
            unsigned ah[2][4], al[2][4], bh[4][2], bl[4][2];
#pragma unroll
            for (int mt = 0; mt < 2; mt++) {
                ldsm_x4(ah[mt][0], ah[mt][1], ah[mt][2], ah[mt][3],
                        aH + (mt * 16 * LDAB + ks) * 2);
                ldsm_x4(al[mt][0], al[mt][1], al[mt][2], al[mt][3],
                        aL + (mt * 16 * LDAB + ks) * 2);
            }
#pragma unroll
            for (int p = 0; p < 2; p++) {
                ldsm_x4(bh[2 * p][0], bh[2 * p][1], bh[2 * p + 1][0], bh[2 * p + 1][1],
                        bH + (p * 16 * LDAB + ks) * 2);
                ldsm_x4(bl[2 * p][0], bl[2 * p][1], bl[2 * p + 1][0], bl[2 * p + 1][1],
                        bL + (p * 16 * LDAB + ks) * 2);
            }
#pragma unroll
            for (int mt = 0; mt < 2; mt++)
#pragma unroll
                for (int nt = 0; nt < 4; nt++) {
                    mma16816(acc[mt][nt], ah[mt], bh[nt]);
                    mma16816(acc[mt][nt], ah[mt], bl[nt]);
                    mma16816(acc[mt][nt], al[mt], bh[nt]);
                }
        }
    }

#pragma unroll
    for (int mt = 0; mt < 2; mt++) {
#pragma unroll
        for (int part = 0; part < 2; part++) {
            const int m = m0 + wm * 32 + mt * 16 + gr + part * 8;
            float ex = 0.0f;
            if (extra) ex = loadv[m];
#pragma unroll
            for (int nt = 0; nt < 4; nt++) {
                const int col = n0 + wn * 32 + nt * 8 + 2 * qc;
                float2 v = make_float2(acc[mt][nt][part * 2], acc[mt][nt][part * 2 + 1]);
                if (extra) {
                    v.x += ex * W[(size_t)col * ldw + 256];
                    v.y += ex * W[(size_t)(col + 1) * ldw + 256];
                }
                const int b = m >> 9, n = m & 511;
                const int h = col >> 4, d = col & 15;
                *(float2*)&out[(((size_t)(b * 16 + h) * 512) + n) * 16 + d] = v;
            }
        }
    }
}

// ---------------------------------------------------------------------------
// Tensor-core GEMM for Wc projection (g_att @ Wc^T + bias -> g_mh).
// ---------------------------------------------------------------------------
__global__ __launch_bounds__(256) void gemm_wc_kernel(
    const float* __restrict__ W,
    const float* __restrict__ bias)
{
    __shared__ __nv_bfloat16 Ah[128 * LDAB], Al[128 * LDAB];
    __shared__ __nv_bfloat16 Bh[64 * LDAB],  Bl[64 * LDAB];

    const float* Ap = (const float*)g_att;
    float* out = g_mh;

    const int m0 = blockIdx.x * 128;
    const int n0 = blockIdx.y * 64;
    const int tid = threadIdx.x;
    const int warp = tid >> 5, lane = tid & 31;
    const int wm = warp >> 1, wn = warp & 1;
    const int gr = lane >> 2, qc = lane & 3;
    const int lt = lane >> 3, lr = lane & 7;

    const unsigned aH = (unsigned)__cvta_generic_to_shared(Ah)
        + ((wm * 32 + (lt & 1) * 8 + lr) * LDAB + (lt >> 1) * 8) * 2;
    const unsigned aL = (unsigned)__cvta_generic_to_shared(Al)
        + ((wm * 32 + (lt & 1) * 8 + lr) * LDAB + (lt >> 1) * 8) * 2;
    const unsigned bH = (unsigned)__cvta_generic_to_shared(Bh)
        + ((wn * 32 + (lt >> 1) * 8 + lr) * LDAB + (lt & 1) * 8) * 2;
    const unsigned bL = (unsigned)__cvta_generic_to_shared(Bl)
        + ((wn * 32 + (lt >> 1) * 8 + lr) * LDAB + (lt & 1) * 8) * 2;

    float acc[2][4][4];
#pragma unroll
    for (int mt = 0; mt < 2; mt++)
#pragma unroll
        for (int nt = 0; nt < 4; nt++)
#pragma unroll
            for (int e = 0; e < 4; e++) acc[mt][nt][e] = 0.0f;

    for (int k0 = 0; k0 < 256; k0 += 32) {
        float4 av[4];
#pragma unroll
        for (int i = 0; i < 4; i++) {
            const int lin = tid + i * 256;
            const int row = lin >> 3, c4 = lin & 7;
            av[i] = *(const float4*)(Ap + (size_t)(m0 + row) * 256 + k0 + c4 * 4);
        }
        float4 wv[2];
#pragma unroll
        for (int i = 0; i < 2; i++) {
            const int lin = tid + i * 256;
            const int row = lin >> 3, c4 = lin & 7;
            wv[i] = *(const float4*)(W + (size_t)(n0 + row) * 256 + k0 + c4 * 4);
        }
        __syncthreads();
#pragma unroll
        for (int i = 0; i < 4; i++) {
            const int lin = tid + i * 256;
            const int row = lin >> 3, c4 = lin & 7;
            store_hl4(&Ah[row * LDAB + c4 * 4], &Al[row * LDAB + c4 * 4], av[i]);
        }
#pragma unroll
        for (int i = 0; i < 2; i++) {
            const int lin = tid + i * 256;
            const int row = lin >> 3, c4 = lin & 7;
            store_hl4(&Bh[row * LDAB + c4 * 4], &Bl[row * LDAB + c4 * 4], wv[i]);
        }
        __syncthreads();

#pragma unroll
        for (int ks = 0; ks < 32; ks += 16) {
            unsigned ah[2][4], al[2][4], bh[4][2], bl[4][2];
#pragma unroll
            for (int mt = 0; mt < 2; mt++) {
                ldsm_x4(ah[mt][0], ah[mt][1], ah[mt][2], ah[mt][3],
                        aH + (mt * 16 * LDAB + ks) * 2);
                ldsm_x4(al[mt][0], al[mt][1], al[mt][2], al[mt][3],
                        aL + (mt * 16 * LDAB + ks) * 2);
            }
#pragma unroll
            for (int p = 0; p < 2; p++) {
                ldsm_x4(bh[2 * p][0], bh[2 * p][1], bh[2 * p + 1][0], bh[2 * p + 1][1],
                        bH + (p * 16 * LDAB + ks) * 2);
                ldsm_x4(bl[2 * p][0], bl[2 * p][1], bl[2 * p + 1][0], bl[2 * p + 1][1],
                        bL + (p * 16 * LDAB + ks) * 2);
            }
#pragma unroll
            for (int mt = 0; mt < 2; mt++)
#pragma unroll
                for (int nt = 0; nt < 4; nt++) {
                    mma16816(acc[mt][nt], ah[mt], bh[nt]);
                    mma16816(acc[mt][nt], ah[mt], bl[nt]);
                    mma16816(acc[mt][nt], al[mt], bh[nt]);
                }
        }
    }

#pragma unroll
    for (int mt = 0; mt < 2; mt++) {
#pragma unroll
        for (int part = 0; part < 2; part++) {
            const int m = m0 + wm * 32 + mt * 16 + gr + part * 8;
#pragma unroll
            for (int nt = 0; nt < 4; nt++) {
                const int col = n0 + wn * 32 + nt * 8 + 2 * qc;
                float2 v = make_float2(acc[mt][nt][part * 2], acc[mt][nt][part * 2 + 1]);
                v.x += bias[col]; v.y += bias[col + 1];
                *(float2*)&out[(size_t)m * 256 + col] = v;
            }
        }
    }
}

// ---------------------------------------------------------------------------
// Flash attention v7: LDSM + mask-skip flag. 64-col n-chunks, occupancy 2.
// ---------------------------------------------------------------------------
#define KH_LD 24
#define VT_LD 520
#define A6_KH   0
#define A6_KL   (512 * KH_LD)
#define A6_VTH  (2 * 512 * KH_LD)
#define A6_VTL  (A6_VTH + 16 * VT_LD)
#define A6_QH   (A6_VTL + 16 * VT_LD)
#define A6_QL   (A6_QH + 128 * 16)
#define A6_TOT  (A6_QL + 128 * 16)

__global__ __launch_bounds__(256, 2) void attention7_kernel(
    const float* __restrict__ mask)
{
    extern __shared__ __nv_bfloat16 smb[];
    __nv_bfloat16* Kh  = smb + A6_KH;
    __nv_bfloat16* Kl  = smb + A6_KL;
    __nv_bfloat16* Vth = smb + A6_VTH;
    __nv_bfloat16* Vtl = smb + A6_VTL;
    __nv_bfloat16* Qh  = smb + A6_QH;
    __nv_bfloat16* Ql  = smb + A6_QL;

    const int bh = blockIdx.x;
    const int b  = bh >> 4;
    const int h  = bh & 15;
    const int p0 = blockIdx.y * 128;
    const int tid = threadIdx.x;
    const int anymask = g_mask_nz;

    const float4* Kg4 = (const float4*)(g_K + (size_t)bh * (NN * DD));
    for (int i = tid; i < 2048; i += 256) {
        float4 v = Kg4[i];
        const int row = i >> 2, dg = (i & 3) * 4;
        store_hl4(&Kh[row * KH_LD + dg], &Kl[row * KH_LD + dg], v);
    }
    const float4* Vg4 = (const float4*)(g_V + (size_t)bh * (NN * DD));
    for (int i = tid; i < 2048; i += 256) {
        float4 v = Vg4[i];
        const int n = i >> 2, dg = (i & 3) * 4;
        float x[4] = {v.x, v.y, v.z, v.w};
#pragma unroll
        for (int j = 0; j < 4; j++) {
            __nv_bfloat16 hh, ll;
            cvt_hl(x[j], hh, ll);
            Vth[(dg + j) * VT_LD + n] = hh;
            Vtl[(dg + j) * VT_LD + n] = ll;
        }
    }
    const float4* Qg4 = (const float4*)(g_Q + ((size_t)bh * PP + p0) * DD);
    for (int i = tid; i < 512; i += 256) {
        float4 v = Qg4[i];
        v.x *= 0.25f; v.y *= 0.25f; v.z *= 0.25f; v.w *= 0.25f;
        const int row = i >> 2, dg = (i & 3) * 4;
        store_hl4(&Qh[row * 16 + dg], &Ql[row * 16 + dg], v);
    }
    __syncthreads();

    const int warp = tid >> 5, lane = tid & 31;
    const int gr = lane >> 2, qc = lane & 3;
    const int lt = lane >> 3, lr = lane & 7;
    const int prow = warp * 16;

    const unsigned sb = (unsigned)__cvta_generic_to_shared(smb);
    const unsigned kBase = sb + ((lt < 2 ? A6_KH : A6_KL)
                                 + lr * KH_LD + (lt & 1) * 8) * 2;
    const unsigned vBase = sb + ((lt < 2 ? A6_VTH : A6_VTL)
                                 + lr * VT_LD + (lt & 1) * 8) * 2;

    unsigned qh[4], ql[4];
    {
        const int base = (prow + gr) * 16 + 2 * qc;
        qh[0] = *(const unsigned*)&Qh[base];
        qh[1] = *(const unsigned*)&Qh[base + 8 * 16];
        qh[2] = *(const unsigned*)&Qh[base + 8];
        qh[3] = *(const unsigned*)&Qh[base + 8 * 16 + 8];
        ql[0] = *(const unsigned*)&Ql[base];
        ql[1] = *(const unsigned*)&Ql[base + 8 * 16];
        ql[2] = *(const unsigned*)&Ql[base + 8];
        ql[3] = *(const unsigned*)&Ql[base + 8 * 16 + 8];
    }

    float m0 = -1e30f, m1 = -1e30f, l0 = 0.0f, l1 = 0.0f;
    float O[2][4];
#pragma unroll
    for (int nd = 0; nd < 2; nd++)
#pragma unroll
        for (int e = 0; e < 4; e++) O[nd][e] = 0.0f;

    const size_t mrow0 = ((size_t)(b * PP + p0 + prow + gr)) * NN;
    const size_t mrow1 = ((size_t)(b * PP + p0 + prow + gr + 8)) * NN;

#pragma unroll 1
    for (int c = 0; c < 8; c++) {
        const int n0c = c * 64;

        float s[8][4];
#pragma unroll
        for (int nf = 0; nf < 8; nf++) {
            s[nf][0] = s[nf][1] = s[nf][2] = s[nf][3] = 0.0f;
            unsigned kbh[2], kbl[2];
            ldsm_x4(kbh[0], kbh[1], kbl[0], kbl[1],
                    kBase + (n0c + nf * 8) * (KH_LD * 2));
            mma16816(s[nf], qh, kbh);
            mma16816(s[nf], qh, kbl);
            mma16816(s[nf], ql, kbh);
        }

        if (anymask) {
#pragma unroll
            for (int nf = 0; nf < 8; nf++) {
                const int ncol = n0c + nf * 8 + 2 * qc;
                float2 mk0 = *(const float2*)&mask[mrow0 + ncol];
                float2 mk1 = *(const float2*)&mask[mrow1 + ncol];
                s[nf][0] += mk0.x; s[nf][1] += mk0.y;
                s[nf][2] += mk1.x; s[nf][3] += mk1.y;
            }
        }

        float mx0 = -1e30f, mx1 = -1e30f;
#pragma unroll
        for (int nf = 0; nf < 8; nf++) {
            mx0 = fmaxf(mx0, fmaxf(s[nf][0], s[nf][1]));
            mx1 = fmaxf(mx1, fmaxf(s[nf][2], s[nf][3]));
        }
        mx0 = fmaxf(mx0, __shfl_xor_sync(0xffffffffu, mx0, 1));
        mx0 = fmaxf(mx0, __shfl_xor_sync(0xffffffffu, mx0, 2));
        mx1 = fmaxf(mx1, __shfl_xor_sync(0xffffffffu, mx1, 1));
        mx1 = fmaxf(mx1, __shfl_xor_sync(0xffffffffu, mx1, 2));

        const float mn0 = fmaxf(m0, mx0);
        const float mn1 = fmaxf(m1, mx1);
        const float f0 = __expf(m0 - mn0);
        const float f1 = __expf(m1 - mn1);
        m0 = mn0; m1 = mn1;
#pragma unroll
        for (int nd = 0; nd < 2; nd++) {
            O[nd][0] *= f0; O[nd][1] *= f0;
            O[nd][2] *= f1; O[nd][3] *= f1;
        }

        float rs0 = 0.0f, rs1 = 0.0f;
#pragma unroll
        for (int nf = 0; nf < 8; nf++) {
            s[nf][0] = __expf(s[nf][0] - mn0);
            s[nf][1] = __expf(s[nf][1] - mn0);
            s[nf][2] = __expf(s[nf][2] - mn1);
            s[nf][3] = __expf(s[nf][3] - mn1);
            rs0 += s[nf][0] + s[nf][1];
            rs1 += s[nf][2] + s[nf][3];
        }
        rs0 += __shfl_xor_sync(0xffffffffu, rs0, 1);
        rs0 += __shfl_xor_sync(0xffffffffu, rs0, 2);
        rs1 += __shfl_xor_sync(0xffffffffu, rs1, 1);
        rs1 += __shfl_xor_sync(0xffffffffu, rs1, 2);
        l0 = l0 * f0 + rs0;
        l1 = l1 * f1 + rs1;

#pragma unroll
        for (int t = 0; t < 4; t++) {
            unsigned ah[4], al[4];
            pack_hl(s[2 * t][0],     s[2 * t][1],     ah[0], al[0]);
            pack_hl(s[2 * t][2],     s[2 * t][3],     ah[1], al[1]);
            pack_hl(s[2 * t + 1][0], s[2 * t + 1][1], ah[2], al[2]);
            pack_hl(s[2 * t + 1][2], s[2 * t + 1][3], ah[3], al[3]);
#pragma unroll
            for (int nd = 0; nd < 2; nd++) {
                unsigned vbh[2], vbl[2];
                ldsm_x4(vbh[0], vbh[1], vbl[0], vbl[1],
                        vBase + (nd * 8 * VT_LD + n0c + 16 * t) * 2);
                mma16816(O[nd], ah, vbh);
                mma16816(O[nd], ah, vbl);
                mma16816(O[nd], al, vbh);
            }
        }
    }

    const float inv0 = 1.0f / l0;
    const float inv1 = 1.0f / l1;
    float* op0 = g_att + ((size_t)(b * PP + p0 + prow + gr)) * (HH * DD) + h * DD;
    float* op1 = g_att + ((size_t)(b * PP + p0 + prow + gr + 8)) * (HH * DD) + h * DD;
#pragma unroll
    for (int nd = 0; nd < 2; nd++) {
        *(float2*)&op0[nd * 8 + 2 * qc] = make_float2(O[nd][0] * inv0, O[nd][1] * inv0);
        *(float2*)&op1[nd * 8 + 2 * qc] = make_float2(O[nd][2] * inv1, O[nd][3] * inv1);
    }
}

// ---------------------------------------------------------------------------
// Final fused kernel v6: mask-skip + fast tanh. Block per (b, 32-row p-tile).
// ---------------------------------------------------------------------------
__global__ __launch_bounds__(256, 2) void final6_kernel(
    const float* __restrict__ enc,
    const float* __restrict__ dist,
    const float* __restrict__ mask,
    float* __restrict__ out)
{
    extern __shared__ char smraw[];
    __nv_bfloat16* Ah = (__nv_bfloat16*)smraw;       // [32][LDAB]
    __nv_bfloat16* Al = Ah + 32 * LDAB;
    __nv_bfloat16* Bh = Al + 32 * LDAB;              // [128][LDAB]
    __nv_bfloat16* Bl = Bh + 128 * LDAB;
    float* S_s = (float*)(Bl + 128 * LDAB);          // [32][512]

    const int b = blockIdx.y;
    const int p0 = blockIdx.x * 32;
    const int tid = threadIdx.x;
    const int warp = tid >> 5, lane = tid & 31;
    const int wm = warp >> 2, wn = warp & 3;
    const int gr = lane >> 2, qc = lane & 3;
    const int lt = lane >> 3, lr = lane & 7;
    const int anymask = g_mask_nz;

    const unsigned aH = (unsigned)__cvta_generic_to_shared(Ah)
        + ((wm * 16 + (lt & 1) * 8 + lr) * LDAB + (lt >> 1) * 8) * 2;
    const unsigned aL = (unsigned)__cvta_generic_to_shared(Al)
        + ((wm * 16 + (lt & 1) * 8 + lr) * LDAB + (lt >> 1) * 8) * 2;
    const unsigned bHb = (unsigned)__cvta_generic_to_shared(Bh)
        + ((wn * 32 + (lt >> 1) * 8 + lr) * LDAB + (lt & 1) * 8) * 2;
    const unsigned bLb = (unsigned)__cvta_generic_to_shared(Bl)
        + ((wn * 32 + (lt >> 1) * 8 + lr) * LDAB + (lt & 1) * 8) * 2;

    const float* encb = enc + (size_t)b * NN * EMB;

#pragma unroll 1
    for (int nc = 0; nc < 4; nc++) {
        float acc[4][4];
#pragma unroll
        for (int nt = 0; nt < 4; nt++)
#pragma unroll
            for (int e = 0; e < 4; e++) acc[nt][e] = 0.0f;

#pragma unroll 1
        for (int k0 = 0; k0 < 256; k0 += 32) {
            const int arow = tid >> 3, ac4 = tid & 7;
            float4 av = *(const float4*)&g_mh[((size_t)(b * PP + p0 + arow)) * 256 + k0 + ac4 * 4];
            float4 bv[4];
#pragma unroll
            for (int i = 0; i < 4; i++) {
                const int lin = tid + i * 256;
                const int row = lin >> 3, c4 = lin & 7;
                bv[i] = *(const float4*)&encb[(size_t)(nc * 128 + row) * 256 + k0 + c4 * 4];
            }
            __syncthreads();
            store_hl4(&Ah[arow * LDAB + ac4 * 4], &Al[arow * LDAB + ac4 * 4], av);
#pragma unroll
            for (int i = 0; i < 4; i++) {
                const int lin = tid + i * 256;
                const int row = lin >> 3, c4 = lin & 7;
                store_hl4(&Bh[row * LDAB + c4 * 4], &Bl[row * LDAB + c4 * 4], bv[i]);
            }
            __syncthreads();

#pragma unroll
            for (int ks = 0; ks < 32; ks += 16) {
                unsigned ah[4], al[4], bh[4][2], bl[4][2];
                ldsm_x4(ah[0], ah[1], ah[2], ah[3], aH + ks * 2);
                ldsm_x4(al[0], al[1], al[2], al[3], aL + ks * 2);
#pragma unroll
                for (int p = 0; p < 2; p++) {
                    ldsm_x4(bh[2 * p][0], bh[2 * p][1], bh[2 * p + 1][0], bh[2 * p + 1][1],
                            bHb + (p * 16 * LDAB + ks) * 2);
                    ldsm_x4(bl[2 * p][0], bl[2 * p][1], bl[2 * p + 1][0], bl[2 * p + 1][1],
                            bLb + (p * 16 * LDAB + ks) * 2);
                }
#pragma unroll
                for (int nt = 0; nt < 4; nt++) {
                    mma16816(acc[nt], ah, bh[nt]);
                    mma16816(acc[nt], ah, bl[nt]);
                    mma16816(acc[nt], al, bh[nt]);
                }
            }
        }

#pragma unroll
        for (int part = 0; part < 2; part++) {
            const int r = wm * 16 + gr + part * 8;
#pragma unroll
            for (int nt = 0; nt < 4; nt++) {
                const int col = nc * 128 + wn * 32 + nt * 8 + 2 * qc;
                float2 v = make_float2(acc[nt][part * 2], acc[nt][part * 2 + 1]);
                *(float2*)&S_s[r * 512 + col] = v;
            }
        }
    }
    __syncthreads();

    // ------- phase 2: warp per row (8 warps x 4 rows = 32 rows) -------
#pragma unroll 1
    for (int rr = 0; rr < 4; rr++) {
        const int r = warp * 4 + rr;
        const int p = p0 + r;
        const float* drow = dist + ((size_t)(b * PP + p)) * NN;
        const float* mrow = mask + ((size_t)(b * PP + p)) * NN;

        unsigned key[16];
        float dv[16];
#pragma unroll
        for (int j = 0; j < 16; j++) {
            dv[j] = drow[j * 32 + lane];
            unsigned u = __float_as_uint(dv[j]);
            key[j] = (u & 0x80000000u) ? ~u : (u ^ 0x80000000u);
        }

        unsigned lo = 0u, hi = 0xffffffffu;
#pragma unroll 1
        for (int it = 0; it < 32; it++) {
            const unsigned mid = lo + ((hi - lo) >> 1);
            int c = 0;
#pragma unroll
            for (int j = 0; j < 16; j++) c += (key[j] <= mid) ? 1 : 0;
            c = __reduce_add_sync(0xffffffffu, c);
            if (c >= 100) hi = mid; else lo = mid + 1;
        }
        const unsigned tau = hi;

        float cv[16];
        float mx = -1e30f;
#pragma unroll
        for (int j = 0; j < 16; j++) {
            const int n = j * 32 + lane;
            float sc = S_s[r * 512 + n] * 0.0625f;
            sc += (key[j] <= tau) ? (-dv[j] * 0.7071067811865475f) : 1.0f;
            // 10*tanh(sc) = 10 - 20/(exp(2 sc)+1)
            const float e = __expf(2.0f * sc);
            float cc = 10.0f - __fdividef(20.0f, e + 1.0f);
            if (anymask) cc += mrow[n];
            cv[j] = cc;
            mx = fmaxf(mx, cc);
        }
#pragma unroll
        for (int o = 16; o; o >>= 1) mx = fmaxf(mx, __shfl_xor_sync(0xffffffffu, mx, o));

        float lsum = 0.0f;
#pragma unroll
        for (int j = 0; j < 16; j++) {
            cv[j] = __expf(cv[j] - mx);
            lsum += cv[j];
        }
#pragma unroll
        for (int o = 16; o; o >>= 1) lsum += __shfl_xor_sync(0xffffffffu, lsum, o);
        const float inv = 1.0f / lsum;

        float* orow = out + ((size_t)(b * PP + p)) * NN;
#pragma unroll
        for (int j = 0; j < 16; j++) orow[j * 32 + lane] = cv[j] * inv;
    }
}

// ---------------------------------------------------------------------------
// Launch
// ---------------------------------------------------------------------------
extern "C" void kernel_launch(void* const* d_in, const int* in_sizes, int n_in,
                              void* d_out, int out_size)
{
    const float* enc   = (const float*)d_in[0];
    const float* last  = (const float*)d_in[1];
    const float* load  = (const float*)d_in[2];
    const float* dist  = (const float*)d_in[3];
    const float* mask  = (const float*)d_in[6];
    const float* Wq    = (const float*)d_in[7];
    const float* Wk    = (const float*)d_in[8];
    const float* Wv    = (const float*)d_in[9];
    const float* Wc    = (const float*)d_in[10];
    const float* Wcb   = (const float*)d_in[11];
    float* out = (float*)d_out;

    init_flag_kernel<<<1, 32>>>();

    // merged K/V/Q projections (+ mask scan in z==0 blocks)
    proj_kernel<<<dim3(BB * PP / 128, 4, 3), 256>>>(enc, last, load, Wk, Wv, Wq, mask);

    const size_t smA = (size_t)A6_TOT * sizeof(__nv_bfloat16);  // 90624 B
    cudaFuncSetAttribute(attention7_kernel,
                         cudaFuncAttributeMaxDynamicSharedMemorySize, (int)smA);
    dim3 gA(BB * HH, PP / 128);  // 512 x 4
    attention7_kernel<<<gA, 256, smA>>>(mask);

    gemm_wc_kernel<<<dim3(BB * PP / 128, 4), 256>>>(Wc, Wcb);

    const size_t smF = (size_t)(32 + 32 + 128 + 128) * LDAB * sizeof(__nv_bfloat16)
                     + (size_t)32 * 512 * sizeof(float);  // 91136 B
    cudaFuncSetAttribute(final6_kernel,
                         cudaFuncAttributeMaxDynamicSharedMemorySize, (int)smF);
    dim3 gF(PP / 32, BB);  // 16 x 32
    final6_kernel<<<gF, 256, smF>>>(enc, dist, mask, out);
}

// round 10
// speedup vs baseline: 3.7097x; 1.0737x over previous
#include <cuda_runtime.h>
#include <cuda_bf16.h>
#include <math.h>

// ---------------------------------------------------------------------------
// Problem constants
// ---------------------------------------------------------------------------
#define BB  32
#define PP  512
#define NN  512
#define EMB 256
#define HH  16
#define DD  16

// Scratch (device globals -- no allocation allowed)
__device__ float g_K[BB * HH * NN * DD];    // [b][h][n][d]
__device__ float g_V[BB * HH * NN * DD];    // [b][h][n][d]
__device__ float g_Q[BB * HH * PP * DD];    // [b][h][p][d]
__device__ float g_att[BB * PP * HH * DD];  // [b][p][h*16+d]
__device__ float g_mh[BB * PP * EMB];       // [b][p][e]
__device__ int   g_mask_nz;                 // 1 if any ninf_mask bit set

// ---------------------------------------------------------------------------
// mma.sync m16n8k16 bf16 + ldmatrix helpers
// ---------------------------------------------------------------------------
__device__ __forceinline__ void mma16816(float* c, const unsigned* a, const unsigned* b) {
    asm volatile(
        "mma.sync.aligned.m16n8k16.row.col.f32.bf16.bf16.f32 "
        "{%0,%1,%2,%3}, {%4,%5,%6,%7}, {%8,%9}, {%0,%1,%2,%3};"
        : "+f"(c[0]), "+f"(c[1]), "+f"(c[2]), "+f"(c[3])
        : "r"(a[0]), "r"(a[1]), "r"(a[2]), "r"(a[3]), "r"(b[0]), "r"(b[1]));
}

__device__ __forceinline__ void ldsm_x4(unsigned& d0, unsigned& d1,
                                        unsigned& d2, unsigned& d3, unsigned addr) {
    asm volatile("ldmatrix.sync.aligned.m8n8.x4.shared.b16 {%0,%1,%2,%3}, [%4];"
                 : "=r"(d0), "=r"(d1), "=r"(d2), "=r"(d3) : "r"(addr));
}

__device__ __forceinline__ unsigned pack_bf16x2(float lo, float hi) {
    unsigned r;
    asm("cvt.rn.satfinite.bf16x2.f32 %0, %1, %2;" : "=r"(r) : "f"(hi), "f"(lo));
    return r;
}

__device__ __forceinline__ void pack_hl(float x0, float x1, unsigned& ph, unsigned& pl) {
    ph = pack_bf16x2(x0, x1);
    const float h0 = __uint_as_float(ph << 16);
    const float h1 = __uint_as_float(ph & 0xFFFF0000u);
    pl = pack_bf16x2(x0 - h0, x1 - h1);
}

__device__ __forceinline__ void cvt_hl(float x, __nv_bfloat16& h, __nv_bfloat16& l) {
    h = __float2bfloat16(x);
    l = __float2bfloat16(x - __bfloat162float(h));
}

__device__ __forceinline__ void store_hl4(__nv_bfloat16* p_h, __nv_bfloat16* p_l, float4 v) {
    unsigned h01, l01, h23, l23;
    pack_hl(v.x, v.y, h01, l01);
    pack_hl(v.z, v.w, h23, l23);
    *(unsigned*)(p_h)     = h01;
    *(unsigned*)(p_h + 2) = h23;
    *(unsigned*)(p_l)     = l01;
    *(unsigned*)(p_l + 2) = l23;
}

#define LDAB 40  // padded bf16 row stride (80 B) -> LDSM conflict-free

// Pipelined GEMM stage layout (elements)
#define P_AH   0
#define P_AL   (128 * LDAB)
#define P_BH   (256 * LDAB)
#define P_BL   (256 * LDAB + 64 * LDAB)
#define P_STAGE (384 * LDAB)   // 15360 elems = 30720 B per stage

// ---------------------------------------------------------------------------
// Flag init
// ---------------------------------------------------------------------------
__global__ void init_flag_kernel() {
    if (threadIdx.x == 0) g_mask_nz = 0;
}

// ---------------------------------------------------------------------------
// Merged projection kernel (pipelined, double-buffered smem).
// blockIdx.z selects K / V / Q; z==0 blocks OR-scan the mask.
// ---------------------------------------------------------------------------
__global__ __launch_bounds__(256, 2) void proj_kernel(
    const float* __restrict__ enc,
    const float* __restrict__ last,
    const float* __restrict__ loadv,
    const float* __restrict__ Wk,
    const float* __restrict__ Wv,
    const float* __restrict__ Wq,
    const float* __restrict__ mask)
{
    extern __shared__ __nv_bfloat16 smp[];
    __shared__ unsigned sred[8];

    const int z = blockIdx.z;
    const float* Ap = (z == 2) ? last : enc;
    const float* W  = (z == 0) ? Wk : (z == 1) ? Wv : Wq;
    const int ldw   = (z == 2) ? 257 : 256;
    const bool extra = (z == 2);
    float* out = (z == 0) ? g_K : (z == 1) ? g_V : g_Q;

    const int m0 = blockIdx.x * 128;
    const int n0 = blockIdx.y * 64;
    const int tid = threadIdx.x;
    const int warp = tid >> 5, lane = tid & 31;
    const int wm = warp >> 1, wn = warp & 1;
    const int gr = lane >> 2, qc = lane & 3;
    const int lt = lane >> 3, lr = lane & 7;
    const int srow = tid >> 3, sc4 = tid & 7;  // stager coords

    // ---- mask OR-scan (z==0 only) ----
    if (z == 0) {
        unsigned accm = 0;
        const uint4* m4 = (const uint4*)mask + (size_t)blockIdx.y * 128 * 4096
                        + (size_t)blockIdx.x * 4096;
        for (int i = tid; i < 4096; i += 256) {
            uint4 v = m4[i];
            accm |= v.x | v.y | v.z | v.w;
        }
#pragma unroll
        for (int o = 16; o; o >>= 1) accm |= __shfl_xor_sync(0xffffffffu, accm, o);
        if (lane == 0) sred[warp] = accm;
        __syncthreads();
        if (tid == 0) {
            unsigned a = 0;
#pragma unroll
            for (int i = 0; i < 8; i++) a |= sred[i];
            if (a) atomicOr(&g_mask_nz, 1);
        }
    }

    // LDSM lane base addresses (stage 0, bytes)
    const unsigned sb = (unsigned)__cvta_generic_to_shared(smp);
    const unsigned aH0 = sb + (P_AH + (wm * 32 + (lt & 1) * 8 + lr) * LDAB + (lt >> 1) * 8) * 2;
    const unsigned aL0 = sb + (P_AL + (wm * 32 + (lt & 1) * 8 + lr) * LDAB + (lt >> 1) * 8) * 2;
    const unsigned bH0 = sb + (P_BH + (wn * 32 + (lt >> 1) * 8 + lr) * LDAB + (lt & 1) * 8) * 2;
    const unsigned bL0 = sb + (P_BL + (wn * 32 + (lt >> 1) * 8 + lr) * LDAB + (lt & 1) * 8) * 2;

    float acc[2][4][4];
#pragma unroll
    for (int mt = 0; mt < 2; mt++)
#pragma unroll
        for (int nt = 0; nt < 4; nt++)
#pragma unroll
            for (int e = 0; e < 4; e++) acc[mt][nt][e] = 0.0f;

    // ---- prologue loads (k=0) ----
    float4 av[4];
    float wv[2][4];
#pragma unroll
    for (int i = 0; i < 4; i++) {
        const int lin = tid + i * 256;
        const int row = lin >> 3, c4 = lin & 7;
        av[i] = *(const float4*)(Ap + (size_t)(m0 + row) * 256 + c4 * 4);
    }
#pragma unroll
    for (int i = 0; i < 2; i++) {
        const int lin = tid + i * 256;
        const int row = lin >> 3, c4 = lin & 7;
        const float* wp = W + (size_t)(n0 + row) * ldw + c4 * 4;
        if (extra) {
            wv[i][0] = wp[0]; wv[i][1] = wp[1]; wv[i][2] = wp[2]; wv[i][3] = wp[3];
        } else {
            float4 t = *(const float4*)wp;
            wv[i][0] = t.x; wv[i][1] = t.y; wv[i][2] = t.z; wv[i][3] = t.w;
        }
    }

#pragma unroll 1
    for (int kb = 0; kb < 8; kb++) {
        const int bufo = (kb & 1) * P_STAGE;
        // ---- store current tile ----
        __nv_bfloat16* Ah = smp + bufo + P_AH;
        __nv_bfloat16* Al = smp + bufo + P_AL;
        __nv_bfloat16* Bh = smp + bufo + P_BH;
        __nv_bfloat16* Bl = smp + bufo + P_BL;
#pragma unroll
        for (int i = 0; i < 4; i++) {
            const int lin = tid + i * 256;
            const int row = lin >> 3, c4 = lin & 7;
            store_hl4(&Ah[row * LDAB + c4 * 4], &Al[row * LDAB + c4 * 4], av[i]);
        }
        {
#pragma unroll
            for (int i = 0; i < 2; i++) {
                const int lin = tid + i * 256;
                const int row = lin >> 3, c4 = lin & 7;
                float4 t = make_float4(wv[i][0], wv[i][1], wv[i][2], wv[i][3]);
                store_hl4(&Bh[row * LDAB + c4 * 4], &Bl[row * LDAB + c4 * 4], t);
            }
        }
        __syncthreads();

        // ---- issue next tile's loads (overlap with compute) ----
        if (kb < 7) {
            const int k0 = (kb + 1) * 32;
#pragma unroll
            for (int i = 0; i < 4; i++) {
                const int lin = tid + i * 256;
                const int row = lin >> 3, c4 = lin & 7;
                av[i] = *(const float4*)(Ap + (size_t)(m0 + row) * 256 + k0 + c4 * 4);
            }
#pragma unroll
            for (int i = 0; i < 2; i++) {
                const int lin = tid + i * 256;
                const int row = lin >> 3, c4 = lin & 7;
                const float* wp = W + (size_t)(n0 + row) * ldw + k0 + c4 * 4;
                if (extra) {
                    wv[i][0] = wp[0]; wv[i][1] = wp[1]; wv[i][2] = wp[2]; wv[i][3] = wp[3];
                } else {
                    float4 t = *(const float4*)wp;
                    wv[i][0] = t.x; wv[i][1] = t.y; wv[i][2] = t.z; wv[i][3] = t.w;
                }
            }
        }

        // ---- compute from buf ----
        const unsigned bo2 = bufo * 2;  // byte offset
#pragma unroll
        for (int ks = 0; ks < 32; ks += 16) {
            unsigned ah[2][4], al[2][4], bh[4][2], bl[4][2];
#pragma unroll
            for (int mt = 0; mt < 2; mt++) {
                ldsm_x4(ah[mt][0], ah[mt][1], ah[mt][2], ah[mt][3],
                        aH0 + bo2 + (mt * 16 * LDAB + ks) * 2);
                ldsm_x4(al[mt][0], al[mt][1], al[mt][2], al[mt][3],
                        aL0 + bo2 + (mt * 16 * LDAB + ks) * 2);
            }
#pragma unroll
            for (int p = 0; p < 2; p++) {
                ldsm_x4(bh[2 * p][0], bh[2 * p][1], bh[2 * p + 1][0], bh[2 * p + 1][1],
                        bH0 + bo2 + (p * 16 * LDAB + ks) * 2);
                ldsm_x4(bl[2 * p][0], bl[2 * p][1], bl[2 * p + 1][0], bl[2 * p + 1][1],
                        bL0 + bo2 + (p * 16 * LDAB + ks) * 2);
            }
#pragma unroll
            for (int mt = 0; mt < 2; mt++)
#pragma unroll
                for (int nt = 0; nt < 4; nt++) {
                    mma16816(acc[mt][nt], ah[mt], bh[nt]);
                    mma16816(acc[mt][nt], ah[mt], bl[nt]);
                    mma16816(acc[mt][nt], al[mt], bh[nt]);
                }
        }
    }

#pragma unroll
    for (int mt = 0; mt < 2; mt++) {
#pragma unroll
        for (int part = 0; part < 2; part++) {
            const int m = m0 + wm * 32 + mt * 16 + gr + part * 8;
            float ex = 0.0f;
            if (extra) ex = loadv[m];
#pragma unroll
            for (int nt = 0; nt < 4; nt++) {
                const int col = n0 + wn * 32 + nt * 8 + 2 * qc;
                float2 v = make_float2(acc[mt][nt][part * 2], acc[mt][nt][part * 2 + 1]);
                if (extra) {
                    v.x += ex * W[(size_t)col * ldw + 256];
                    v.y += ex * W[(size_t)(col + 1) * ldw + 256];
                }
                const int b = m >> 9, n = m & 511;
                const int h = col >> 4, d = col & 15;
                *(float2*)&out[(((size_t)(b * 16 + h) * 512) + n) * 16 + d] = v;
            }
        }
    }
    (void)srow; (void)sc4;
}

// ---------------------------------------------------------------------------
// Wc projection (pipelined, double-buffered): g_att @ Wc^T + bias -> g_mh
// ---------------------------------------------------------------------------
__global__ __launch_bounds__(256, 2) void gemm_wc_kernel(
    const float* __restrict__ W,
    const float* __restrict__ bias)
{
    extern __shared__ __nv_bfloat16 smp[];
    const float* Ap = (const float*)g_att;
    float* out = g_mh;

    const int m0 = blockIdx.x * 128;
    const int n0 = blockIdx.y * 64;
    const int tid = threadIdx.x;
    const int warp = tid >> 5, lane = tid & 31;
    const int wm = warp >> 1, wn = warp & 1;
    const int gr = lane >> 2, qc = lane & 3;
    const int lt = lane >> 3, lr = lane & 7;

    const unsigned sb = (unsigned)__cvta_generic_to_shared(smp);
    const unsigned aH0 = sb + (P_AH + (wm * 32 + (lt & 1) * 8 + lr) * LDAB + (lt >> 1) * 8) * 2;
    const unsigned aL0 = sb + (P_AL + (wm * 32 + (lt & 1) * 8 + lr) * LDAB + (lt >> 1) * 8) * 2;
    const unsigned bH0 = sb + (P_BH + (wn * 32 + (lt >> 1) * 8 + lr) * LDAB + (lt & 1) * 8) * 2;
    const unsigned bL0 = sb + (P_BL + (wn * 32 + (lt >> 1) * 8 + lr) * LDAB + (lt & 1) * 8) * 2;

    float acc[2][4][4];
#pragma unroll
    for (int mt = 0; mt < 2; mt++)
#pragma unroll
        for (int nt = 0; nt < 4; nt++)
#pragma unroll
            for (int e = 0; e < 4; e++) acc[mt][nt][e] = 0.0f;

    float4 av[4], wv[2];
#pragma unroll
    for (int i = 0; i < 4; i++) {
        const int lin = tid + i * 256;
        const int row = lin >> 3, c4 = lin & 7;
        av[i] = *(const float4*)(Ap + (size_t)(m0 + row) * 256 + c4 * 4);
    }
#pragma unroll
    for (int i = 0; i < 2; i++) {
        const int lin = tid + i * 256;
        const int row = lin >> 3, c4 = lin & 7;
        wv[i] = *(const float4*)(W + (size_t)(n0 + row) * 256 + c4 * 4);
    }

#pragma unroll 1
    for (int kb = 0; kb < 8; kb++) {
        const int bufo = (kb & 1) * P_STAGE;
        __nv_bfloat16* Ah = smp + bufo + P_AH;
        __nv_bfloat16* Al = smp + bufo + P_AL;
        __nv_bfloat16* Bh = smp + bufo + P_BH;
        __nv_bfloat16* Bl = smp + bufo + P_BL;
#pragma unroll
        for (int i = 0; i < 4; i++) {
            const int lin = tid + i * 256;
            const int row = lin >> 3, c4 = lin & 7;
            store_hl4(&Ah[row * LDAB + c4 * 4], &Al[row * LDAB + c4 * 4], av[i]);
        }
#pragma unroll
        for (int i = 0; i < 2; i++) {
            const int lin = tid + i * 256;
            const int row = lin >> 3, c4 = lin & 7;
            store_hl4(&Bh[row * LDAB + c4 * 4], &Bl[row * LDAB + c4 * 4], wv[i]);
        }
        __syncthreads();

        if (kb < 7) {
            const int k0 = (kb + 1) * 32;
#pragma unroll
            for (int i = 0; i < 4; i++) {
                const int lin = tid + i * 256;
                const int row = lin >> 3, c4 = lin & 7;
                av[i] = *(const float4*)(Ap + (size_t)(m0 + row) * 256 + k0 + c4 * 4);
            }
#pragma unroll
            for (int i = 0; i < 2; i++) {
                const int lin = tid + i * 256;
                const int row = lin >> 3, c4 = lin & 7;
                wv[i] = *(const float4*)(W + (size_t)(n0 + row) * 256 + k0 + c4 * 4);
            }
        }

        const unsigned bo2 = bufo * 2;
#pragma unroll
        for (int ks = 0; ks < 32; ks += 16) {
            unsigned ah[2][4], al[2][4], bh[4][2], bl[4][2];
#pragma unroll
            for (int mt = 0; mt < 2; mt++) {
                ldsm_x4(ah[mt][0], ah[mt][1], ah[mt][2], ah[mt][3],
                        aH0 + bo2 + (mt * 16 * LDAB + ks) * 2);
                ldsm_x4(al[mt][0], al[mt][1], al[mt][2], al[mt][3],
                        aL0 + bo2 + (mt * 16 * LDAB + ks) * 2);
            }
#pragma unroll
            for (int p = 0; p < 2; p++) {
                ldsm_x4(bh[2 * p][0], bh[2 * p][1], bh[2 * p + 1][0], bh[2 * p + 1][1],
                        bH0 + bo2 + (p * 16 * LDAB + ks) * 2);
                ldsm_x4(bl[2 * p][0], bl[2 * p][1], bl[2 * p + 1][0], bl[2 * p + 1][1],
                        bL0 + bo2 + (p * 16 * LDAB + ks) * 2);
            }
#pragma unroll
            for (int mt = 0; mt < 2; mt++)
#pragma unroll
                for (int nt = 0; nt < 4; nt++) {
                    mma16816(acc[mt][nt], ah[mt], bh[nt]);
                    mma16816(acc[mt][nt], ah[mt], bl[nt]);
                    mma16816(acc[mt][nt], al[mt], bh[nt]);
                }
        }
    }

#pragma unroll
    for (int mt = 0; mt < 2; mt++) {
#pragma unroll
        for (int part = 0; part < 2; part++) {
            const int m = m0 + wm * 32 + mt * 16 + gr + part * 8;
#pragma unroll
            for (int nt = 0; nt < 4; nt++) {
                const int col = n0 + wn * 32 + nt * 8 + 2 * qc;
                float2 v = make_float2(acc[mt][nt][part * 2], acc[mt][nt][part * 2 + 1]);
                v.x += bias[col]; v.y += bias[col + 1];
                *(float2*)&out[(size_t)m * 256 + col] = v;
            }
        }
    }
}

// ---------------------------------------------------------------------------
// Flash attention v8: LDSM + mask-skip + 2 p-tiles per block (staging amortized)
// ---------------------------------------------------------------------------
#define KH_LD 24
#define VT_LD 520
#define A6_KH   0
#define A6_KL   (512 * KH_LD)
#define A6_VTH  (2 * 512 * KH_LD)
#define A6_VTL  (A6_VTH + 16 * VT_LD)
#define A6_QH   (A6_VTL + 16 * VT_LD)
#define A6_QL   (A6_QH + 128 * 16)
#define A6_TOT  (A6_QL + 128 * 16)

__global__ __launch_bounds__(256, 2) void attention8_kernel(
    const float* __restrict__ mask)
{
    extern __shared__ __nv_bfloat16 smb[];
    __nv_bfloat16* Kh  = smb + A6_KH;
    __nv_bfloat16* Kl  = smb + A6_KL;
    __nv_bfloat16* Vth = smb + A6_VTH;
    __nv_bfloat16* Vtl = smb + A6_VTL;
    __nv_bfloat16* Qh  = smb + A6_QH;
    __nv_bfloat16* Ql  = smb + A6_QL;

    const int bh = blockIdx.x;
    const int b  = bh >> 4;
    const int h  = bh & 15;
    const int tid = threadIdx.x;
    const int anymask = g_mask_nz;

    // ---- stage K/V once per block ----
    const float4* Kg4 = (const float4*)(g_K + (size_t)bh * (NN * DD));
    for (int i = tid; i < 2048; i += 256) {
        float4 v = Kg4[i];
        const int row = i >> 2, dg = (i & 3) * 4;
        store_hl4(&Kh[row * KH_LD + dg], &Kl[row * KH_LD + dg], v);
    }
    const float4* Vg4 = (const float4*)(g_V + (size_t)bh * (NN * DD));
    for (int i = tid; i < 2048; i += 256) {
        float4 v = Vg4[i];
        const int n = i >> 2, dg = (i & 3) * 4;
        float x[4] = {v.x, v.y, v.z, v.w};
#pragma unroll
        for (int j = 0; j < 4; j++) {
            __nv_bfloat16 hh, ll;
            cvt_hl(x[j], hh, ll);
            Vth[(dg + j) * VT_LD + n] = hh;
            Vtl[(dg + j) * VT_LD + n] = ll;
        }
    }

    const int warp = tid >> 5, lane = tid & 31;
    const int gr = lane >> 2, qc = lane & 3;
    const int lt = lane >> 3, lr = lane & 7;
    const int prow = warp * 16;

    const unsigned sb = (unsigned)__cvta_generic_to_shared(smb);
    const unsigned kBase = sb + ((lt < 2 ? A6_KH : A6_KL)
                                 + lr * KH_LD + (lt & 1) * 8) * 2;
    const unsigned vBase = sb + ((lt < 2 ? A6_VTH : A6_VTL)
                                 + lr * VT_LD + (lt & 1) * 8) * 2;

#pragma unroll 1
    for (int ip = 0; ip < 2; ip++) {
        const int p0 = blockIdx.y * 256 + ip * 128;

        // ---- stage Q for this p-tile (barrier protects vs in-flight readers) ----
        __syncthreads();
        const float4* Qg4 = (const float4*)(g_Q + ((size_t)bh * PP + p0) * DD);
        for (int i = tid; i < 512; i += 256) {
            float4 v = Qg4[i];
            v.x *= 0.25f; v.y *= 0.25f; v.z *= 0.25f; v.w *= 0.25f;
            const int row = i >> 2, dg = (i & 3) * 4;
            store_hl4(&Qh[row * 16 + dg], &Ql[row * 16 + dg], v);
        }
        __syncthreads();

        unsigned qh[4], ql[4];
        {
            const int base = (prow + gr) * 16 + 2 * qc;
            qh[0] = *(const unsigned*)&Qh[base];
            qh[1] = *(const unsigned*)&Qh[base + 8 * 16];
            qh[2] = *(const unsigned*)&Qh[base + 8];
            qh[3] = *(const unsigned*)&Qh[base + 8 * 16 + 8];
            ql[0] = *(const unsigned*)&Ql[base];
            ql[1] = *(const unsigned*)&Ql[base + 8 * 16];
            ql[2] = *(const unsigned*)&Ql[base + 8];
            ql[3] = *(const unsigned*)&Ql[base + 8 * 16 + 8];
        }

        float m0 = -1e30f, m1 = -1e30f, l0 = 0.0f, l1 = 0.0f;
        float O[2][4];
#pragma unroll
        for (int nd = 0; nd < 2; nd++)
#pragma unroll
            for (int e = 0; e < 4; e++) O[nd][e] = 0.0f;

        const size_t mrow0 = ((size_t)(b * PP + p0 + prow + gr)) * NN;
        const size_t mrow1 = ((size_t)(b * PP + p0 + prow + gr + 8)) * NN;

#pragma unroll 1
        for (int c = 0; c < 8; c++) {
            const int n0c = c * 64;

            float s[8][4];
#pragma unroll
            for (int nf = 0; nf < 8; nf++) {
                s[nf][0] = s[nf][1] = s[nf][2] = s[nf][3] = 0.0f;
                unsigned kbh[2], kbl[2];
                ldsm_x4(kbh[0], kbh[1], kbl[0], kbl[1],
                        kBase + (n0c + nf * 8) * (KH_LD * 2));
                mma16816(s[nf], qh, kbh);
                mma16816(s[nf], qh, kbl);
                mma16816(s[nf], ql, kbh);
            }

            if (anymask) {
#pragma unroll
                for (int nf = 0; nf < 8; nf++) {
                    const int ncol = n0c + nf * 8 + 2 * qc;
                    float2 mk0 = *(const float2*)&mask[mrow0 + ncol];
                    float2 mk1 = *(const float2*)&mask[mrow1 + ncol];
                    s[nf][0] += mk0.x; s[nf][1] += mk0.y;
                    s[nf][2] += mk1.x; s[nf][3] += mk1.y;
                }
            }

            float mx0 = -1e30f, mx1 = -1e30f;
#pragma unroll
            for (int nf = 0; nf < 8; nf++) {
                mx0 = fmaxf(mx0, fmaxf(s[nf][0], s[nf][1]));
                mx1 = fmaxf(mx1, fmaxf(s[nf][2], s[nf][3]));
            }
            mx0 = fmaxf(mx0, __shfl_xor_sync(0xffffffffu, mx0, 1));
            mx0 = fmaxf(mx0, __shfl_xor_sync(0xffffffffu, mx0, 2));
            mx1 = fmaxf(mx1, __shfl_xor_sync(0xffffffffu, mx1, 1));
            mx1 = fmaxf(mx1, __shfl_xor_sync(0xffffffffu, mx1, 2));

            const float mn0 = fmaxf(m0, mx0);
            const float mn1 = fmaxf(m1, mx1);
            const float f0 = __expf(m0 - mn0);
            const float f1 = __expf(m1 - mn1);
            m0 = mn0; m1 = mn1;
#pragma unroll
            for (int nd = 0; nd < 2; nd++) {
                O[nd][0] *= f0; O[nd][1] *= f0;
                O[nd][2] *= f1; O[nd][3] *= f1;
            }

            float rs0 = 0.0f, rs1 = 0.0f;
#pragma unroll
            for (int nf = 0; nf < 8; nf++) {
                s[nf][0] = __expf(s[nf][0] - mn0);
                s[nf][1] = __expf(s[nf][1] - mn0);
                s[nf][2] = __expf(s[nf][2] - mn1);
                s[nf][3] = __expf(s[nf][3] - mn1);
                rs0 += s[nf][0] + s[nf][1];
                rs1 += s[nf][2] + s[nf][3];
            }
            rs0 += __shfl_xor_sync(0xffffffffu, rs0, 1);
            rs0 += __shfl_xor_sync(0xffffffffu, rs0, 2);
            rs1 += __shfl_xor_sync(0xffffffffu, rs1, 1);
            rs1 += __shfl_xor_sync(0xffffffffu, rs1, 2);
            l0 = l0 * f0 + rs0;
            l1 = l1 * f1 + rs1;

#pragma unroll
            for (int t = 0; t < 4; t++) {
                unsigned ah[4], al[4];
                pack_hl(s[2 * t][0],     s[2 * t][1],     ah[0], al[0]);
                pack_hl(s[2 * t][2],     s[2 * t][3],     ah[1], al[1]);
                pack_hl(s[2 * t + 1][0], s[2 * t + 1][1], ah[2], al[2]);
                pack_hl(s[2 * t + 1][2], s[2 * t + 1][3], ah[3], al[3]);
#pragma unroll
                for (int nd = 0; nd < 2; nd++) {
                    unsigned vbh[2], vbl[2];
                    ldsm_x4(vbh[0], vbh[1], vbl[0], vbl[1],
                            vBase + (nd * 8 * VT_LD + n0c + 16 * t) * 2);
                    mma16816(O[nd], ah, vbh);
                    mma16816(O[nd], ah, vbl);
                    mma16816(O[nd], al, vbh);
                }
            }
        }

        const float inv0 = 1.0f / l0;
        const float inv1 = 1.0f / l1;
        float* op0 = g_att + ((size_t)(b * PP + p0 + prow + gr)) * (HH * DD) + h * DD;
        float* op1 = g_att + ((size_t)(b * PP + p0 + prow + gr + 8)) * (HH * DD) + h * DD;
#pragma unroll
        for (int nd = 0; nd < 2; nd++) {
            *(float2*)&op0[nd * 8 + 2 * qc] = make_float2(O[nd][0] * inv0, O[nd][1] * inv0);
            *(float2*)&op1[nd * 8 + 2 * qc] = make_float2(O[nd][2] * inv1, O[nd][3] * inv1);
        }
    }
}

// ---------------------------------------------------------------------------
// Final fused kernel v6 (unchanged): mask-skip + fast tanh.
// ---------------------------------------------------------------------------
__global__ __launch_bounds__(256, 2) void final6_kernel(
    const float* __restrict__ enc,
    const float* __restrict__ dist,
    const float* __restrict__ mask,
    float* __restrict__ out)
{
    extern __shared__ char smraw[];
    __nv_bfloat16* Ah = (__nv_bfloat16*)smraw;       // [32][LDAB]
    __nv_bfloat16* Al = Ah + 32 * LDAB;
    __nv_bfloat16* Bh = Al + 32 * LDAB;              // [128][LDAB]
    __nv_bfloat16* Bl = Bh + 128 * LDAB;
    float* S_s = (float*)(Bl + 128 * LDAB);          // [32][512]

    const int b = blockIdx.y;
    const int p0 = blockIdx.x * 32;
    const int tid = threadIdx.x;
    const int warp = tid >> 5, lane = tid & 31;
    const int wm = warp >> 2, wn = warp & 3;
    const int gr = lane >> 2, qc = lane & 3;
    const int lt = lane >> 3, lr = lane & 7;
    const int anymask = g_mask_nz;

    const unsigned aH = (unsigned)__cvta_generic_to_shared(Ah)
        + ((wm * 16 + (lt & 1) * 8 + lr) * LDAB + (lt >> 1) * 8) * 2;
    const unsigned aL = (unsigned)__cvta_generic_to_shared(Al)
        + ((wm * 16 + (lt & 1) * 8 + lr) * LDAB + (lt >> 1) * 8) * 2;
    const unsigned bHb = (unsigned)__cvta_generic_to_shared(Bh)
        + ((wn * 32 + (lt >> 1) * 8 + lr) * LDAB + (lt & 1) * 8) * 2;
    const unsigned bLb = (unsigned)__cvta_generic_to_shared(Bl)
        + ((wn * 32 + (lt >> 1) * 8 + lr) * LDAB + (lt & 1) * 8) * 2;

    const float* encb = enc + (size_t)b * NN * EMB;

#pragma unroll 1
    for (int nc = 0; nc < 4; nc++) {
        float acc[4][4];
#pragma unroll
        for (int nt = 0; nt < 4; nt++)
#pragma unroll
            for (int e = 0; e < 4; e++) acc[nt][e] = 0.0f;

#pragma unroll 1
        for (int k0 = 0; k0 < 256; k0 += 32) {
            const int arow = tid >> 3, ac4 = tid & 7;
            float4 av = *(const float4*)&g_mh[((size_t)(b * PP + p0 + arow)) * 256 + k0 + ac4 * 4];
            float4 bv[4];
#pragma unroll
            for (int i = 0; i < 4; i++) {
                const int lin = tid + i * 256;
                const int row = lin >> 3, c4 = lin & 7;
                bv[i] = *(const float4*)&encb[(size_t)(nc * 128 + row) * 256 + k0 + c4 * 4];
            }
            __syncthreads();
            store_hl4(&Ah[arow * LDAB + ac4 * 4], &Al[arow * LDAB + ac4 * 4], av);
#pragma unroll
            for (int i = 0; i < 4; i++) {
                const int lin = tid + i * 256;
                const int row = lin >> 3, c4 = lin & 7;
                store_hl4(&Bh[row * LDAB + c4 * 4], &Bl[row * LDAB + c4 * 4], bv[i]);
            }
            __syncthreads();

#pragma unroll
            for (int ks = 0; ks < 32; ks += 16) {
                unsigned ah[4], al[4], bh[4][2], bl[4][2];
                ldsm_x4(ah[0], ah[1], ah[2], ah[3], aH + ks * 2);
                ldsm_x4(al[0], al[1], al[2], al[3], aL + ks * 2);
#pragma unroll
                for (int p = 0; p < 2; p++) {
                    ldsm_x4(bh[2 * p][0], bh[2 * p][1], bh[2 * p + 1][0], bh[2 * p + 1][1],
                            bHb + (p * 16 * LDAB + ks) * 2);
                    ldsm_x4(bl[2 * p][0], bl[2 * p][1], bl[2 * p + 1][0], bl[2 * p + 1][1],
                            bLb + (p * 16 * LDAB + ks) * 2);
                }
#pragma unroll
                for (int nt = 0; nt < 4; nt++) {
                    mma16816(acc[nt], ah, bh[nt]);
                    mma16816(acc[nt], ah, bl[nt]);
                    mma16816(acc[nt], al, bh[nt]);
                }
            }
        }

#pragma unroll
        for (int part = 0; part < 2; part++) {
            const int r = wm * 16 + gr + part * 8;
#pragma unroll
            for (int nt = 0; nt < 4; nt++) {
                const int col = nc * 128 + wn * 32 + nt * 8 + 2 * qc;
                float2 v = make_float2(acc[nt][part * 2], acc[nt][part * 2 + 1]);
                *(float2*)&S_s[r * 512 + col] = v;
            }
        }
    }
    __syncthreads();

#pragma unroll 1
    for (int rr = 0; rr < 4; rr++) {
        const int r = warp * 4 + rr;
        const int p = p0 + r;
        const float* drow = dist + ((size_t)(b * PP + p)) * NN;
        const float* mrow = mask + ((size_t)(b * PP + p)) * NN;

        unsigned key[16];
        float dv[16];
#pragma unroll
        for (int j = 0; j < 16; j++) {
            dv[j] = drow[j * 32 + lane];
            unsigned u = __float_as_uint(dv[j]);
            key[j] = (u & 0x80000000u) ? ~u : (u ^ 0x80000000u);
        }

        unsigned lo = 0u, hi = 0xffffffffu;
#pragma unroll 1
        for (int it = 0; it < 32; it++) {
            const unsigned mid = lo + ((hi - lo) >> 1);
            int c = 0;
#pragma unroll
            for (int j = 0; j < 16; j++) c += (key[j] <= mid) ? 1 : 0;
            c = __reduce_add_sync(0xffffffffu, c);
            if (c >= 100) hi = mid; else lo = mid + 1;
        }
        const unsigned tau = hi;

        float cv[16];
        float mx = -1e30f;
#pragma unroll
        for (int j = 0; j < 16; j++) {
            const int n = j * 32 + lane;
            float sc = S_s[r * 512 + n] * 0.0625f;
            sc += (key[j] <= tau) ? (-dv[j] * 0.7071067811865475f) : 1.0f;
            const float e = __expf(2.0f * sc);
            float cc = 10.0f - __fdividef(20.0f, e + 1.0f);
            if (anymask) cc += mrow[n];
            cv[j] = cc;
            mx = fmaxf(mx, cc);
        }
#pragma unroll
        for (int o = 16; o; o >>= 1) mx = fmaxf(mx, __shfl_xor_sync(0xffffffffu, mx, o));

        float lsum = 0.0f;
#pragma unroll
        for (int j = 0; j < 16; j++) {
            cv[j] = __expf(cv[j] - mx);
            lsum += cv[j];
        }
#pragma unroll
        for (int o = 16; o; o >>= 1) lsum += __shfl_xor_sync(0xffffffffu, lsum, o);
        const float inv = 1.0f / lsum;

        float* orow = out + ((size_t)(b * PP + p)) * NN;
#pragma unroll
        for (int j = 0; j < 16; j++) orow[j * 32 + lane] = cv[j] * inv;
    }
}

// ---------------------------------------------------------------------------
// Launch
// ---------------------------------------------------------------------------
extern "C" void kernel_launch(void* const* d_in, const int* in_sizes, int n_in,
                              void* d_out, int out_size)
{
    const float* enc   = (const float*)d_in[0];
    const float* last  = (const float*)d_in[1];
    const float* load  = (const float*)d_in[2];
    const float* dist  = (const float*)d_in[3];
    const float* mask  = (const float*)d_in[6];
    const float* Wq    = (const float*)d_in[7];
    const float* Wk    = (const float*)d_in[8];
    const float* Wv    = (const float*)d_in[9];
    const float* Wc    = (const float*)d_in[10];
    const float* Wcb   = (const float*)d_in[11];
    float* out = (float*)d_out;

    init_flag_kernel<<<1, 32>>>();

    // merged K/V/Q projections (pipelined, 2-stage smem)
    const size_t smP = (size_t)2 * P_STAGE * sizeof(__nv_bfloat16);  // 61440 B
    cudaFuncSetAttribute(proj_kernel,
                         cudaFuncAttributeMaxDynamicSharedMemorySize, (int)smP);
    proj_kernel<<<dim3(BB * PP / 128, 4, 3), 256, smP>>>(
        enc, last, load, Wk, Wv, Wq, mask);

    const size_t smA = (size_t)A6_TOT * sizeof(__nv_bfloat16);  // 90624 B
    cudaFuncSetAttribute(attention8_kernel,
                         cudaFuncAttributeMaxDynamicSharedMemorySize, (int)smA);
    dim3 gA(BB * HH, 2);  // 512 x 2 (2 p-tiles per block)
    attention8_kernel<<<gA, 256, smA>>>(mask);

    cudaFuncSetAttribute(gemm_wc_kernel,
                         cudaFuncAttributeMaxDynamicSharedMemorySize, (int)smP);
    gemm_wc_kernel<<<dim3(BB * PP / 128, 4), 256, smP>>>(Wc, Wcb);

    const size_t smF = (size_t)(32 + 32 + 128 + 128) * LDAB * sizeof(__nv_bfloat16)
                     + (size_t)32 * 512 * sizeof(float);  // 91136 B
    cudaFuncSetAttribute(final6_kernel,
                         cudaFuncAttributeMaxDynamicSharedMemorySize, (int)smF);
    dim3 gF(PP / 32, BB);  // 16 x 32
    final6_kernel<<<gF, 256, smF>>>(enc, dist, mask, out);
}

// round 11
// speedup vs baseline: 3.7635x; 1.0145x over previous
#include <cuda_runtime.h>
#include <cuda_bf16.h>
#include <math.h>

// ---------------------------------------------------------------------------
// Problem constants
// ---------------------------------------------------------------------------
#define BB  32
#define PP  512
#define NN  512
#define EMB 256
#define HH  16
#define DD  16

// Scratch (device globals -- no allocation allowed)
__device__ float g_K[BB * HH * NN * DD];    // [b][h][n][d]
__device__ float g_V[BB * HH * NN * DD];    // [b][h][n][d]
__device__ float g_Q[BB * HH * PP * DD];    // [b][h][p][d]
__device__ float g_att[BB * PP * HH * DD];  // [b][p][h*16+d]
__device__ float g_mh[BB * PP * EMB];       // [b][p][e]
__device__ int   g_mask_nz;                 // 1 if any ninf_mask bit set

// ---------------------------------------------------------------------------
// mma.sync m16n8k16 bf16 + ldmatrix helpers
// ---------------------------------------------------------------------------
__device__ __forceinline__ void mma16816(float* c, const unsigned* a, const unsigned* b) {
    asm volatile(
        "mma.sync.aligned.m16n8k16.row.col.f32.bf16.bf16.f32 "
        "{%0,%1,%2,%3}, {%4,%5,%6,%7}, {%8,%9}, {%0,%1,%2,%3};"
        : "+f"(c[0]), "+f"(c[1]), "+f"(c[2]), "+f"(c[3])
        : "r"(a[0]), "r"(a[1]), "r"(a[2]), "r"(a[3]), "r"(b[0]), "r"(b[1]));
}

__device__ __forceinline__ void ldsm_x4(unsigned& d0, unsigned& d1,
                                        unsigned& d2, unsigned& d3, unsigned addr) {
    asm volatile("ldmatrix.sync.aligned.m8n8.x4.shared.b16 {%0,%1,%2,%3}, [%4];"
                 : "=r"(d0), "=r"(d1), "=r"(d2), "=r"(d3) : "r"(addr));
}

__device__ __forceinline__ unsigned pack_bf16x2(float lo, float hi) {
    unsigned r;
    asm("cvt.rn.satfinite.bf16x2.f32 %0, %1, %2;" : "=r"(r) : "f"(hi), "f"(lo));
    return r;
}

__device__ __forceinline__ void pack_hl(float x0, float x1, unsigned& ph, unsigned& pl) {
    ph = pack_bf16x2(x0, x1);
    const float h0 = __uint_as_float(ph << 16);
    const float h1 = __uint_as_float(ph & 0xFFFF0000u);
    pl = pack_bf16x2(x0 - h0, x1 - h1);
}

__device__ __forceinline__ void cvt_hl(float x, __nv_bfloat16& h, __nv_bfloat16& l) {
    h = __float2bfloat16(x);
    l = __float2bfloat16(x - __bfloat162float(h));
}

__device__ __forceinline__ void store_hl4(__nv_bfloat16* p_h, __nv_bfloat16* p_l, float4 v) {
    unsigned h01, l01, h23, l23;
    pack_hl(v.x, v.y, h01, l01);
    pack_hl(v.z, v.w, h23, l23);
    *(unsigned*)(p_h)     = h01;
    *(unsigned*)(p_h + 2) = h23;
    *(unsigned*)(p_l)     = l01;
    *(unsigned*)(p_l + 2) = l23;
}

#define LDAB 40  // padded bf16 row stride (80 B) -> LDSM conflict-free

// Pipelined GEMM stage layout (elements)
#define P_AH   0
#define P_AL   (128 * LDAB)
#define P_BH   (256 * LDAB)
#define P_BL   (256 * LDAB + 64 * LDAB)
#define P_STAGE (384 * LDAB)   // 15360 elems = 30720 B per stage

// ---------------------------------------------------------------------------
// Flag init
// ---------------------------------------------------------------------------
__global__ void init_flag_kernel() {
    if (threadIdx.x == 0) g_mask_nz = 0;
}

// ---------------------------------------------------------------------------
// Merged projection kernel (pipelined, double-buffered smem).
// blockIdx.z selects K / V / Q; z==0 blocks OR-scan the mask.
// ---------------------------------------------------------------------------
__global__ __launch_bounds__(256, 2) void proj_kernel(
    const float* __restrict__ enc,
    const float* __restrict__ last,
    const float* __restrict__ loadv,
    const float* __restrict__ Wk,
    const float* __restrict__ Wv,
    const float* __restrict__ Wq,
    const float* __restrict__ mask)
{
    extern __shared__ __nv_bfloat16 smp[];
    __shared__ unsigned sred[8];

    const int z = blockIdx.z;
    const float* Ap = (z == 2) ? last : enc;
    const float* W  = (z == 0) ? Wk : (z == 1) ? Wv : Wq;
    const int ldw   = (z == 2) ? 257 : 256;
    const bool extra = (z == 2);
    float* out = (z == 0) ? g_K : (z == 1) ? g_V : g_Q;

    const int m0 = blockIdx.x * 128;
    const int n0 = blockIdx.y * 64;
    const int tid = threadIdx.x;
    const int warp = tid >> 5, lane = tid & 31;
    const int wm = warp >> 1, wn = warp & 1;
    const int gr = lane >> 2, qc = lane & 3;
    const int lt = lane >> 3, lr = lane & 7;

    if (z == 0) {
        unsigned accm = 0;
        const uint4* m4 = (const uint4*)mask + (size_t)blockIdx.y * 128 * 4096
                        + (size_t)blockIdx.x * 4096;
        for (int i = tid; i < 4096; i += 256) {
            uint4 v = m4[i];
            accm |= v.x | v.y | v.z | v.w;
        }
#pragma unroll
        for (int o = 16; o; o >>= 1) accm |= __shfl_xor_sync(0xffffffffu, accm, o);
        if (lane == 0) sred[warp] = accm;
        __syncthreads();
        if (tid == 0) {
            unsigned a = 0;
#pragma unroll
            for (int i = 0; i < 8; i++) a |= sred[i];
            if (a) atomicOr(&g_mask_nz, 1);
        }
    }

    const unsigned sb = (unsigned)__cvta_generic_to_shared(smp);
    const unsigned aH0 = sb + (P_AH + (wm * 32 + (lt & 1) * 8 + lr) * LDAB + (lt >> 1) * 8) * 2;
    const unsigned aL0 = sb + (P_AL + (wm * 32 + (lt & 1) * 8 + lr) * LDAB + (lt >> 1) * 8) * 2;
    const unsigned bH0 = sb + (P_BH + (wn * 32 + (lt >> 1) * 8 + lr) * LDAB + (lt & 1) * 8) * 2;
    const unsigned bL0 = sb + (P_BL + (wn * 32 + (lt >> 1) * 8 + lr) * LDAB + (lt & 1) * 8) * 2;

    float acc[2][4][4];
#pragma unroll
    for (int mt = 0; mt < 2; mt++)
#pragma unroll
        for (int nt = 0; nt < 4; nt++)
#pragma unroll
            for (int e = 0; e < 4; e++) acc[mt][nt][e] = 0.0f;

    float4 av[4];
    float wv[2][4];
#pragma unroll
    for (int i = 0; i < 4; i++) {
        const int lin = tid + i * 256;
        const int row = lin >> 3, c4 = lin & 7;
        av[i] = *(const float4*)(Ap + (size_t)(m0 + row) * 256 + c4 * 4);
    }
#pragma unroll
    for (int i = 0; i < 2; i++) {
        const int lin = tid + i * 256;
        const int row = lin >> 3, c4 = lin & 7;
        const float* wp = W + (size_t)(n0 + row) * ldw + c4 * 4;
        if (extra) {
            wv[i][0] = wp[0]; wv[i][1] = wp[1]; wv[i][2] = wp[2]; wv[i][3] = wp[3];
        } else {
            float4 t = *(const float4*)wp;
            wv[i][0] = t.x; wv[i][1] = t.y; wv[i][2] = t.z; wv[i][3] = t.w;
        }
    }

#pragma unroll 1
    for (int kb = 0; kb < 8; kb++) {
        const int bufo = (kb & 1) * P_STAGE;
        __nv_bfloat16* Ah = smp + bufo + P_AH;
        __nv_bfloat16* Al = smp + bufo + P_AL;
        __nv_bfloat16* Bh = smp + bufo + P_BH;
        __nv_bfloat16* Bl = smp + bufo + P_BL;
#pragma unroll
        for (int i = 0; i < 4; i++) {
            const int lin = tid + i * 256;
            const int row = lin >> 3, c4 = lin & 7;
            store_hl4(&Ah[row * LDAB + c4 * 4], &Al[row * LDAB + c4 * 4], av[i]);
        }
#pragma unroll
        for (int i = 0; i < 2; i++) {
            const int lin = tid + i * 256;
            const int row = lin >> 3, c4 = lin & 7;
            float4 t = make_float4(wv[i][0], wv[i][1], wv[i][2], wv[i][3]);
            store_hl4(&Bh[row * LDAB + c4 * 4], &Bl[row * LDAB + c4 * 4], t);
        }
        __syncthreads();

        if (kb < 7) {
            const int k0 = (kb + 1) * 32;
#pragma unroll
            for (int i = 0; i < 4; i++) {
                const int lin = tid + i * 256;
                const int row = lin >> 3, c4 = lin & 7;
                av[i] = *(const float4*)(Ap + (size_t)(m0 + row) * 256 + k0 + c4 * 4);
            }
#pragma unroll
            for (int i = 0; i < 2; i++) {
                const int lin = tid + i * 256;
                const int row = lin >> 3, c4 = lin & 7;
                const float* wp = W + (size_t)(n0 + row) * ldw + k0 + c4 * 4;
                if (extra) {
                    wv[i][0] = wp[0]; wv[i][1] = wp[1]; wv[i][2] = wp[2]; wv[i][3] = wp[3];
                } else {
                    float4 t = *(const float4*)wp;
                    wv[i][0] = t.x; wv[i][1] = t.y; wv[i][2] = t.z; wv[i][3] = t.w;
                }
            }
        }

        const unsigned bo2 = bufo * 2;
#pragma unroll
        for (int ks = 0; ks < 32; ks += 16) {
            unsigned ah[2][4], al[2][4], bh[4][2], bl[4][2];
#pragma unroll
            for (int mt = 0; mt < 2; mt++) {
                ldsm_x4(ah[mt][0], ah[mt][1], ah[mt][2], ah[mt][3],
                        aH0 + bo2 + (mt * 16 * LDAB + ks) * 2);
                ldsm_x4(al[mt][0], al[mt][1], al[mt][2], al[mt][3],
                        aL0 + bo2 + (mt * 16 * LDAB + ks) * 2);
            }
#pragma unroll
            for (int p = 0; p < 2; p++) {
                ldsm_x4(bh[2 * p][0], bh[2 * p][1], bh[2 * p + 1][0], bh[2 * p + 1][1],
                        bH0 + bo2 + (p * 16 * LDAB + ks) * 2);
                ldsm_x4(bl[2 * p][0], bl[2 * p][1], bl[2 * p + 1][0], bl[2 * p + 1][1],
                        bL0 + bo2 + (p * 16 * LDAB + ks) * 2);
            }
#pragma unroll
            for (int mt = 0; mt < 2; mt++)
#pragma unroll
                for (int nt = 0; nt < 4; nt++) {
                    mma16816(acc[mt][nt], ah[mt], bh[nt]);
                    mma16816(acc[mt][nt], ah[mt], bl[nt]);
                    mma16816(acc[mt][nt], al[mt], bh[nt]);
                }
        }
    }

#pragma unroll
    for (int mt = 0; mt < 2; mt++) {
#pragma unroll
        for (int part = 0; part < 2; part++) {
            const int m = m0 + wm * 32 + mt * 16 + gr + part * 8;
            float ex = 0.0f;
            if (extra) ex = loadv[m];
#pragma unroll
            for (int nt = 0; nt < 4; nt++) {
                const int col = n0 + wn * 32 + nt * 8 + 2 * qc;
                float2 v = make_float2(acc[mt][nt][part * 2], acc[mt][nt][part * 2 + 1]);
                if (extra) {
                    v.x += ex * W[(size_t)col * ldw + 256];
                    v.y += ex * W[(size_t)(col + 1) * ldw + 256];
                }
                const int b = m >> 9, n = m & 511;
                const int h = col >> 4, d = col & 15;
                *(float2*)&out[(((size_t)(b * 16 + h) * 512) + n) * 16 + d] = v;
            }
        }
    }
}

// ---------------------------------------------------------------------------
// Wc projection (pipelined, double-buffered): g_att @ Wc^T + bias -> g_mh
// ---------------------------------------------------------------------------
__global__ __launch_bounds__(256, 2) void gemm_wc_kernel(
    const float* __restrict__ W,
    const float* __restrict__ bias)
{
    extern __shared__ __nv_bfloat16 smp[];
    const float* Ap = (const float*)g_att;
    float* out = g_mh;

    const int m0 = blockIdx.x * 128;
    const int n0 = blockIdx.y * 64;
    const int tid = threadIdx.x;
    const int warp = tid >> 5, lane = tid & 31;
    const int wm = warp >> 1, wn = warp & 1;
    const int gr = lane >> 2, qc = lane & 3;
    const int lt = lane >> 3, lr = lane & 7;

    const unsigned sb = (unsigned)__cvta_generic_to_shared(smp);
    const unsigned aH0 = sb + (P_AH + (wm * 32 + (lt & 1) * 8 + lr) * LDAB + (lt >> 1) * 8) * 2;
    const unsigned aL0 = sb + (P_AL + (wm * 32 + (lt & 1) * 8 + lr) * LDAB + (lt >> 1) * 8) * 2;
    const unsigned bH0 = sb + (P_BH + (wn * 32 + (lt >> 1) * 8 + lr) * LDAB + (lt & 1) * 8) * 2;
    const unsigned bL0 = sb + (P_BL + (wn * 32 + (lt >> 1) * 8 + lr) * LDAB + (lt & 1) * 8) * 2;

    float acc[2][4][4];
#pragma unroll
    for (int mt = 0; mt < 2; mt++)
#pragma unroll
        for (int nt = 0; nt < 4; nt++)
#pragma unroll
            for (int e = 0; e < 4; e++) acc[mt][nt][e] = 0.0f;

    float4 av[4], wv[2];
#pragma unroll
    for (int i = 0; i < 4; i++) {
        const int lin = tid + i * 256;
        const int row = lin >> 3, c4 = lin & 7;
        av[i] = *(const float4*)(Ap + (size_t)(m0 + row) * 256 + c4 * 4);
    }
#pragma unroll
    for (int i = 0; i < 2; i++) {
        const int lin = tid + i * 256;
        const int row = lin >> 3, c4 = lin & 7;
        wv[i] = *(const float4*)(W + (size_t)(n0 + row) * 256 + c4 * 4);
    }

#pragma unroll 1
    for (int kb = 0; kb < 8; kb++) {
        const int bufo = (kb & 1) * P_STAGE;
        __nv_bfloat16* Ah = smp + bufo + P_AH;
        __nv_bfloat16* Al = smp + bufo + P_AL;
        __nv_bfloat16* Bh = smp + bufo + P_BH;
        __nv_bfloat16* Bl = smp + bufo + P_BL;
#pragma unroll
        for (int i = 0; i < 4; i++) {
            const int lin = tid + i * 256;
            const int row = lin >> 3, c4 = lin & 7;
            store_hl4(&Ah[row * LDAB + c4 * 4], &Al[row * LDAB + c4 * 4], av[i]);
        }
#pragma unroll
        for (int i = 0; i < 2; i++) {
            const int lin = tid + i * 256;
            const int row = lin >> 3, c4 = lin & 7;
            store_hl4(&Bh[row * LDAB + c4 * 4], &Bl[row * LDAB + c4 * 4], wv[i]);
        }
        __syncthreads();

        if (kb < 7) {
            const int k0 = (kb + 1) * 32;
#pragma unroll
            for (int i = 0; i < 4; i++) {
                const int lin = tid + i * 256;
                const int row = lin >> 3, c4 = lin & 7;
                av[i] = *(const float4*)(Ap + (size_t)(m0 + row) * 256 + k0 + c4 * 4);
            }
#pragma unroll
            for (int i = 0; i < 2; i++) {
                const int lin = tid + i * 256;
                const int row = lin >> 3, c4 = lin & 7;
                wv[i] = *(const float4*)(W + (size_t)(n0 + row) * 256 + k0 + c4 * 4);
            }
        }

        const unsigned bo2 = bufo * 2;
#pragma unroll
        for (int ks = 0; ks < 32; ks += 16) {
            unsigned ah[2][4], al[2][4], bh[4][2], bl[4][2];
#pragma unroll
            for (int mt = 0; mt < 2; mt++) {
                ldsm_x4(ah[mt][0], ah[mt][1], ah[mt][2], ah[mt][3],
                        aH0 + bo2 + (mt * 16 * LDAB + ks) * 2);
                ldsm_x4(al[mt][0], al[mt][1], al[mt][2], al[mt][3],
                        aL0 + bo2 + (mt * 16 * LDAB + ks) * 2);
            }
#pragma unroll
            for (int p = 0; p < 2; p++) {
                ldsm_x4(bh[2 * p][0], bh[2 * p][1], bh[2 * p + 1][0], bh[2 * p + 1][1],
                        bH0 + bo2 + (p * 16 * LDAB + ks) * 2);
                ldsm_x4(bl[2 * p][0], bl[2 * p][1], bl[2 * p + 1][0], bl[2 * p + 1][1],
                        bL0 + bo2 + (p * 16 * LDAB + ks) * 2);
            }
#pragma unroll
            for (int mt = 0; mt < 2; mt++)
#pragma unroll
                for (int nt = 0; nt < 4; nt++) {
                    mma16816(acc[mt][nt], ah[mt], bh[nt]);
                    mma16816(acc[mt][nt], ah[mt], bl[nt]);
                    mma16816(acc[mt][nt], al[mt], bh[nt]);
                }
        }
    }

#pragma unroll
    for (int mt = 0; mt < 2; mt++) {
#pragma unroll
        for (int part = 0; part < 2; part++) {
            const int m = m0 + wm * 32 + mt * 16 + gr + part * 8;
#pragma unroll
            for (int nt = 0; nt < 4; nt++) {
                const int col = n0 + wn * 32 + nt * 8 + 2 * qc;
                float2 v = make_float2(acc[mt][nt][part * 2], acc[mt][nt][part * 2 + 1]);
                v.x += bias[col]; v.y += bias[col + 1];
                *(float2*)&out[(size_t)m * 256 + col] = v;
            }
        }
    }
}

// ---------------------------------------------------------------------------
// Flash attention v8 (unchanged): LDSM + mask-skip + 2 p-tiles per block.
// ---------------------------------------------------------------------------
#define KH_LD 24
#define VT_LD 520
#define A6_KH   0
#define A6_KL   (512 * KH_LD)
#define A6_VTH  (2 * 512 * KH_LD)
#define A6_VTL  (A6_VTH + 16 * VT_LD)
#define A6_QH   (A6_VTL + 16 * VT_LD)
#define A6_QL   (A6_QH + 128 * 16)
#define A6_TOT  (A6_QL + 128 * 16)

__global__ __launch_bounds__(256, 2) void attention8_kernel(
    const float* __restrict__ mask)
{
    extern __shared__ __nv_bfloat16 smb[];
    __nv_bfloat16* Kh  = smb + A6_KH;
    __nv_bfloat16* Kl  = smb + A6_KL;
    __nv_bfloat16* Vth = smb + A6_VTH;
    __nv_bfloat16* Vtl = smb + A6_VTL;
    __nv_bfloat16* Qh  = smb + A6_QH;
    __nv_bfloat16* Ql  = smb + A6_QL;

    const int bh = blockIdx.x;
    const int b  = bh >> 4;
    const int h  = bh & 15;
    const int tid = threadIdx.x;
    const int anymask = g_mask_nz;

    const float4* Kg4 = (const float4*)(g_K + (size_t)bh * (NN * DD));
    for (int i = tid; i < 2048; i += 256) {
        float4 v = Kg4[i];
        const int row = i >> 2, dg = (i & 3) * 4;
        store_hl4(&Kh[row * KH_LD + dg], &Kl[row * KH_LD + dg], v);
    }
    const float4* Vg4 = (const float4*)(g_V + (size_t)bh * (NN * DD));
    for (int i = tid; i < 2048; i += 256) {
        float4 v = Vg4[i];
        const int n = i >> 2, dg = (i & 3) * 4;
        float x[4] = {v.x, v.y, v.z, v.w};
#pragma unroll
        for (int j = 0; j < 4; j++) {
            __nv_bfloat16 hh, ll;
            cvt_hl(x[j], hh, ll);
            Vth[(dg + j) * VT_LD + n] = hh;
            Vtl[(dg + j) * VT_LD + n] = ll;
        }
    }

    const int warp = tid >> 5, lane = tid & 31;
    const int gr = lane >> 2, qc = lane & 3;
    const int lt = lane >> 3, lr = lane & 7;
    const int prow = warp * 16;

    const unsigned sb = (unsigned)__cvta_generic_to_shared(smb);
    const unsigned kBase = sb + ((lt < 2 ? A6_KH : A6_KL)
                                 + lr * KH_LD + (lt & 1) * 8) * 2;
    const unsigned vBase = sb + ((lt < 2 ? A6_VTH : A6_VTL)
                                 + lr * VT_LD + (lt & 1) * 8) * 2;

#pragma unroll 1
    for (int ip = 0; ip < 2; ip++) {
        const int p0 = blockIdx.y * 256 + ip * 128;

        __syncthreads();
        const float4* Qg4 = (const float4*)(g_Q + ((size_t)bh * PP + p0) * DD);
        for (int i = tid; i < 512; i += 256) {
            float4 v = Qg4[i];
            v.x *= 0.25f; v.y *= 0.25f; v.z *= 0.25f; v.w *= 0.25f;
            const int row = i >> 2, dg = (i & 3) * 4;
            store_hl4(&Qh[row * 16 + dg], &Ql[row * 16 + dg], v);
        }
        __syncthreads();

        unsigned qh[4], ql[4];
        {
            const int base = (prow + gr) * 16 + 2 * qc;
            qh[0] = *(const unsigned*)&Qh[base];
            qh[1] = *(const unsigned*)&Qh[base + 8 * 16];
            qh[2] = *(const unsigned*)&Qh[base + 8];
            qh[3] = *(const unsigned*)&Qh[base + 8 * 16 + 8];
            ql[0] = *(const unsigned*)&Ql[base];
            ql[1] = *(const unsigned*)&Ql[base + 8 * 16];
            ql[2] = *(const unsigned*)&Ql[base + 8];
            ql[3] = *(const unsigned*)&Ql[base + 8 * 16 + 8];
        }

        float m0 = -1e30f, m1 = -1e30f, l0 = 0.0f, l1 = 0.0f;
        float O[2][4];
#pragma unroll
        for (int nd = 0; nd < 2; nd++)
#pragma unroll
            for (int e = 0; e < 4; e++) O[nd][e] = 0.0f;

        const size_t mrow0 = ((size_t)(b * PP + p0 + prow + gr)) * NN;
        const size_t mrow1 = ((size_t)(b * PP + p0 + prow + gr + 8)) * NN;

#pragma unroll 1
        for (int c = 0; c < 8; c++) {
            const int n0c = c * 64;

            float s[8][4];
#pragma unroll
            for (int nf = 0; nf < 8; nf++) {
                s[nf][0] = s[nf][1] = s[nf][2] = s[nf][3] = 0.0f;
                unsigned kbh[2], kbl[2];
                ldsm_x4(kbh[0], kbh[1], kbl[0], kbl[1],
                        kBase + (n0c + nf * 8) * (KH_LD * 2));
                mma16816(s[nf], qh, kbh);
                mma16816(s[nf], qh, kbl);
                mma16816(s[nf], ql, kbh);
            }

            if (anymask) {
#pragma unroll
                for (int nf = 0; nf < 8; nf++) {
                    const int ncol = n0c + nf * 8 + 2 * qc;
                    float2 mk0 = *(const float2*)&mask[mrow0 + ncol];
                    float2 mk1 = *(const float2*)&mask[mrow1 + ncol];
                    s[nf][0] += mk0.x; s[nf][1] += mk0.y;
                    s[nf][2] += mk1.x; s[nf][3] += mk1.y;
                }
            }

            float mx0 = -1e30f, mx1 = -1e30f;
#pragma unroll
            for (int nf = 0; nf < 8; nf++) {
                mx0 = fmaxf(mx0, fmaxf(s[nf][0], s[nf][1]));
                mx1 = fmaxf(mx1, fmaxf(s[nf][2], s[nf][3]));
            }
            mx0 = fmaxf(mx0, __shfl_xor_sync(0xffffffffu, mx0, 1));
            mx0 = fmaxf(mx0, __shfl_xor_sync(0xffffffffu, mx0, 2));
            mx1 = fmaxf(mx1, __shfl_xor_sync(0xffffffffu, mx1, 1));
            mx1 = fmaxf(mx1, __shfl_xor_sync(0xffffffffu, mx1, 2));

            const float mn0 = fmaxf(m0, mx0);
            const float mn1 = fmaxf(m1, mx1);
            const float f0 = __expf(m0 - mn0);
            const float f1 = __expf(m1 - mn1);
            m0 = mn0; m1 = mn1;
#pragma unroll
            for (int nd = 0; nd < 2; nd++) {
                O[nd][0] *= f0; O[nd][1] *= f0;
                O[nd][2] *= f1; O[nd][3] *= f1;
            }

            float rs0 = 0.0f, rs1 = 0.0f;
#pragma unroll
            for (int nf = 0; nf < 8; nf++) {
                s[nf][0] = __expf(s[nf][0] - mn0);
                s[nf][1] = __expf(s[nf][1] - mn0);
                s[nf][2] = __expf(s[nf][2] - mn1);
                s[nf][3] = __expf(s[nf][3] - mn1);
                rs0 += s[nf][0] + s[nf][1];
                rs1 += s[nf][2] + s[nf][3];
            }
            rs0 += __shfl_xor_sync(0xffffffffu, rs0, 1);
            rs0 += __shfl_xor_sync(0xffffffffu, rs0, 2);
            rs1 += __shfl_xor_sync(0xffffffffu, rs1, 1);
            rs1 += __shfl_xor_sync(0xffffffffu, rs1, 2);
            l0 = l0 * f0 + rs0;
            l1 = l1 * f1 + rs1;

#pragma unroll
            for (int t = 0; t < 4; t++) {
                unsigned ah[4], al[4];
                pack_hl(s[2 * t][0],     s[2 * t][1],     ah[0], al[0]);
                pack_hl(s[2 * t][2],     s[2 * t][3],     ah[1], al[1]);
                pack_hl(s[2 * t + 1][0], s[2 * t + 1][1], ah[2], al[2]);
                pack_hl(s[2 * t + 1][2], s[2 * t + 1][3], ah[3], al[3]);
#pragma unroll
                for (int nd = 0; nd < 2; nd++) {
                    unsigned vbh[2], vbl[2];
                    ldsm_x4(vbh[0], vbh[1], vbl[0], vbl[1],
                            vBase + (nd * 8 * VT_LD + n0c + 16 * t) * 2);
                    mma16816(O[nd], ah, vbh);
                    mma16816(O[nd], ah, vbl);
                    mma16816(O[nd], al, vbh);
                }
            }
        }

        const float inv0 = 1.0f / l0;
        const float inv1 = 1.0f / l1;
        float* op0 = g_att + ((size_t)(b * PP + p0 + prow + gr)) * (HH * DD) + h * DD;
        float* op1 = g_att + ((size_t)(b * PP + p0 + prow + gr + 8)) * (HH * DD) + h * DD;
#pragma unroll
        for (int nd = 0; nd < 2; nd++) {
            *(float2*)&op0[nd * 8 + 2 * qc] = make_float2(O[nd][0] * inv0, O[nd][1] * inv0);
            *(float2*)&op1[nd * 8 + 2 * qc] = make_float2(O[nd][2] * inv1, O[nd][3] * inv1);
        }
    }
}

// ---------------------------------------------------------------------------
// Final fused kernel v7: tau-first, A staged once (full K), B k-pipelined,
// no S_s (fixed softmax shift 10), unnormalized exp -> out, in-block rescale.
// Block per (b, 32-row p-tile). 256 threads, 2 CTA/SM.
// ---------------------------------------------------------------------------
#define F_BH 0
#define F_BL (128 * LDAB)
#define F_BSTAGE (256 * LDAB)               // 10240 elems / 20480 B per stage
#define F_AH (2 * F_BSTAGE)                 // 20480
#define F_A_LD 264
#define F_AL (F_AH + 32 * F_A_LD)           // 28928
#define F_TOT (F_AL + 32 * F_A_LD)          // 37376 elems = 74752 B

__global__ __launch_bounds__(256, 2) void final7_kernel(
    const float* __restrict__ enc,
    const float* __restrict__ dist,
    const float* __restrict__ mask,
    float* __restrict__ out)
{
    extern __shared__ __nv_bfloat16 smf[];
    __shared__ float s_tau[32];
    __shared__ float s_sum[32];

    const int b = blockIdx.y;
    const int p0 = blockIdx.x * 32;
    const int tid = threadIdx.x;
    const int warp = tid >> 5, lane = tid & 31;
    const int wm = warp >> 2, wn = warp & 3;
    const int gr = lane >> 2, qc = lane & 3;
    const int lt = lane >> 3, lr = lane & 7;
    const int anymask = g_mask_nz;

    if (tid < 32) s_sum[tid] = 0.0f;

    // ---- phase A: per-row tau (100th smallest distance threshold) ----
#pragma unroll 1
    for (int rr = 0; rr < 4; rr++) {
        const int r = warp * 4 + rr;
        const float* drow = dist + ((size_t)(b * PP + p0 + r)) * NN;
        unsigned key[16];
#pragma unroll
        for (int j = 0; j < 16; j++) {
            unsigned u = __float_as_uint(drow[j * 32 + lane]);
            key[j] = (u & 0x80000000u) ? ~u : (u ^ 0x80000000u);
        }
        unsigned lo = 0u, hi = 0xffffffffu;
#pragma unroll 1
        for (int it = 0; it < 32; it++) {
            const unsigned mid = lo + ((hi - lo) >> 1);
            int c = 0;
#pragma unroll
            for (int j = 0; j < 16; j++) c += (key[j] <= mid) ? 1 : 0;
            c = __reduce_add_sync(0xffffffffu, c);
            if (c >= 100) hi = mid; else lo = mid + 1;
        }
        if (lane == 0) {
            const unsigned tau = hi;
            // invert orderable-key transform (tau corresponds to a non-negative float here)
            const unsigned u = (tau & 0x80000000u) ? (tau ^ 0x80000000u) : ~tau;
            s_tau[r] = __uint_as_float(u);
        }
    }

    // ---- stage A (mh tile, FULL K) once ----
    __nv_bfloat16* Ah = smf + F_AH;
    __nv_bfloat16* Al = smf + F_AL;
#pragma unroll
    for (int i = 0; i < 8; i++) {
        const int lin = tid + i * 256;
        const int row = lin >> 6, c4 = lin & 63;
        float4 av = *(const float4*)&g_mh[((size_t)(b * PP + p0 + row)) * 256 + c4 * 4];
        store_hl4(&Ah[row * F_A_LD + c4 * 4], &Al[row * F_A_LD + c4 * 4], av);
    }
    __syncthreads();

    const unsigned sb = (unsigned)__cvta_generic_to_shared(smf);
    const unsigned aHb = sb + (F_AH + (wm * 16 + (lt & 1) * 8 + lr) * F_A_LD + (lt >> 1) * 8) * 2;
    const unsigned aLb = sb + (F_AL + (wm * 16 + (lt & 1) * 8 + lr) * F_A_LD + (lt >> 1) * 8) * 2;
    const unsigned bHb = sb + (F_BH + (wn * 32 + (lt >> 1) * 8 + lr) * LDAB + (lt & 1) * 8) * 2;
    const unsigned bLb = sb + (F_BL + (wn * 32 + (lt >> 1) * 8 + lr) * LDAB + (lt & 1) * 8) * 2;

    const float* encb = enc + (size_t)b * NN * EMB;
    const size_t outbase = ((size_t)(b * PP + p0)) * NN;

#pragma unroll 1
    for (int nc = 0; nc < 4; nc++) {
        float acc[4][4];
#pragma unroll
        for (int nt = 0; nt < 4; nt++)
#pragma unroll
            for (int e = 0; e < 4; e++) acc[nt][e] = 0.0f;

        // prologue B loads (k=0)
        float4 bv[4];
#pragma unroll
        for (int i = 0; i < 4; i++) {
            const int lin = tid + i * 256;
            const int row = lin >> 3, c4 = lin & 7;
            bv[i] = *(const float4*)&encb[(size_t)(nc * 128 + row) * 256 + c4 * 4];
        }

#pragma unroll 1
        for (int kb = 0; kb < 8; kb++) {
            const int bufo = (kb & 1) * F_BSTAGE;
            __nv_bfloat16* Bh = smf + bufo + F_BH;
            __nv_bfloat16* Bl = smf + bufo + F_BL;
#pragma unroll
            for (int i = 0; i < 4; i++) {
                const int lin = tid + i * 256;
                const int row = lin >> 3, c4 = lin & 7;
                store_hl4(&Bh[row * LDAB + c4 * 4], &Bl[row * LDAB + c4 * 4], bv[i]);
            }
            __syncthreads();

            if (kb < 7) {
                const int k0 = (kb + 1) * 32;
#pragma unroll
                for (int i = 0; i < 4; i++) {
                    const int lin = tid + i * 256;
                    const int row = lin >> 3, c4 = lin & 7;
                    bv[i] = *(const float4*)&encb[(size_t)(nc * 128 + row) * 256 + k0 + c4 * 4];
                }
            }

            const unsigned bo2 = bufo * 2;
#pragma unroll
            for (int ks = 0; ks < 16 * 2; ks += 16) {
                const int ka = kb * 32 + ks;  // column in full-K A slab
                unsigned ah[4], al[4], bh[4][2], bl[4][2];
                ldsm_x4(ah[0], ah[1], ah[2], ah[3], aHb + ka * 2);
                ldsm_x4(al[0], al[1], al[2], al[3], aLb + ka * 2);
#pragma unroll
                for (int p = 0; p < 2; p++) {
                    ldsm_x4(bh[2 * p][0], bh[2 * p][1], bh[2 * p + 1][0], bh[2 * p + 1][1],
                            bHb + bo2 + (p * 16 * LDAB + ks) * 2);
                    ldsm_x4(bl[2 * p][0], bl[2 * p][1], bl[2 * p + 1][0], bl[2 * p + 1][1],
                            bLb + bo2 + (p * 16 * LDAB + ks) * 2);
                }
#pragma unroll
                for (int nt = 0; nt < 4; nt++) {
                    mma16816(acc[nt], ah, bh[nt]);
                    mma16816(acc[nt], ah, bl[nt]);
                    mma16816(acc[nt], al, bh[nt]);
                }
            }
        }

        // ---- epilogue for this nc: penalty + tanh-clip + exp(cc-10) ----
#pragma unroll
        for (int part = 0; part < 2; part++) {
            const int rloc = wm * 16 + gr + part * 8;
            const float tauf = s_tau[rloc];
            const size_t rowoff = outbase + (size_t)rloc * NN;
            float lsum = 0.0f;
#pragma unroll
            for (int nt = 0; nt < 4; nt++) {
                const int col = nc * 128 + wn * 32 + nt * 8 + 2 * qc;
                float2 d2 = *(const float2*)&dist[rowoff + col];
                float sc0 = acc[nt][part * 2] * 0.0625f
                          + ((d2.x <= tauf) ? (-d2.x * 0.7071067811865475f) : 1.0f);
                float sc1 = acc[nt][part * 2 + 1] * 0.0625f
                          + ((d2.y <= tauf) ? (-d2.y * 0.7071067811865475f) : 1.0f);
                // cc = 10*tanh(sc) = 10 - 20/(exp(2 sc)+1); e = exp(cc - 10)
                float cc0 = -__fdividef(20.0f, __expf(2.0f * sc0) + 1.0f);
                float cc1 = -__fdividef(20.0f, __expf(2.0f * sc1) + 1.0f);
                if (anymask) {
                    float2 mk = *(const float2*)&mask[rowoff + col];
                    cc0 += mk.x; cc1 += mk.y;
                }
                const float e0 = __expf(cc0);
                const float e1 = __expf(cc1);
                lsum += e0 + e1;
                *(float2*)&out[rowoff + col] = make_float2(e0, e1);
            }
            atomicAdd(&s_sum[rloc], lsum);
        }
    }
    __syncthreads();

    if (tid < 32) s_sum[tid] = 1.0f / s_sum[tid];
    __syncthreads();

    // ---- rescale pass (L2/L1-resident) ----
    float2* out2 = (float2*)&out[outbase];
#pragma unroll 4
    for (int i = tid; i < 32 * 256; i += 256) {
        const float inv = s_sum[i >> 8];
        float2 v = out2[i];
        v.x *= inv; v.y *= inv;
        out2[i] = v;
    }
}

// ---------------------------------------------------------------------------
// Launch
// ---------------------------------------------------------------------------
extern "C" void kernel_launch(void* const* d_in, const int* in_sizes, int n_in,
                              void* d_out, int out_size)
{
    const float* enc   = (const float*)d_in[0];
    const float* last  = (const float*)d_in[1];
    const float* load  = (const float*)d_in[2];
    const float* dist  = (const float*)d_in[3];
    const float* mask  = (const float*)d_in[6];
    const float* Wq    = (const float*)d_in[7];
    const float* Wk    = (const float*)d_in[8];
    const float* Wv    = (const float*)d_in[9];
    const float* Wc    = (const float*)d_in[10];
    const float* Wcb   = (const float*)d_in[11];
    float* out = (float*)d_out;

    init_flag_kernel<<<1, 32>>>();

    const size_t smP = (size_t)2 * P_STAGE * sizeof(__nv_bfloat16);  // 61440 B
    cudaFuncSetAttribute(proj_kernel,
                         cudaFuncAttributeMaxDynamicSharedMemorySize, (int)smP);
    proj_kernel<<<dim3(BB * PP / 128, 4, 3), 256, smP>>>(
        enc, last, load, Wk, Wv, Wq, mask);

    const size_t smA = (size_t)A6_TOT * sizeof(__nv_bfloat16);  // 90624 B
    cudaFuncSetAttribute(attention8_kernel,
                         cudaFuncAttributeMaxDynamicSharedMemorySize, (int)smA);
    dim3 gA(BB * HH, 2);
    attention8_kernel<<<gA, 256, smA>>>(mask);

    cudaFuncSetAttribute(gemm_wc_kernel,
                         cudaFuncAttributeMaxDynamicSharedMemorySize, (int)smP);
    gemm_wc_kernel<<<dim3(BB * PP / 128, 4), 256, smP>>>(Wc, Wcb);

    const size_t smF = (size_t)F_TOT * sizeof(__nv_bfloat16);  // 74752 B
    cudaFuncSetAttribute(final7_kernel,
                         cudaFuncAttributeMaxDynamicSharedMemorySize, (int)smF);
    dim3 gF(PP / 32, BB);  // 16 x 32
    final7_kernel<<<gF, 256, smF>>>(enc, dist, mask, out);
}